// round 6
// baseline (speedup 1.0000x reference)
#include <cuda_runtime.h>
#include <cuda_fp16.h>
#include <math.h>
#include <stdint.h>

// Problem constants
#define Bc   4
#define Sc   2048
#define Dc   512
#define Hc   8
#define Dhc  64
#define Mrows (Bc*Sc)      // 8192
#define D3   (3*Dc)        // 1536
#define DffC (4*Dc)        // 2048

// ---- scratch (device globals; no cudaMalloc allowed) ----
// weights as fp16(32*w), hi + lo residual
__device__ __half g_fwhi[3145728];
__device__ __half g_fwlo[3145728];
#define FW_IN   0
#define FW_OUT  786432
#define FW_FF1  1048576
#define FW_FF2  2097152
// activations
__device__ __half g_a16  [(size_t)Mrows * Dc];    // act/32 (GEMM A operand)
__device__ __half g_ff16 [(size_t)Mrows * DffC];  // gelu out / 32
__device__ __half g_qkv16[(size_t)Mrows * D3];    // qkv, unscaled fp16
__device__ float  g_x1   [(size_t)Mrows * Dc];

// ============================================================
// helpers
// ============================================================
__device__ __forceinline__ uint32_t smem_u32(const void* p) {
    uint32_t a;
    asm("{ .reg .u64 t; cvta.to.shared.u64 t, %1; cvt.u32.u64 %0, t; }" : "=r"(a) : "l"(p));
    return a;
}
__device__ __forceinline__ uint32_t sw128(uint32_t o) { return o ^ ((o >> 3) & 0x70); }

__device__ __forceinline__ void split2_f16(float x, float y, uint32_t& hi, uint32_t& lo) {
    __half2 h = __floats2half2_rn(x, y);
    float rx = x - __half2float(h.x);
    float ry = y - __half2float(h.y);
    __half2 l = __floats2half2_rn(rx, ry);
    hi = *reinterpret_cast<uint32_t*>(&h);
    lo = *reinterpret_cast<uint32_t*>(&l);
}

__device__ __forceinline__ void cp16(uint32_t dst, const void* src) {
    asm volatile("cp.async.cg.shared.global [%0], [%1], 16;" :: "r"(dst), "l"(src) : "memory");
}
#define CP_COMMIT() asm volatile("cp.async.commit_group;" ::: "memory")
#define CP_WAIT0()  asm volatile("cp.async.wait_group 0;" ::: "memory")

__device__ __forceinline__ void ldm_x4(uint32_t* r, uint32_t addr) {
    asm volatile("ldmatrix.sync.aligned.m8n8.x4.shared.b16 {%0,%1,%2,%3}, [%4];"
                 : "=r"(r[0]), "=r"(r[1]), "=r"(r[2]), "=r"(r[3]) : "r"(addr));
}
__device__ __forceinline__ void mma_f16(float* c, const uint32_t* a, uint32_t b0, uint32_t b1) {
    asm volatile("mma.sync.aligned.m16n8k16.row.col.f32.f16.f16.f32 "
                 "{%0,%1,%2,%3}, {%4,%5,%6,%7}, {%8,%9}, {%0,%1,%2,%3};"
                 : "+f"(c[0]), "+f"(c[1]), "+f"(c[2]), "+f"(c[3])
                 : "r"(a[0]), "r"(a[1]), "r"(a[2]), "r"(a[3]), "r"(b0), "r"(b1));
}

// ============================================================
// weight conversion: w -> fp16(32*w) hi + lo  (merged, 2 launches)
// ============================================================
__global__ void wconv_attn(const float* __restrict__ in_w, const float* __restrict__ out_w,
                           __half* __restrict__ hi, __half* __restrict__ lo) {
    int i = blockIdx.x * 256 + threadIdx.x;          // 0..262143 (float4 units)
    const float* w = (i < 196608) ? in_w : (out_w - 4*(size_t)196608/4*4 + 0); // resolved below
    float4 v;
    if (i < 196608) v = ((const float4*)in_w)[i];
    else            v = ((const float4*)out_w)[i - 196608];
    uint32_t h0, l0, h1, l1;
    split2_f16(v.x * 32.0f, v.y * 32.0f, h0, l0);
    split2_f16(v.z * 32.0f, v.w * 32.0f, h1, l1);
    ((uint2*)hi)[i] = make_uint2(h0, h1);
    ((uint2*)lo)[i] = make_uint2(l0, l1);
    (void)w;
}
__global__ void wconv_ff(const float* __restrict__ w1, const float* __restrict__ w2,
                         __half* __restrict__ hi, __half* __restrict__ lo) {
    int i = blockIdx.x * 256 + threadIdx.x;          // 0..524287 (float4 units)
    float4 v;
    if (i < 262144) v = ((const float4*)w1)[i];
    else            v = ((const float4*)w2)[i - 262144];
    uint32_t h0, l0, h1, l1;
    split2_f16(v.x * 32.0f, v.y * 32.0f, h0, l0);
    split2_f16(v.z * 32.0f, v.w * 32.0f, h1, l1);
    ((uint2*)hi)[i] = make_uint2(h0, h1);
    ((uint2*)lo)[i] = make_uint2(l0, l1);
}

// ============================================================
// LayerNorm -> fp16(out/32)
// ============================================================
__global__ void ln_kernel(const float* __restrict__ x,
                          const float* __restrict__ g,
                          const float* __restrict__ b,
                          __half* __restrict__ h16) {
    int row = blockIdx.x;
    int t = threadIdx.x;                 // 0..127
    const float4* xr = (const float4*)(x + (size_t)row * Dc);
    float4 v = xr[t];
    float s  = v.x + v.y + v.z + v.w;
    float s2 = v.x*v.x + v.y*v.y + v.z*v.z + v.w*v.w;
    #pragma unroll
    for (int o = 16; o > 0; o >>= 1) {
        s  += __shfl_xor_sync(0xffffffffu, s,  o);
        s2 += __shfl_xor_sync(0xffffffffu, s2, o);
    }
    __shared__ float sh[8];
    int w = t >> 5;
    if ((t & 31) == 0) { sh[w*2] = s; sh[w*2+1] = s2; }
    __syncthreads();
    s  = sh[0] + sh[2] + sh[4] + sh[6];
    s2 = sh[1] + sh[3] + sh[5] + sh[7];
    float mu  = s * (1.0f / Dc);
    float var = s2 * (1.0f / Dc) - mu * mu;
    float rstd = rsqrtf(var + 1e-5f);
    float4 gv = ((const float4*)g)[t];
    float4 bv = ((const float4*)b)[t];
    float o0 = (v.x - mu) * rstd * gv.x + bv.x;
    float o1 = (v.y - mu) * rstd * gv.y + bv.y;
    float o2 = (v.z - mu) * rstd * gv.z + bv.z;
    float o3 = (v.w - mu) * rstd * gv.w + bv.w;
    __half2 p0 = __floats2half2_rn(o0 * 0.03125f, o1 * 0.03125f);
    __half2 p1 = __floats2half2_rn(o2 * 0.03125f, o3 * 0.03125f);
    size_t base = (size_t)row * Dc + t * 4;
    *(uint2*)(h16 + base) = make_uint2(*reinterpret_cast<uint32_t*>(&p0),
                                       *reinterpret_cast<uint32_t*>(&p1));
}

// ============================================================
// 2-term fp16 GEMM via mma.sync:
//   C[M,N] = (A/32)[M,K] @ (32*B)[N,K]^T + bias  (fp32 accum, scale cancels)
// 128x128 block, 8 warps (2m x 4n, each 64x32), BK=64, 2-stage cp.async,
// 96KB smem -> 2 CTAs/SM, 1 syncthreads per chunk, ldm_x4 for B pairs.
// EPI: 0=bias->fp16 (qkv), 1=bias+residual->fp32, 2=bias+GELU->fp16(/32)
// ============================================================
#define TB  16384            // one 128x64 fp16 tile
#define SSZ (3*TB)           // stage: Ahi, Bhi, Blo
#define SM_SZ (2*SSZ)        // 98304

template<int EPI>
__global__ __launch_bounds__(256, 2)
void gemm_mma(const __half* __restrict__ Ahi,
              const __half* __restrict__ Bhi, const __half* __restrict__ Blo,
              const float* __restrict__ bias, const float* __restrict__ res,
              float* __restrict__ C, __half* __restrict__ C16,
              int M, int N, int K)
{
    extern __shared__ __align__(128) char smem[];
    uint32_t sb = smem_u32(smem);
    int tid = threadIdx.x;
    int lane = tid & 31, wid = tid >> 5;
    int bm = blockIdx.y * 128, bn = blockIdx.x * 128;
    int m0 = (wid & 1) * 64;          // warp tile: 64 (m) x 32 (n)
    int n0 = (wid >> 1) * 32;

    float acc[4][4][4];
    #pragma unroll
    for (int i = 0; i < 4; i++)
        #pragma unroll
        for (int j = 0; j < 4; j++)
            #pragma unroll
            for (int k = 0; k < 4; k++) acc[i][j][k] = 0.0f;

    auto load_stage = [&](int st, int k0) {
        uint32_t base = sb + st * SSZ;
        #pragma unroll
        for (int t = 0; t < 4; t++) {
            int line = tid + t * 256;           // 0..1023
            int r  = line >> 3;                 // row 0..127
            int cc = line & 7;                  // 16B column chunk
            uint32_t d = sw128((uint32_t)(r * 128 + cc * 16));
            size_t aoff = (size_t)(bm + r) * K + k0 + cc * 8;
            size_t boff = (size_t)(bn + r) * K + k0 + cc * 8;
            cp16(base + d,          Ahi + aoff);
            cp16(base + TB + d,     Bhi + boff);
            cp16(base + 2*TB + d,   Blo + boff);
        }
    };

    int nk = K >> 6;
    load_stage(0, 0);
    CP_COMMIT();

    for (int ch = 0; ch < nk; ch++) {
        CP_WAIT0();
        __syncthreads();            // chunk ch resident; stage ch-1 fully consumed
        if (ch + 1 < nk) {
            load_stage((ch + 1) & 1, (ch + 1) * 64);
            CP_COMMIT();
        }

        uint32_t abase = sb + (ch & 1) * SSZ;
        uint32_t bbase = abase + TB;

        #pragma unroll
        for (int ks = 0; ks < 4; ks++) {
            int k0 = ks * 16;
            // fragment addressing (identical formula for A and B tiles)
            int frow = (lane & 7) + ((lane >> 3) & 1) * 8;
            int fcol = k0 + (lane >> 4) * 8;
            uint32_t ahi[4][4], bh[2][4], bl[2][4];
            #pragma unroll
            for (int mi = 0; mi < 4; mi++) {
                uint32_t o = sw128((uint32_t)((m0 + mi*16 + frow) * 128 + fcol * 2));
                ldm_x4(ahi[mi], abase + o);
            }
            #pragma unroll
            for (int pr = 0; pr < 2; pr++) {
                uint32_t o = sw128((uint32_t)((n0 + pr*16 + frow) * 128 + fcol * 2));
                ldm_x4(bh[pr], bbase + o);
                ldm_x4(bl[pr], bbase + TB + o);
            }
            #pragma unroll
            for (int mi = 0; mi < 4; mi++)
                #pragma unroll
                for (int ni = 0; ni < 4; ni++) {
                    int pr = ni >> 1, sel = ni & 1;
                    mma_f16(acc[mi][ni], ahi[mi], bh[pr][sel], bh[pr][sel+2]);
                    mma_f16(acc[mi][ni], ahi[mi], bl[pr][sel], bl[pr][sel+2]);
                }
        }
        // no bottom barrier: next iteration's top barrier protects stage reuse
    }

    // epilogue: direct stores (each thread owns 2 consecutive cols per frag)
    int gr = lane >> 2, tq = lane & 3;
    #pragma unroll
    for (int mi = 0; mi < 4; mi++) {
        #pragma unroll
        for (int ni = 0; ni < 4; ni++) {
            int col = bn + n0 + ni*8 + tq*2;
            float b0 = bias[col], b1 = bias[col + 1];
            #pragma unroll
            for (int half = 0; half < 2; half++) {
                int row = bm + m0 + mi*16 + gr + half*8;
                float v0 = acc[mi][ni][half*2 + 0] + b0;
                float v1 = acc[mi][ni][half*2 + 1] + b1;
                size_t off = (size_t)row * N + col;
                if (EPI == 1) {
                    float2 r2 = *(const float2*)(res + off);
                    v0 += r2.x; v1 += r2.y;
                    *(float2*)(C + off) = make_float2(v0, v1);
                } else if (EPI == 2) {
                    v0 = 0.5f * v0 * (1.0f + erff(v0 * 0.7071067811865475f));
                    v1 = 0.5f * v1 * (1.0f + erff(v1 * 0.7071067811865475f));
                    __half2 p = __floats2half2_rn(v0 * 0.03125f, v1 * 0.03125f);
                    *(uint32_t*)(C16 + off) = *reinterpret_cast<uint32_t*>(&p);
                } else {
                    __half2 p = __floats2half2_rn(v0, v1);
                    *(uint32_t*)(C16 + off) = *reinterpret_cast<uint32_t*>(&p);
                }
            }
        }
    }
}

// ============================================================
// Local attention: one warp per (b,s,h); fp16 qkv in, fp16(ctx/32) out
// ============================================================
__global__ void attn_kernel(const __half* __restrict__ qkv16,
                            __half* __restrict__ ctx16) {
    int gwarp = (blockIdx.x * blockDim.x + threadIdx.x) >> 5;
    int lane = threadIdx.x & 31;
    int h  = gwarp & (Hc - 1);
    int bs = gwarp >> 3;
    int s  = bs & (Sc - 1);
    int rowbase = bs - s;

    const __half2* qr = (const __half2*)(qkv16 + (size_t)bs * D3 + h * Dhc);
    float2 q = __half22float2(qr[lane]);

    float e[9];
    float mx = -INFINITY;
    #pragma unroll
    for (int jj = 0; jj < 9; jj++) {
        int j = s - 4 + jj;
        float sc = -INFINITY;
        if (j >= 0 && j < Sc) {
            const __half2* kr = (const __half2*)(qkv16 + (size_t)(rowbase + j) * D3 + Dc + h * Dhc);
            float2 k2 = __half22float2(kr[lane]);
            float p = q.x * k2.x + q.y * k2.y;
            #pragma unroll
            for (int o = 16; o > 0; o >>= 1)
                p += __shfl_xor_sync(0xffffffffu, p, o);
            sc = p * 0.125f;
        }
        e[jj] = sc;
        mx = fmaxf(mx, sc);
    }
    float sum = 0.0f;
    #pragma unroll
    for (int jj = 0; jj < 9; jj++) {
        e[jj] = expf(e[jj] - mx);
        sum += e[jj];
    }
    float inv = 1.0f / sum;
    float c0 = 0.0f, c1 = 0.0f;
    #pragma unroll
    for (int jj = 0; jj < 9; jj++) {
        int j = s - 4 + jj;
        if (j >= 0 && j < Sc) {
            const __half2* vr = (const __half2*)(qkv16 + (size_t)(rowbase + j) * D3 + 2*Dc + h * Dhc);
            float2 v2 = __half22float2(vr[lane]);
            float w = e[jj] * inv;
            c0 = fmaf(w, v2.x, c0);
            c1 = fmaf(w, v2.y, c1);
        }
    }
    __half2 p = __floats2half2_rn(c0 * 0.03125f, c1 * 0.03125f);
    *(uint32_t*)(ctx16 + (size_t)bs * Dc + h * Dhc + 2*lane) = *reinterpret_cast<uint32_t*>(&p);
}

// ============================================================
extern "C" void kernel_launch(void* const* d_in, const int* in_sizes, int n_in,
                              void* d_out, int out_size) {
    const float* x     = (const float*)d_in[0];
    const float* in_w  = (const float*)d_in[1];
    const float* in_b  = (const float*)d_in[2];
    const float* out_w = (const float*)d_in[3];
    const float* out_b = (const float*)d_in[4];
    const float* ff_w1 = (const float*)d_in[5];
    const float* ff_b1 = (const float*)d_in[6];
    const float* ff_w2 = (const float*)d_in[7];
    const float* ff_b2 = (const float*)d_in[8];
    const float* ln1_g = (const float*)d_in[9];
    const float* ln1_b = (const float*)d_in[10];
    const float* ln2_g = (const float*)d_in[11];
    const float* ln2_b = (const float*)d_in[12];
    float* out = (float*)d_out;

    __half *fwhi, *fwlo, *a16, *ff16, *qkv16;
    float *x1;
    cudaGetSymbolAddress((void**)&fwhi,  g_fwhi);
    cudaGetSymbolAddress((void**)&fwlo,  g_fwlo);
    cudaGetSymbolAddress((void**)&a16,   g_a16);
    cudaGetSymbolAddress((void**)&ff16,  g_ff16);
    cudaGetSymbolAddress((void**)&qkv16, g_qkv16);
    cudaGetSymbolAddress((void**)&x1,    g_x1);

    cudaFuncSetAttribute(gemm_mma<0>, cudaFuncAttributeMaxDynamicSharedMemorySize, SM_SZ);
    cudaFuncSetAttribute(gemm_mma<1>, cudaFuncAttributeMaxDynamicSharedMemorySize, SM_SZ);
    cudaFuncSetAttribute(gemm_mma<2>, cudaFuncAttributeMaxDynamicSharedMemorySize, SM_SZ);

    // weight conversions (fp16(32*w) hi/lo), merged
    wconv_attn<<<1024, 256>>>(in_w, out_w, fwhi, fwlo);
    wconv_ff  <<<2048, 256>>>(ff_w1, ff_w2, fwhi + FW_FF1, fwlo + FW_FF1);

    // 1) a16 = fp16(LN1(x)/32)
    ln_kernel<<<Mrows, 128>>>(x, ln1_g, ln1_b, a16);
    // 2) qkv16 = fp16(a16 @ (32*in_w)^T + in_b)
    gemm_mma<0><<<dim3(D3/128, Mrows/128), 256, SM_SZ>>>(
        a16, fwhi + FW_IN, fwlo + FW_IN, in_b, nullptr, nullptr, qkv16,
        Mrows, D3, Dc);
    // 3) a16 = fp16(attention(qkv16)/32)
    attn_kernel<<<(Mrows * Hc * 32) / 256, 256>>>(qkv16, a16);
    // 4) x1 = x + a16 @ (32*out_w)^T + out_b
    gemm_mma<1><<<dim3(Dc/128, Mrows/128), 256, SM_SZ>>>(
        a16, fwhi + FW_OUT, fwlo + FW_OUT, out_b, x, x1, nullptr,
        Mrows, Dc, Dc);
    // 5) a16 = fp16(LN2(x1)/32)
    ln_kernel<<<Mrows, 128>>>(x1, ln2_g, ln2_b, a16);
    // 6) ff16 = fp16(gelu(a16 @ (32*ff_w1)^T + ff_b1)/32)
    gemm_mma<2><<<dim3(DffC/128, Mrows/128), 256, SM_SZ>>>(
        a16, fwhi + FW_FF1, fwlo + FW_FF1, ff_b1, nullptr, nullptr, ff16,
        Mrows, DffC, Dc);
    // 7) out = x1 + ff16 @ (32*ff_w2)^T + ff_b2
    gemm_mma<1><<<dim3(Dc/128, Mrows/128), 256, SM_SZ>>>(
        ff16, fwhi + FW_FF2, fwlo + FW_FF2, ff_b2, x1, out, nullptr,
        Mrows, Dc, DffC);
}

// round 7
// speedup vs baseline: 1.5508x; 1.5508x over previous
#include <cuda_runtime.h>
#include <cuda_fp16.h>
#include <math.h>
#include <stdint.h>

// Problem constants
#define Bc   4
#define Sc   2048
#define Dc   512
#define Hc   8
#define Dhc  64
#define Mrows (Bc*Sc)      // 8192
#define D3   (3*Dc)        // 1536
#define DffC (4*Dc)        // 2048

// ---- scratch (device globals; no cudaMalloc allowed) ----
// weights as fp16(32*w), hi only (1-term scheme)
__device__ __half g_fw[3145728];
#define FW_IN   0
#define FW_OUT  786432
#define FW_FF1  1048576
#define FW_FF2  2097152
// activations
__device__ __half g_a16  [(size_t)Mrows * Dc];    // act/32 (GEMM A operand)
__device__ __half g_ff16 [(size_t)Mrows * DffC];  // gelu out / 32
__device__ __half g_qkv16[(size_t)Mrows * D3];    // qkv, unscaled fp16
__device__ float  g_x1   [(size_t)Mrows * Dc];

// ============================================================
// helpers
// ============================================================
__device__ __forceinline__ uint32_t smem_u32(const void* p) {
    uint32_t a;
    asm("{ .reg .u64 t; cvta.to.shared.u64 t, %1; cvt.u32.u64 %0, t; }" : "=r"(a) : "l"(p));
    return a;
}
__device__ __forceinline__ uint32_t sw128(uint32_t o) { return o ^ ((o >> 3) & 0x70); }

__device__ __forceinline__ void cp16(uint32_t dst, const void* src) {
    asm volatile("cp.async.cg.shared.global [%0], [%1], 16;" :: "r"(dst), "l"(src) : "memory");
}
#define CP_COMMIT() asm volatile("cp.async.commit_group;" ::: "memory")
#define CP_WAIT1()  asm volatile("cp.async.wait_group 1;" ::: "memory")

__device__ __forceinline__ void ldm_x4(uint32_t* r, uint32_t addr) {
    asm volatile("ldmatrix.sync.aligned.m8n8.x4.shared.b16 {%0,%1,%2,%3}, [%4];"
                 : "=r"(r[0]), "=r"(r[1]), "=r"(r[2]), "=r"(r[3]) : "r"(addr));
}
__device__ __forceinline__ void mma_f16(float* c, const uint32_t* a, uint32_t b0, uint32_t b1) {
    asm volatile("mma.sync.aligned.m16n8k16.row.col.f32.f16.f16.f32 "
                 "{%0,%1,%2,%3}, {%4,%5,%6,%7}, {%8,%9}, {%0,%1,%2,%3};"
                 : "+f"(c[0]), "+f"(c[1]), "+f"(c[2]), "+f"(c[3])
                 : "r"(a[0]), "r"(a[1]), "r"(a[2]), "r"(a[3]), "r"(b0), "r"(b1));
}

// ============================================================
// weight conversion: w -> fp16(32*w)  (hi only)
// ============================================================
__global__ void wconv_attn(const float* __restrict__ in_w, const float* __restrict__ out_w,
                           __half* __restrict__ hi) {
    int i = blockIdx.x * 256 + threadIdx.x;          // float4 units
    float4 v;
    if (i < 196608) v = ((const float4*)in_w)[i];
    else            v = ((const float4*)out_w)[i - 196608];
    __half2 p0 = __floats2half2_rn(v.x * 32.0f, v.y * 32.0f);
    __half2 p1 = __floats2half2_rn(v.z * 32.0f, v.w * 32.0f);
    ((uint2*)hi)[i] = make_uint2(*reinterpret_cast<uint32_t*>(&p0),
                                 *reinterpret_cast<uint32_t*>(&p1));
}
__global__ void wconv_ff(const float* __restrict__ w1, const float* __restrict__ w2,
                         __half* __restrict__ hi) {
    int i = blockIdx.x * 256 + threadIdx.x;          // float4 units
    float4 v;
    if (i < 262144) v = ((const float4*)w1)[i];
    else            v = ((const float4*)w2)[i - 262144];
    __half2 p0 = __floats2half2_rn(v.x * 32.0f, v.y * 32.0f);
    __half2 p1 = __floats2half2_rn(v.z * 32.0f, v.w * 32.0f);
    ((uint2*)hi)[i] = make_uint2(*reinterpret_cast<uint32_t*>(&p0),
                                 *reinterpret_cast<uint32_t*>(&p1));
}

// ============================================================
// LayerNorm -> fp16(out/32)
// ============================================================
__global__ void ln_kernel(const float* __restrict__ x,
                          const float* __restrict__ g,
                          const float* __restrict__ b,
                          __half* __restrict__ h16) {
    int row = blockIdx.x;
    int t = threadIdx.x;                 // 0..127
    const float4* xr = (const float4*)(x + (size_t)row * Dc);
    float4 v = xr[t];
    float s  = v.x + v.y + v.z + v.w;
    float s2 = v.x*v.x + v.y*v.y + v.z*v.z + v.w*v.w;
    #pragma unroll
    for (int o = 16; o > 0; o >>= 1) {
        s  += __shfl_xor_sync(0xffffffffu, s,  o);
        s2 += __shfl_xor_sync(0xffffffffu, s2, o);
    }
    __shared__ float sh[8];
    int w = t >> 5;
    if ((t & 31) == 0) { sh[w*2] = s; sh[w*2+1] = s2; }
    __syncthreads();
    s  = sh[0] + sh[2] + sh[4] + sh[6];
    s2 = sh[1] + sh[3] + sh[5] + sh[7];
    float mu  = s * (1.0f / Dc);
    float var = s2 * (1.0f / Dc) - mu * mu;
    float rstd = rsqrtf(var + 1e-5f);
    float4 gv = ((const float4*)g)[t];
    float4 bv = ((const float4*)b)[t];
    float o0 = (v.x - mu) * rstd * gv.x + bv.x;
    float o1 = (v.y - mu) * rstd * gv.y + bv.y;
    float o2 = (v.z - mu) * rstd * gv.z + bv.z;
    float o3 = (v.w - mu) * rstd * gv.w + bv.w;
    __half2 p0 = __floats2half2_rn(o0 * 0.03125f, o1 * 0.03125f);
    __half2 p1 = __floats2half2_rn(o2 * 0.03125f, o3 * 0.03125f);
    size_t base = (size_t)row * Dc + t * 4;
    *(uint2*)(h16 + base) = make_uint2(*reinterpret_cast<uint32_t*>(&p0),
                                       *reinterpret_cast<uint32_t*>(&p1));
}

// ============================================================
// 1-term fp16 GEMM via mma.sync:
//   C[M,N] = (A/32)[M,K] @ (32*B)[N,K]^T + bias  (fp32 accum, scale cancels)
// 128x128 block, 8 warps (2m x 4n, each 64x32), BK=64,
// 3-stage cp.async (stage = Ahi 16KB + Bhi 16KB = 32KB; 96KB -> 2 CTAs/SM)
// EPI: 0=bias->fp16 (qkv), 1=bias+residual->fp32, 2=bias+GELU->fp16(/32)
// ============================================================
#define TB  16384            // one 128x64 fp16 tile
#define SSZ (2*TB)           // stage: Ahi, Bhi
#define SM_SZ (3*SSZ)        // 98304

template<int EPI>
__global__ __launch_bounds__(256, 2)
void gemm_mma(const __half* __restrict__ Ahi, const __half* __restrict__ Bhi,
              const float* __restrict__ bias, const float* __restrict__ res,
              float* __restrict__ C, __half* __restrict__ C16,
              int M, int N, int K)
{
    extern __shared__ __align__(128) char smem[];
    uint32_t sb = smem_u32(smem);
    int tid = threadIdx.x;
    int lane = tid & 31, wid = tid >> 5;
    int bm = blockIdx.y * 128, bn = blockIdx.x * 128;
    int m0 = (wid & 1) * 64;          // warp tile: 64 (m) x 32 (n)
    int n0 = (wid >> 1) * 32;

    float acc[4][4][4];
    #pragma unroll
    for (int i = 0; i < 4; i++)
        #pragma unroll
        for (int j = 0; j < 4; j++)
            #pragma unroll
            for (int k = 0; k < 4; k++) acc[i][j][k] = 0.0f;

    auto load_stage = [&](int st, int k0) {
        uint32_t base = sb + st * SSZ;
        #pragma unroll
        for (int t = 0; t < 4; t++) {
            int line = tid + t * 256;           // 0..1023
            int r  = line >> 3;                 // row 0..127
            int cc = line & 7;                  // 16B column chunk
            uint32_t d = sw128((uint32_t)(r * 128 + cc * 16));
            cp16(base + d,      Ahi + (size_t)(bm + r) * K + k0 + cc * 8);
            cp16(base + TB + d, Bhi + (size_t)(bn + r) * K + k0 + cc * 8);
        }
    };

    int nk = K >> 6;
    load_stage(0, 0);  CP_COMMIT();
    load_stage(1, 64); CP_COMMIT();

    int st = 0;
    for (int ch = 0; ch < nk; ch++) {
        CP_WAIT1();                 // oldest group (chunk ch) complete
        __syncthreads();            // all warps past compute(ch-1)
        if (ch + 2 < nk) {
            int st2 = st + 2; if (st2 >= 3) st2 -= 3;
            load_stage(st2, (ch + 2) * 64);
        }
        CP_COMMIT();                // always commit (possibly empty) group

        uint32_t abase = sb + st * SSZ;
        uint32_t bbase = abase + TB;

        #pragma unroll
        for (int ks = 0; ks < 4; ks++) {
            int k0 = ks * 16;
            int frow = (lane & 7) + ((lane >> 3) & 1) * 8;
            int fcol = k0 + (lane >> 4) * 8;
            uint32_t ahi[4][4], bh[2][4];
            #pragma unroll
            for (int mi = 0; mi < 4; mi++) {
                uint32_t o = sw128((uint32_t)((m0 + mi*16 + frow) * 128 + fcol * 2));
                ldm_x4(ahi[mi], abase + o);
            }
            #pragma unroll
            for (int pr = 0; pr < 2; pr++) {
                uint32_t o = sw128((uint32_t)((n0 + pr*16 + frow) * 128 + fcol * 2));
                ldm_x4(bh[pr], bbase + o);
            }
            #pragma unroll
            for (int mi = 0; mi < 4; mi++)
                #pragma unroll
                for (int ni = 0; ni < 4; ni++) {
                    int pr = ni >> 1, sel = ni & 1;
                    mma_f16(acc[mi][ni], ahi[mi], bh[pr][sel], bh[pr][sel+2]);
                }
        }
        st++; if (st >= 3) st = 0;
        // next iteration's top barrier protects stage reuse
    }

    // epilogue: direct stores (each thread owns 2 consecutive cols per frag)
    int gr = lane >> 2, tq = lane & 3;
    #pragma unroll
    for (int mi = 0; mi < 4; mi++) {
        #pragma unroll
        for (int ni = 0; ni < 4; ni++) {
            int col = bn + n0 + ni*8 + tq*2;
            float b0 = bias[col], b1 = bias[col + 1];
            #pragma unroll
            for (int half = 0; half < 2; half++) {
                int row = bm + m0 + mi*16 + gr + half*8;
                float v0 = acc[mi][ni][half*2 + 0] + b0;
                float v1 = acc[mi][ni][half*2 + 1] + b1;
                size_t off = (size_t)row * N + col;
                if (EPI == 1) {
                    float2 r2 = *(const float2*)(res + off);
                    v0 += r2.x; v1 += r2.y;
                    *(float2*)(C + off) = make_float2(v0, v1);
                } else if (EPI == 2) {
                    v0 = 0.5f * v0 * (1.0f + erff(v0 * 0.7071067811865475f));
                    v1 = 0.5f * v1 * (1.0f + erff(v1 * 0.7071067811865475f));
                    __half2 p = __floats2half2_rn(v0 * 0.03125f, v1 * 0.03125f);
                    *(uint32_t*)(C16 + off) = *reinterpret_cast<uint32_t*>(&p);
                } else {
                    __half2 p = __floats2half2_rn(v0, v1);
                    *(uint32_t*)(C16 + off) = *reinterpret_cast<uint32_t*>(&p);
                }
            }
        }
    }
}

// ============================================================
// Local attention: one warp per (b,s,h); fp16 qkv in, fp16(ctx/32) out
// ============================================================
__global__ void attn_kernel(const __half* __restrict__ qkv16,
                            __half* __restrict__ ctx16) {
    int gwarp = (blockIdx.x * blockDim.x + threadIdx.x) >> 5;
    int lane = threadIdx.x & 31;
    int h  = gwarp & (Hc - 1);
    int bs = gwarp >> 3;
    int s  = bs & (Sc - 1);
    int rowbase = bs - s;

    const __half2* qr = (const __half2*)(qkv16 + (size_t)bs * D3 + h * Dhc);
    float2 q = __half22float2(qr[lane]);

    float e[9];
    float mx = -INFINITY;
    #pragma unroll
    for (int jj = 0; jj < 9; jj++) {
        int j = s - 4 + jj;
        float sc = -INFINITY;
        if (j >= 0 && j < Sc) {
            const __half2* kr = (const __half2*)(qkv16 + (size_t)(rowbase + j) * D3 + Dc + h * Dhc);
            float2 k2 = __half22float2(kr[lane]);
            float p = q.x * k2.x + q.y * k2.y;
            #pragma unroll
            for (int o = 16; o > 0; o >>= 1)
                p += __shfl_xor_sync(0xffffffffu, p, o);
            sc = p * 0.125f;
        }
        e[jj] = sc;
        mx = fmaxf(mx, sc);
    }
    float sum = 0.0f;
    #pragma unroll
    for (int jj = 0; jj < 9; jj++) {
        e[jj] = expf(e[jj] - mx);
        sum += e[jj];
    }
    float inv = 1.0f / sum;
    float c0 = 0.0f, c1 = 0.0f;
    #pragma unroll
    for (int jj = 0; jj < 9; jj++) {
        int j = s - 4 + jj;
        if (j >= 0 && j < Sc) {
            const __half2* vr = (const __half2*)(qkv16 + (size_t)(rowbase + j) * D3 + 2*Dc + h * Dhc);
            float2 v2 = __half22float2(vr[lane]);
            float w = e[jj] * inv;
            c0 = fmaf(w, v2.x, c0);
            c1 = fmaf(w, v2.y, c1);
        }
    }
    __half2 p = __floats2half2_rn(c0 * 0.03125f, c1 * 0.03125f);
    *(uint32_t*)(ctx16 + (size_t)bs * Dc + h * Dhc + 2*lane) = *reinterpret_cast<uint32_t*>(&p);
}

// ============================================================
extern "C" void kernel_launch(void* const* d_in, const int* in_sizes, int n_in,
                              void* d_out, int out_size) {
    const float* x     = (const float*)d_in[0];
    const float* in_w  = (const float*)d_in[1];
    const float* in_b  = (const float*)d_in[2];
    const float* out_w = (const float*)d_in[3];
    const float* out_b = (const float*)d_in[4];
    const float* ff_w1 = (const float*)d_in[5];
    const float* ff_b1 = (const float*)d_in[6];
    const float* ff_w2 = (const float*)d_in[7];
    const float* ff_b2 = (const float*)d_in[8];
    const float* ln1_g = (const float*)d_in[9];
    const float* ln1_b = (const float*)d_in[10];
    const float* ln2_g = (const float*)d_in[11];
    const float* ln2_b = (const float*)d_in[12];
    float* out = (float*)d_out;

    __half *fw, *a16, *ff16, *qkv16;
    float *x1;
    cudaGetSymbolAddress((void**)&fw,    g_fw);
    cudaGetSymbolAddress((void**)&a16,   g_a16);
    cudaGetSymbolAddress((void**)&ff16,  g_ff16);
    cudaGetSymbolAddress((void**)&qkv16, g_qkv16);
    cudaGetSymbolAddress((void**)&x1,    g_x1);

    cudaFuncSetAttribute(gemm_mma<0>, cudaFuncAttributeMaxDynamicSharedMemorySize, SM_SZ);
    cudaFuncSetAttribute(gemm_mma<1>, cudaFuncAttributeMaxDynamicSharedMemorySize, SM_SZ);
    cudaFuncSetAttribute(gemm_mma<2>, cudaFuncAttributeMaxDynamicSharedMemorySize, SM_SZ);

    // weight conversions (fp16(32*w) hi only)
    wconv_attn<<<1024, 256>>>(in_w, out_w, fw);
    wconv_ff  <<<2048, 256>>>(ff_w1, ff_w2, fw + FW_FF1);

    // 1) a16 = fp16(LN1(x)/32)
    ln_kernel<<<Mrows, 128>>>(x, ln1_g, ln1_b, a16);
    // 2) qkv16 = fp16(a16 @ (32*in_w)^T + in_b)
    gemm_mma<0><<<dim3(D3/128, Mrows/128), 256, SM_SZ>>>(
        a16, fw + FW_IN, in_b, nullptr, nullptr, qkv16, Mrows, D3, Dc);
    // 3) a16 = fp16(attention(qkv16)/32)
    attn_kernel<<<(Mrows * Hc * 32) / 256, 256>>>(qkv16, a16);
    // 4) x1 = x + a16 @ (32*out_w)^T + out_b
    gemm_mma<1><<<dim3(Dc/128, Mrows/128), 256, SM_SZ>>>(
        a16, fw + FW_OUT, out_b, x, x1, nullptr, Mrows, Dc, Dc);
    // 5) a16 = fp16(LN2(x1)/32)
    ln_kernel<<<Mrows, 128>>>(x1, ln2_g, ln2_b, a16);
    // 6) ff16 = fp16(gelu(a16 @ (32*ff_w1)^T + ff_b1)/32)
    gemm_mma<2><<<dim3(DffC/128, Mrows/128), 256, SM_SZ>>>(
        a16, fw + FW_FF1, ff_b1, nullptr, nullptr, ff16, Mrows, DffC, Dc);
    // 7) out = x1 + ff16 @ (32*ff_w2)^T + ff_b2
    gemm_mma<1><<<dim3(Dc/128, Mrows/128), 256, SM_SZ>>>(
        ff16, fw + FW_FF2, ff_b2, x1, out, nullptr, Mrows, Dc, DffC);
}

// round 8
// speedup vs baseline: 1.5525x; 1.0011x over previous
#include <cuda_runtime.h>
#include <cuda_fp16.h>
#include <math.h>
#include <stdint.h>

// Problem constants
#define Bc   4
#define Sc   2048
#define Dc   512
#define Hc   8
#define Dhc  64
#define Mrows (Bc*Sc)      // 8192
#define D3   (3*Dc)        // 1536
#define DffC (4*Dc)        // 2048

// ---- scratch (device globals; no cudaMalloc allowed) ----
// weights as fp16(32*w)
__device__ __half g_fw[3145728];
#define FW_IN   0
#define FW_OUT  786432
#define FW_FF1  1048576
#define FW_FF2  2097152
// activations
__device__ __half g_a16  [(size_t)Mrows * Dc];    // act/32 (GEMM A operand)
__device__ __half g_ff16 [(size_t)Mrows * DffC];  // gelu out / 32
__device__ __half g_qkv16[(size_t)Mrows * D3];    // qkv, unscaled fp16
__device__ float  g_x1   [(size_t)Mrows * Dc];

// ============================================================
// helpers
// ============================================================
__device__ __forceinline__ uint32_t smem_u32(const void* p) {
    uint32_t a;
    asm("{ .reg .u64 t; cvta.to.shared.u64 t, %1; cvt.u32.u64 %0, t; }" : "=r"(a) : "l"(p));
    return a;
}
__device__ __forceinline__ uint32_t sw128(uint32_t o) { return o ^ ((o >> 3) & 0x70); }

__device__ __forceinline__ void cp16(uint32_t dst, const void* src) {
    asm volatile("cp.async.cg.shared.global [%0], [%1], 16;" :: "r"(dst), "l"(src) : "memory");
}
#define CP_COMMIT() asm volatile("cp.async.commit_group;" ::: "memory")
#define CP_WAIT1()  asm volatile("cp.async.wait_group 1;" ::: "memory")

__device__ __forceinline__ void ldm_x4(uint32_t* r, uint32_t addr) {
    asm volatile("ldmatrix.sync.aligned.m8n8.x4.shared.b16 {%0,%1,%2,%3}, [%4];"
                 : "=r"(r[0]), "=r"(r[1]), "=r"(r[2]), "=r"(r[3]) : "r"(addr));
}
__device__ __forceinline__ void mma_f16(float* c, const uint32_t* a, uint32_t b0, uint32_t b1) {
    asm volatile("mma.sync.aligned.m16n8k16.row.col.f32.f16.f16.f32 "
                 "{%0,%1,%2,%3}, {%4,%5,%6,%7}, {%8,%9}, {%0,%1,%2,%3};"
                 : "+f"(c[0]), "+f"(c[1]), "+f"(c[2]), "+f"(c[3])
                 : "r"(a[0]), "r"(a[1]), "r"(a[2]), "r"(a[3]), "r"(b0), "r"(b1));
}

// ============================================================
// weight conversion: w -> fp16(32*w)
// ============================================================
__global__ void wconv_attn(const float* __restrict__ in_w, const float* __restrict__ out_w,
                           __half* __restrict__ hi) {
    int i = blockIdx.x * 256 + threadIdx.x;          // float4 units
    float4 v;
    if (i < 196608) v = ((const float4*)in_w)[i];
    else            v = ((const float4*)out_w)[i - 196608];
    __half2 p0 = __floats2half2_rn(v.x * 32.0f, v.y * 32.0f);
    __half2 p1 = __floats2half2_rn(v.z * 32.0f, v.w * 32.0f);
    ((uint2*)hi)[i] = make_uint2(*reinterpret_cast<uint32_t*>(&p0),
                                 *reinterpret_cast<uint32_t*>(&p1));
}
__global__ void wconv_ff(const float* __restrict__ w1, const float* __restrict__ w2,
                         __half* __restrict__ hi) {
    int i = blockIdx.x * 256 + threadIdx.x;          // float4 units
    float4 v;
    if (i < 262144) v = ((const float4*)w1)[i];
    else            v = ((const float4*)w2)[i - 262144];
    __half2 p0 = __floats2half2_rn(v.x * 32.0f, v.y * 32.0f);
    __half2 p1 = __floats2half2_rn(v.z * 32.0f, v.w * 32.0f);
    ((uint2*)hi)[i] = make_uint2(*reinterpret_cast<uint32_t*>(&p0),
                                 *reinterpret_cast<uint32_t*>(&p1));
}

// ============================================================
// LayerNorm -> fp16(out/32)
// ============================================================
__global__ void ln_kernel(const float* __restrict__ x,
                          const float* __restrict__ g,
                          const float* __restrict__ b,
                          __half* __restrict__ h16) {
    int row = blockIdx.x;
    int t = threadIdx.x;                 // 0..127
    const float4* xr = (const float4*)(x + (size_t)row * Dc);
    float4 v = xr[t];
    float s  = v.x + v.y + v.z + v.w;
    float s2 = v.x*v.x + v.y*v.y + v.z*v.z + v.w*v.w;
    #pragma unroll
    for (int o = 16; o > 0; o >>= 1) {
        s  += __shfl_xor_sync(0xffffffffu, s,  o);
        s2 += __shfl_xor_sync(0xffffffffu, s2, o);
    }
    __shared__ float sh[8];
    int w = t >> 5;
    if ((t & 31) == 0) { sh[w*2] = s; sh[w*2+1] = s2; }
    __syncthreads();
    s  = sh[0] + sh[2] + sh[4] + sh[6];
    s2 = sh[1] + sh[3] + sh[5] + sh[7];
    float mu  = s * (1.0f / Dc);
    float var = s2 * (1.0f / Dc) - mu * mu;
    float rstd = rsqrtf(var + 1e-5f);
    float4 gv = ((const float4*)g)[t];
    float4 bv = ((const float4*)b)[t];
    float o0 = (v.x - mu) * rstd * gv.x + bv.x;
    float o1 = (v.y - mu) * rstd * gv.y + bv.y;
    float o2 = (v.z - mu) * rstd * gv.z + bv.z;
    float o3 = (v.w - mu) * rstd * gv.w + bv.w;
    __half2 p0 = __floats2half2_rn(o0 * 0.03125f, o1 * 0.03125f);
    __half2 p1 = __floats2half2_rn(o2 * 0.03125f, o3 * 0.03125f);
    size_t base = (size_t)row * Dc + t * 4;
    *(uint2*)(h16 + base) = make_uint2(*reinterpret_cast<uint32_t*>(&p0),
                                       *reinterpret_cast<uint32_t*>(&p1));
}

// ============================================================
// 1-term fp16 GEMM via mma.sync:
//   C[M,N] = (A/32)[M,K] @ (32*B)[N,K]^T + bias  (fp32 accum, scale cancels)
// 128x128 block, 4 warps (2m x 2n, each 64x64), BK=64,
// 3-stage cp.async (stage 32KB; 96KB smem -> 2 CTAs/SM)
// EPI: 0=bias->fp16 (qkv), 1=bias+residual->fp32, 2=bias+GELU->fp16(/32)
// ============================================================
#define TB  16384            // one 128x64 fp16 tile
#define SSZ (2*TB)           // stage: Ahi, Bhi
#define SM_SZ (3*SSZ)        // 98304

template<int EPI>
__global__ __launch_bounds__(128, 2)
void gemm_mma(const __half* __restrict__ Ahi, const __half* __restrict__ Bhi,
              const float* __restrict__ bias, const float* __restrict__ res,
              float* __restrict__ C, __half* __restrict__ C16,
              int M, int N, int K)
{
    extern __shared__ __align__(128) char smem[];
    uint32_t sb = smem_u32(smem);
    int tid = threadIdx.x;
    int lane = tid & 31, wid = tid >> 5;
    int bm = blockIdx.y * 128, bn = blockIdx.x * 128;
    int m0 = (wid & 1) * 64;          // warp tile: 64 (m) x 64 (n)
    int n0 = (wid >> 1) * 64;

    float acc[4][8][4];
    #pragma unroll
    for (int i = 0; i < 4; i++)
        #pragma unroll
        for (int j = 0; j < 8; j++)
            #pragma unroll
            for (int k = 0; k < 4; k++) acc[i][j][k] = 0.0f;

    auto load_stage = [&](int st, int k0) {
        uint32_t base = sb + st * SSZ;
        #pragma unroll
        for (int t = 0; t < 8; t++) {
            int line = tid + t * 128;           // 0..1023
            int r  = line >> 3;                 // row 0..127
            int cc = line & 7;                  // 16B column chunk
            uint32_t d = sw128((uint32_t)(r * 128 + cc * 16));
            cp16(base + d,      Ahi + (size_t)(bm + r) * K + k0 + cc * 8);
            cp16(base + TB + d, Bhi + (size_t)(bn + r) * K + k0 + cc * 8);
        }
    };

    int nk = K >> 6;
    load_stage(0, 0);  CP_COMMIT();
    load_stage(1, 64); CP_COMMIT();

    int st = 0;
    for (int ch = 0; ch < nk; ch++) {
        CP_WAIT1();                 // oldest group (chunk ch) complete
        __syncthreads();            // all warps past compute(ch-1)
        if (ch + 2 < nk) {
            int st2 = st + 2; if (st2 >= 3) st2 -= 3;
            load_stage(st2, (ch + 2) * 64);
        }
        CP_COMMIT();                // always commit (possibly empty) group

        uint32_t abase = sb + st * SSZ;
        uint32_t bbase = abase + TB;

        #pragma unroll
        for (int ks = 0; ks < 4; ks++) {
            int k0 = ks * 16;
            int frow = (lane & 7) + ((lane >> 3) & 1) * 8;
            int fcol = k0 + (lane >> 4) * 8;
            uint32_t ahi[4][4], bh[4][4];
            #pragma unroll
            for (int mi = 0; mi < 4; mi++) {
                uint32_t o = sw128((uint32_t)((m0 + mi*16 + frow) * 128 + fcol * 2));
                ldm_x4(ahi[mi], abase + o);
            }
            #pragma unroll
            for (int pr = 0; pr < 4; pr++) {
                uint32_t o = sw128((uint32_t)((n0 + pr*16 + frow) * 128 + fcol * 2));
                ldm_x4(bh[pr], bbase + o);
            }
            #pragma unroll
            for (int mi = 0; mi < 4; mi++)
                #pragma unroll
                for (int ni = 0; ni < 8; ni++) {
                    int pr = ni >> 1, sel = ni & 1;
                    mma_f16(acc[mi][ni], ahi[mi], bh[pr][sel], bh[pr][sel+2]);
                }
        }
        st++; if (st >= 3) st = 0;
        // next iteration's top barrier protects stage reuse
    }

    // epilogue: direct stores (each thread owns 2 consecutive cols per frag)
    int gr = lane >> 2, tq = lane & 3;
    #pragma unroll
    for (int mi = 0; mi < 4; mi++) {
        #pragma unroll
        for (int ni = 0; ni < 8; ni++) {
            int col = bn + n0 + ni*8 + tq*2;
            float b0 = bias[col], b1 = bias[col + 1];
            #pragma unroll
            for (int half = 0; half < 2; half++) {
                int row = bm + m0 + mi*16 + gr + half*8;
                float v0 = acc[mi][ni][half*2 + 0] + b0;
                float v1 = acc[mi][ni][half*2 + 1] + b1;
                size_t off = (size_t)row * N + col;
                if (EPI == 1) {
                    float2 r2 = *(const float2*)(res + off);
                    v0 += r2.x; v1 += r2.y;
                    *(float2*)(C + off) = make_float2(v0, v1);
                } else if (EPI == 2) {
                    v0 = 0.5f * v0 * (1.0f + erff(v0 * 0.7071067811865475f));
                    v1 = 0.5f * v1 * (1.0f + erff(v1 * 0.7071067811865475f));
                    __half2 p = __floats2half2_rn(v0 * 0.03125f, v1 * 0.03125f);
                    *(uint32_t*)(C16 + off) = *reinterpret_cast<uint32_t*>(&p);
                } else {
                    __half2 p = __floats2half2_rn(v0, v1);
                    *(uint32_t*)(C16 + off) = *reinterpret_cast<uint32_t*>(&p);
                }
            }
        }
    }
}

// ============================================================
// Local attention: one warp per (b,s,h); fp16 qkv in, fp16(ctx/32) out
// ============================================================
__global__ void attn_kernel(const __half* __restrict__ qkv16,
                            __half* __restrict__ ctx16) {
    int gwarp = (blockIdx.x * blockDim.x + threadIdx.x) >> 5;
    int lane = threadIdx.x & 31;
    int h  = gwarp & (Hc - 1);
    int bs = gwarp >> 3;
    int s  = bs & (Sc - 1);
    int rowbase = bs - s;

    const __half2* qr = (const __half2*)(qkv16 + (size_t)bs * D3 + h * Dhc);
    float2 q = __half22float2(qr[lane]);

    float e[9];
    float mx = -INFINITY;
    #pragma unroll
    for (int jj = 0; jj < 9; jj++) {
        int j = s - 4 + jj;
        float sc = -INFINITY;
        if (j >= 0 && j < Sc) {
            const __half2* kr = (const __half2*)(qkv16 + (size_t)(rowbase + j) * D3 + Dc + h * Dhc);
            float2 k2 = __half22float2(kr[lane]);
            float p = q.x * k2.x + q.y * k2.y;
            #pragma unroll
            for (int o = 16; o > 0; o >>= 1)
                p += __shfl_xor_sync(0xffffffffu, p, o);
            sc = p * 0.125f;
        }
        e[jj] = sc;
        mx = fmaxf(mx, sc);
    }
    float sum = 0.0f;
    #pragma unroll
    for (int jj = 0; jj < 9; jj++) {
        e[jj] = expf(e[jj] - mx);
        sum += e[jj];
    }
    float inv = 1.0f / sum;
    float c0 = 0.0f, c1 = 0.0f;
    #pragma unroll
    for (int jj = 0; jj < 9; jj++) {
        int j = s - 4 + jj;
        if (j >= 0 && j < Sc) {
            const __half2* vr = (const __half2*)(qkv16 + (size_t)(rowbase + j) * D3 + 2*Dc + h * Dhc);
            float2 v2 = __half22float2(vr[lane]);
            float w = e[jj] * inv;
            c0 = fmaf(w, v2.x, c0);
            c1 = fmaf(w, v2.y, c1);
        }
    }
    __half2 p = __floats2half2_rn(c0 * 0.03125f, c1 * 0.03125f);
    *(uint32_t*)(ctx16 + (size_t)bs * Dc + h * Dhc + 2*lane) = *reinterpret_cast<uint32_t*>(&p);
}

// ============================================================
extern "C" void kernel_launch(void* const* d_in, const int* in_sizes, int n_in,
                              void* d_out, int out_size) {
    const float* x     = (const float*)d_in[0];
    const float* in_w  = (const float*)d_in[1];
    const float* in_b  = (const float*)d_in[2];
    const float* out_w = (const float*)d_in[3];
    const float* out_b = (const float*)d_in[4];
    const float* ff_w1 = (const float*)d_in[5];
    const float* ff_b1 = (const float*)d_in[6];
    const float* ff_w2 = (const float*)d_in[7];
    const float* ff_b2 = (const float*)d_in[8];
    const float* ln1_g = (const float*)d_in[9];
    const float* ln1_b = (const float*)d_in[10];
    const float* ln2_g = (const float*)d_in[11];
    const float* ln2_b = (const float*)d_in[12];
    float* out = (float*)d_out;

    __half *fw, *a16, *ff16, *qkv16;
    float *x1;
    cudaGetSymbolAddress((void**)&fw,    g_fw);
    cudaGetSymbolAddress((void**)&a16,   g_a16);
    cudaGetSymbolAddress((void**)&ff16,  g_ff16);
    cudaGetSymbolAddress((void**)&qkv16, g_qkv16);
    cudaGetSymbolAddress((void**)&x1,    g_x1);

    cudaFuncSetAttribute(gemm_mma<0>, cudaFuncAttributeMaxDynamicSharedMemorySize, SM_SZ);
    cudaFuncSetAttribute(gemm_mma<1>, cudaFuncAttributeMaxDynamicSharedMemorySize, SM_SZ);
    cudaFuncSetAttribute(gemm_mma<2>, cudaFuncAttributeMaxDynamicSharedMemorySize, SM_SZ);

    // weight conversions (fp16(32*w))
    wconv_attn<<<1024, 256>>>(in_w, out_w, fw);
    wconv_ff  <<<2048, 256>>>(ff_w1, ff_w2, fw + FW_FF1);

    // 1) a16 = fp16(LN1(x)/32)
    ln_kernel<<<Mrows, 128>>>(x, ln1_g, ln1_b, a16);
    // 2) qkv16 = fp16(a16 @ (32*in_w)^T + in_b)
    gemm_mma<0><<<dim3(D3/128, Mrows/128), 128, SM_SZ>>>(
        a16, fw + FW_IN, in_b, nullptr, nullptr, qkv16, Mrows, D3, Dc);
    // 3) a16 = fp16(attention(qkv16)/32)
    attn_kernel<<<(Mrows * Hc * 32) / 256, 256>>>(qkv16, a16);
    // 4) x1 = x + a16 @ (32*out_w)^T + out_b
    gemm_mma<1><<<dim3(Dc/128, Mrows/128), 128, SM_SZ>>>(
        a16, fw + FW_OUT, out_b, x, x1, nullptr, Mrows, Dc, Dc);
    // 5) a16 = fp16(LN2(x1)/32)
    ln_kernel<<<Mrows, 128>>>(x1, ln2_g, ln2_b, a16);
    // 6) ff16 = fp16(gelu(a16 @ (32*ff_w1)^T + ff_b1)/32)
    gemm_mma<2><<<dim3(DffC/128, Mrows/128), 128, SM_SZ>>>(
        a16, fw + FW_FF1, ff_b1, nullptr, nullptr, ff16, Mrows, DffC, Dc);
    // 7) out = x1 + ff16 @ (32*ff_w2)^T + ff_b2
    gemm_mma<1><<<dim3(Dc/128, Mrows/128), 128, SM_SZ>>>(
        ff16, fw + FW_FF2, ff_b2, x1, out, nullptr, Mrows, Dc, DffC);
}

// round 9
// speedup vs baseline: 1.6322x; 1.0513x over previous
#include <cuda_runtime.h>
#include <cuda_fp16.h>
#include <math.h>
#include <stdint.h>

// Problem constants
#define Bc   4
#define Sc   2048
#define Dc   512
#define Hc   8
#define Dhc  64
#define Mrows (Bc*Sc)      // 8192
#define D3   (3*Dc)        // 1536
#define DffC (4*Dc)        // 2048

// ---- scratch (device globals; no cudaMalloc allowed) ----
__device__ __half g_fw[3145728];
#define FW_IN   0
#define FW_OUT  786432
#define FW_FF1  1048576
#define FW_FF2  2097152
__device__ __half g_a16  [(size_t)Mrows * Dc];
__device__ __half g_ff16 [(size_t)Mrows * DffC];
__device__ __half g_qkv16[(size_t)Mrows * D3];
__device__ float  g_x1   [(size_t)Mrows * Dc];

// ============================================================
// helpers
// ============================================================
__device__ __forceinline__ uint32_t smem_u32(const void* p) {
    uint32_t a;
    asm("{ .reg .u64 t; cvta.to.shared.u64 t, %1; cvt.u32.u64 %0, t; }" : "=r"(a) : "l"(p));
    return a;
}
__device__ __forceinline__ uint32_t sw128(uint32_t o) { return o ^ ((o >> 3) & 0x70); }

__device__ __forceinline__ void cp16(uint32_t dst, const void* src) {
    asm volatile("cp.async.cg.shared.global [%0], [%1], 16;" :: "r"(dst), "l"(src) : "memory");
}
#define CP_COMMIT() asm volatile("cp.async.commit_group;" ::: "memory")
#define CP_WAIT1()  asm volatile("cp.async.wait_group 1;" ::: "memory")

__device__ __forceinline__ void ldm_x4(uint32_t* r, uint32_t addr) {
    asm volatile("ldmatrix.sync.aligned.m8n8.x4.shared.b16 {%0,%1,%2,%3}, [%4];"
                 : "=r"(r[0]), "=r"(r[1]), "=r"(r[2]), "=r"(r[3]) : "r"(addr));
}
__device__ __forceinline__ void mma_f16(float* c, const uint32_t* a, uint32_t b0, uint32_t b1) {
    asm volatile("mma.sync.aligned.m16n8k16.row.col.f32.f16.f16.f32 "
                 "{%0,%1,%2,%3}, {%4,%5,%6,%7}, {%8,%9}, {%0,%1,%2,%3};"
                 : "+f"(c[0]), "+f"(c[1]), "+f"(c[2]), "+f"(c[3])
                 : "r"(a[0]), "r"(a[1]), "r"(a[2]), "r"(a[3]), "r"(b0), "r"(b1));
}

// ============================================================
// weight conversion: all four weights -> fp16(32*w), one launch
// ============================================================
__global__ void wconv_all(const float* __restrict__ in_w, const float* __restrict__ out_w,
                          const float* __restrict__ w1, const float* __restrict__ w2,
                          __half* __restrict__ hi) {
    int i = blockIdx.x * 256 + threadIdx.x;          // float4 units, 0..786431
    float4 v;
    if      (i < 196608) v = ((const float4*)in_w)[i];
    else if (i < 262144) v = ((const float4*)out_w)[i - 196608];
    else if (i < 524288) v = ((const float4*)w1)[i - 262144];
    else                 v = ((const float4*)w2)[i - 524288];
    __half2 p0 = __floats2half2_rn(v.x * 32.0f, v.y * 32.0f);
    __half2 p1 = __floats2half2_rn(v.z * 32.0f, v.w * 32.0f);
    ((uint2*)hi)[i] = make_uint2(*reinterpret_cast<uint32_t*>(&p0),
                                 *reinterpret_cast<uint32_t*>(&p1));
}

// ============================================================
// LayerNorm -> fp16(out/32)
// ============================================================
__global__ void ln_kernel(const float* __restrict__ x,
                          const float* __restrict__ g,
                          const float* __restrict__ b,
                          __half* __restrict__ h16) {
    int row = blockIdx.x;
    int t = threadIdx.x;                 // 0..127
    const float4* xr = (const float4*)(x + (size_t)row * Dc);
    float4 v = xr[t];
    float s  = v.x + v.y + v.z + v.w;
    float s2 = v.x*v.x + v.y*v.y + v.z*v.z + v.w*v.w;
    #pragma unroll
    for (int o = 16; o > 0; o >>= 1) {
        s  += __shfl_xor_sync(0xffffffffu, s,  o);
        s2 += __shfl_xor_sync(0xffffffffu, s2, o);
    }
    __shared__ float sh[8];
    int w = t >> 5;
    if ((t & 31) == 0) { sh[w*2] = s; sh[w*2+1] = s2; }
    __syncthreads();
    s  = sh[0] + sh[2] + sh[4] + sh[6];
    s2 = sh[1] + sh[3] + sh[5] + sh[7];
    float mu  = s * (1.0f / Dc);
    float var = s2 * (1.0f / Dc) - mu * mu;
    float rstd = rsqrtf(var + 1e-5f);
    float4 gv = ((const float4*)g)[t];
    float4 bv = ((const float4*)b)[t];
    float o0 = (v.x - mu) * rstd * gv.x + bv.x;
    float o1 = (v.y - mu) * rstd * gv.y + bv.y;
    float o2 = (v.z - mu) * rstd * gv.z + bv.z;
    float o3 = (v.w - mu) * rstd * gv.w + bv.w;
    __half2 p0 = __floats2half2_rn(o0 * 0.03125f, o1 * 0.03125f);
    __half2 p1 = __floats2half2_rn(o2 * 0.03125f, o3 * 0.03125f);
    size_t base = (size_t)row * Dc + t * 4;
    *(uint2*)(h16 + base) = make_uint2(*reinterpret_cast<uint32_t*>(&p0),
                                       *reinterpret_cast<uint32_t*>(&p1));
}

// ============================================================
// 128x128 GEMM (4 warps of 64x64), 3-stage, 2 CTAs/SM.
// EPI: 0=bias->fp16, 2=bias+GELU->fp16(/32)
// ============================================================
#define TB  16384
#define SSZ (2*TB)
#define SM_SZ (3*SSZ)        // 98304

template<int EPI>
__global__ __launch_bounds__(128, 2)
void gemm_mma(const __half* __restrict__ Ahi, const __half* __restrict__ Bhi,
              const float* __restrict__ bias,
              __half* __restrict__ C16,
              int M, int N, int K)
{
    extern __shared__ __align__(128) char smem[];
    uint32_t sb = smem_u32(smem);
    int tid = threadIdx.x;
    int lane = tid & 31, wid = tid >> 5;
    int bm = blockIdx.y * 128, bn = blockIdx.x * 128;
    int m0 = (wid & 1) * 64;
    int n0 = (wid >> 1) * 64;

    float acc[4][8][4];
    #pragma unroll
    for (int i = 0; i < 4; i++)
        #pragma unroll
        for (int j = 0; j < 8; j++)
            #pragma unroll
            for (int k = 0; k < 4; k++) acc[i][j][k] = 0.0f;

    auto load_stage = [&](int st, int k0) {
        uint32_t base = sb + st * SSZ;
        #pragma unroll
        for (int t = 0; t < 8; t++) {
            int line = tid + t * 128;
            int r  = line >> 3;
            int cc = line & 7;
            uint32_t d = sw128((uint32_t)(r * 128 + cc * 16));
            cp16(base + d,      Ahi + (size_t)(bm + r) * K + k0 + cc * 8);
            cp16(base + TB + d, Bhi + (size_t)(bn + r) * K + k0 + cc * 8);
        }
    };

    int nk = K >> 6;
    load_stage(0, 0);  CP_COMMIT();
    load_stage(1, 64); CP_COMMIT();

    int st = 0;
    for (int ch = 0; ch < nk; ch++) {
        CP_WAIT1();
        __syncthreads();
        if (ch + 2 < nk) {
            int st2 = st + 2; if (st2 >= 3) st2 -= 3;
            load_stage(st2, (ch + 2) * 64);
        }
        CP_COMMIT();

        uint32_t abase = sb + st * SSZ;
        uint32_t bbase = abase + TB;

        #pragma unroll
        for (int ks = 0; ks < 4; ks++) {
            int k0 = ks * 16;
            int frow = (lane & 7) + ((lane >> 3) & 1) * 8;
            int fcol = k0 + (lane >> 4) * 8;
            uint32_t ahi[4][4], bh[4][4];
            #pragma unroll
            for (int mi = 0; mi < 4; mi++) {
                uint32_t o = sw128((uint32_t)((m0 + mi*16 + frow) * 128 + fcol * 2));
                ldm_x4(ahi[mi], abase + o);
            }
            #pragma unroll
            for (int pr = 0; pr < 4; pr++) {
                uint32_t o = sw128((uint32_t)((n0 + pr*16 + frow) * 128 + fcol * 2));
                ldm_x4(bh[pr], bbase + o);
            }
            #pragma unroll
            for (int mi = 0; mi < 4; mi++)
                #pragma unroll
                for (int ni = 0; ni < 8; ni++) {
                    int pr = ni >> 1, sel = ni & 1;
                    mma_f16(acc[mi][ni], ahi[mi], bh[pr][sel], bh[pr][sel+2]);
                }
        }
        st++; if (st >= 3) st = 0;
    }

    int gr = lane >> 2, tq = lane & 3;
    #pragma unroll
    for (int mi = 0; mi < 4; mi++) {
        #pragma unroll
        for (int ni = 0; ni < 8; ni++) {
            int col = bn + n0 + ni*8 + tq*2;
            float b0 = bias[col], b1 = bias[col + 1];
            #pragma unroll
            for (int half = 0; half < 2; half++) {
                int row = bm + m0 + mi*16 + gr + half*8;
                float v0 = acc[mi][ni][half*2 + 0] + b0;
                float v1 = acc[mi][ni][half*2 + 1] + b1;
                size_t off = (size_t)row * N + col;
                if (EPI == 2) {
                    v0 = 0.5f * v0 * (1.0f + erff(v0 * 0.7071067811865475f));
                    v1 = 0.5f * v1 * (1.0f + erff(v1 * 0.7071067811865475f));
                    __half2 p = __floats2half2_rn(v0 * 0.03125f, v1 * 0.03125f);
                    *(uint32_t*)(C16 + off) = *reinterpret_cast<uint32_t*>(&p);
                } else {
                    __half2 p = __floats2half2_rn(v0, v1);
                    *(uint32_t*)(C16 + off) = *reinterpret_cast<uint32_t*>(&p);
                }
            }
        }
    }
}

// ============================================================
// 256x128 GEMM (8 warps of 64x64), 3-stage, 1 CTA/SM — for the
// N=512 GEMMs (out-proj, FF2): grid=128 CTAs = one balanced wave.
// Epilogue: bias + residual -> fp32.
// ============================================================
#define ATB 32768            // A tile 256x64 fp16
#define BTB 16384            // B tile 128x64 fp16
#define SSZL (ATB + BTB)     // 49152
#define SM_SZL (3*SSZL)      // 147456

__global__ __launch_bounds__(256, 1)
void gemm_mma_l(const __half* __restrict__ Ahi, const __half* __restrict__ Bhi,
                const float* __restrict__ bias, const float* __restrict__ res,
                float* __restrict__ C,
                int M, int N, int K)
{
    extern __shared__ __align__(128) char smem[];
    uint32_t sb = smem_u32(smem);
    int tid = threadIdx.x;
    int lane = tid & 31, wid = tid >> 5;
    int bm = blockIdx.y * 256, bn = blockIdx.x * 128;
    int m0 = (wid & 3) * 64;          // 4 warps in m
    int n0 = (wid >> 2) * 64;         // 2 warps in n

    float acc[4][8][4];
    #pragma unroll
    for (int i = 0; i < 4; i++)
        #pragma unroll
        for (int j = 0; j < 8; j++)
            #pragma unroll
            for (int k = 0; k < 4; k++) acc[i][j][k] = 0.0f;

    auto load_stage = [&](int st, int k0) {
        uint32_t base = sb + st * SSZL;
        #pragma unroll
        for (int t = 0; t < 8; t++) {            // A: 2048 16B lines
            int line = tid + t * 256;
            int r  = line >> 3;                  // 0..255
            int cc = line & 7;
            uint32_t d = sw128((uint32_t)(r * 128 + cc * 16));
            cp16(base + d, Ahi + (size_t)(bm + r) * K + k0 + cc * 8);
        }
        #pragma unroll
        for (int t = 0; t < 4; t++) {            // B: 1024 16B lines
            int line = tid + t * 256;
            int r  = line >> 3;                  // 0..127
            int cc = line & 7;
            uint32_t d = sw128((uint32_t)(r * 128 + cc * 16));
            cp16(base + ATB + d, Bhi + (size_t)(bn + r) * K + k0 + cc * 8);
        }
    };

    int nk = K >> 6;
    load_stage(0, 0);  CP_COMMIT();
    load_stage(1, 64); CP_COMMIT();

    int st = 0;
    for (int ch = 0; ch < nk; ch++) {
        CP_WAIT1();
        __syncthreads();
        if (ch + 2 < nk) {
            int st2 = st + 2; if (st2 >= 3) st2 -= 3;
            load_stage(st2, (ch + 2) * 64);
        }
        CP_COMMIT();

        uint32_t abase = sb + st * SSZL;
        uint32_t bbase = abase + ATB;

        #pragma unroll
        for (int ks = 0; ks < 4; ks++) {
            int k0 = ks * 16;
            int frow = (lane & 7) + ((lane >> 3) & 1) * 8;
            int fcol = k0 + (lane >> 4) * 8;
            uint32_t ahi[4][4], bh[4][4];
            #pragma unroll
            for (int mi = 0; mi < 4; mi++) {
                uint32_t o = sw128((uint32_t)((m0 + mi*16 + frow) * 128 + fcol * 2));
                ldm_x4(ahi[mi], abase + o);
            }
            #pragma unroll
            for (int pr = 0; pr < 4; pr++) {
                uint32_t o = sw128((uint32_t)((n0 + pr*16 + frow) * 128 + fcol * 2));
                ldm_x4(bh[pr], bbase + o);
            }
            #pragma unroll
            for (int mi = 0; mi < 4; mi++)
                #pragma unroll
                for (int ni = 0; ni < 8; ni++) {
                    int pr = ni >> 1, sel = ni & 1;
                    mma_f16(acc[mi][ni], ahi[mi], bh[pr][sel], bh[pr][sel+2]);
                }
        }
        st++; if (st >= 3) st = 0;
    }

    int gr = lane >> 2, tq = lane & 3;
    #pragma unroll
    for (int mi = 0; mi < 4; mi++) {
        #pragma unroll
        for (int ni = 0; ni < 8; ni++) {
            int col = bn + n0 + ni*8 + tq*2;
            float b0 = bias[col], b1 = bias[col + 1];
            #pragma unroll
            for (int half = 0; half < 2; half++) {
                int row = bm + m0 + mi*16 + gr + half*8;
                size_t off = (size_t)row * N + col;
                float2 r2 = *(const float2*)(res + off);
                *(float2*)(C + off) = make_float2(acc[mi][ni][half*2+0] + b0 + r2.x,
                                                  acc[mi][ni][half*2+1] + b1 + r2.y);
            }
        }
    }
}

// ============================================================
// Local attention, smem-tiled: block = (b,h, 64-token span).
// K/V (span+halo = 72 rows) staged in smem once.
// ============================================================
__global__ __launch_bounds__(256)
void attn_tile(const __half* __restrict__ qkv16, __half* __restrict__ ctx16) {
    __shared__ __half2 Ks[72][32];
    __shared__ __half2 Vs[72][32];
    int blk = blockIdx.x;
    int span = blk & 31;              // Sc/64 = 32 spans
    int bh = blk >> 5;
    int h = bh & (Hc - 1), b = bh >> 3;
    int s0 = span * 64;
    int rowbase = b * Sc;
    int tid = threadIdx.x;

    for (int i = tid; i < 72 * 32; i += 256) {
        int rr = i >> 5, d = i & 31;
        int j = s0 - 4 + rr;
        __half2 kv = __float2half2_rn(0.0f), vv = kv;
        if (j >= 0 && j < Sc) {
            const __half2* kp = (const __half2*)(qkv16 + (size_t)(rowbase + j) * D3 + Dc + h * Dhc);
            const __half2* vp = (const __half2*)(qkv16 + (size_t)(rowbase + j) * D3 + 2*Dc + h * Dhc);
            kv = kp[d]; vv = vp[d];
        }
        Ks[rr][d] = kv; Vs[rr][d] = vv;
    }
    __syncthreads();

    int wid = tid >> 5, lane = tid & 31;
    #pragma unroll
    for (int i = 0; i < 8; i++) {
        int sl = wid * 8 + i;         // 0..63 local
        int s  = s0 + sl;
        int bs = rowbase + s;
        float2 q = __half22float2(((const __half2*)(qkv16 + (size_t)bs * D3 + h * Dhc))[lane]);

        float e[9];
        float mx = -INFINITY;
        #pragma unroll
        for (int jj = 0; jj < 9; jj++) {
            int j = s - 4 + jj;
            float sc = -INFINITY;
            if (j >= 0 && j < Sc) {
                float2 k2 = __half22float2(Ks[sl + jj][lane]);
                float p = q.x * k2.x + q.y * k2.y;
                #pragma unroll
                for (int o = 16; o > 0; o >>= 1)
                    p += __shfl_xor_sync(0xffffffffu, p, o);
                sc = p * 0.125f;
            }
            e[jj] = sc;
            mx = fmaxf(mx, sc);
        }
        float sum = 0.0f;
        #pragma unroll
        for (int jj = 0; jj < 9; jj++) {
            e[jj] = expf(e[jj] - mx);
            sum += e[jj];
        }
        float inv = 1.0f / sum;
        float c0 = 0.0f, c1 = 0.0f;
        #pragma unroll
        for (int jj = 0; jj < 9; jj++) {
            int j = s - 4 + jj;
            if (j >= 0 && j < Sc) {
                float2 v2 = __half22float2(Vs[sl + jj][lane]);
                float w = e[jj] * inv;
                c0 = fmaf(w, v2.x, c0);
                c1 = fmaf(w, v2.y, c1);
            }
        }
        __half2 p = __floats2half2_rn(c0 * 0.03125f, c1 * 0.03125f);
        *(uint32_t*)(ctx16 + (size_t)bs * Dc + h * Dhc + 2*lane) = *reinterpret_cast<uint32_t*>(&p);
    }
}

// ============================================================
extern "C" void kernel_launch(void* const* d_in, const int* in_sizes, int n_in,
                              void* d_out, int out_size) {
    const float* x     = (const float*)d_in[0];
    const float* in_w  = (const float*)d_in[1];
    const float* in_b  = (const float*)d_in[2];
    const float* out_w = (const float*)d_in[3];
    const float* out_b = (const float*)d_in[4];
    const float* ff_w1 = (const float*)d_in[5];
    const float* ff_b1 = (const float*)d_in[6];
    const float* ff_w2 = (const float*)d_in[7];
    const float* ff_b2 = (const float*)d_in[8];
    const float* ln1_g = (const float*)d_in[9];
    const float* ln1_b = (const float*)d_in[10];
    const float* ln2_g = (const float*)d_in[11];
    const float* ln2_b = (const float*)d_in[12];
    float* out = (float*)d_out;

    __half *fw, *a16, *ff16, *qkv16;
    float *x1;
    cudaGetSymbolAddress((void**)&fw,    g_fw);
    cudaGetSymbolAddress((void**)&a16,   g_a16);
    cudaGetSymbolAddress((void**)&ff16,  g_ff16);
    cudaGetSymbolAddress((void**)&qkv16, g_qkv16);
    cudaGetSymbolAddress((void**)&x1,    g_x1);

    cudaFuncSetAttribute(gemm_mma<0>, cudaFuncAttributeMaxDynamicSharedMemorySize, SM_SZ);
    cudaFuncSetAttribute(gemm_mma<2>, cudaFuncAttributeMaxDynamicSharedMemorySize, SM_SZ);
    cudaFuncSetAttribute(gemm_mma_l,  cudaFuncAttributeMaxDynamicSharedMemorySize, SM_SZL);

    // weight conversion (single launch)
    wconv_all<<<3072, 256>>>(in_w, out_w, ff_w1, ff_w2, fw);

    // 1) a16 = fp16(LN1(x)/32)
    ln_kernel<<<Mrows, 128>>>(x, ln1_g, ln1_b, a16);
    // 2) qkv16 = fp16(a16 @ (32*in_w)^T + in_b)
    gemm_mma<0><<<dim3(D3/128, Mrows/128), 128, SM_SZ>>>(
        a16, fw + FW_IN, in_b, qkv16, Mrows, D3, Dc);
    // 3) a16 = fp16(attention(qkv16)/32)   (smem-tiled)
    attn_tile<<<32 * Bc * Hc, 256>>>(qkv16, a16);
    // 4) x1 = x + a16 @ (32*out_w)^T + out_b   (256-row tiles, 128 CTAs)
    gemm_mma_l<<<dim3(Dc/128, Mrows/256), 256, SM_SZL>>>(
        a16, fw + FW_OUT, out_b, x, x1, Mrows, Dc, Dc);
    // 5) a16 = fp16(LN2(x1)/32)
    ln_kernel<<<Mrows, 128>>>(x1, ln2_g, ln2_b, a16);
    // 6) ff16 = fp16(gelu(a16 @ (32*ff_w1)^T + ff_b1)/32)
    gemm_mma<2><<<dim3(DffC/128, Mrows/128), 128, SM_SZ>>>(
        a16, fw + FW_FF1, ff_b1, ff16, Mrows, DffC, Dc);
    // 7) out = x1 + ff16 @ (32*ff_w2)^T + ff_b2   (256-row tiles, 128 CTAs)
    gemm_mma_l<<<dim3(Dc/128, Mrows/256), 256, SM_SZL>>>(
        ff16, fw + FW_FF2, ff_b2, x1, out, Mrows, Dc, DffC);
}

// round 10
// speedup vs baseline: 1.7210x; 1.0544x over previous
#include <cuda_runtime.h>
#include <cuda_fp16.h>
#include <math.h>
#include <stdint.h>

// Problem constants
#define Bc   4
#define Sc   2048
#define Dc   512
#define Hc   8
#define Dhc  64
#define Mrows (Bc*Sc)      // 8192
#define D3   (3*Dc)        // 1536
#define DffC (4*Dc)        // 2048

// ---- scratch (device globals; no cudaMalloc allowed) ----
__device__ __half g_fw[3145728];
#define FW_IN   0
#define FW_OUT  786432
#define FW_FF1  1048576
#define FW_FF2  2097152
__device__ __half g_a16  [(size_t)Mrows * Dc];
__device__ __half g_ff16 [(size_t)Mrows * DffC];
__device__ __half g_qkv16[(size_t)Mrows * D3];
__device__ float  g_x1   [(size_t)Mrows * Dc];

// ============================================================
// helpers
// ============================================================
__device__ __forceinline__ uint32_t smem_u32(const void* p) {
    uint32_t a;
    asm("{ .reg .u64 t; cvta.to.shared.u64 t, %1; cvt.u32.u64 %0, t; }" : "=r"(a) : "l"(p));
    return a;
}
__device__ __forceinline__ uint32_t sw128(uint32_t o) { return o ^ ((o >> 3) & 0x70); }

__device__ __forceinline__ void cp16(uint32_t dst, const void* src) {
    asm volatile("cp.async.cg.shared.global [%0], [%1], 16;" :: "r"(dst), "l"(src) : "memory");
}
#define CP_COMMIT() asm volatile("cp.async.commit_group;" ::: "memory")
#define CP_WAIT1()  asm volatile("cp.async.wait_group 1;" ::: "memory")
#define CP_WAIT2()  asm volatile("cp.async.wait_group 2;" ::: "memory")

__device__ __forceinline__ void ldm_x4(uint32_t* r, uint32_t addr) {
    asm volatile("ldmatrix.sync.aligned.m8n8.x4.shared.b16 {%0,%1,%2,%3}, [%4];"
                 : "=r"(r[0]), "=r"(r[1]), "=r"(r[2]), "=r"(r[3]) : "r"(addr));
}
__device__ __forceinline__ void mma_f16(float* c, const uint32_t* a, uint32_t b0, uint32_t b1) {
    asm volatile("mma.sync.aligned.m16n8k16.row.col.f32.f16.f16.f32 "
                 "{%0,%1,%2,%3}, {%4,%5,%6,%7}, {%8,%9}, {%0,%1,%2,%3};"
                 : "+f"(c[0]), "+f"(c[1]), "+f"(c[2]), "+f"(c[3])
                 : "r"(a[0]), "r"(a[1]), "r"(a[2]), "r"(a[3]), "r"(b0), "r"(b1));
}

// ============================================================
// weight conversion: all four weights -> fp16(32*w), one launch, 2x ILP
// ============================================================
__device__ __forceinline__ void wconv_one(int i,
    const float* __restrict__ in_w, const float* __restrict__ out_w,
    const float* __restrict__ w1, const float* __restrict__ w2,
    __half* __restrict__ hi) {
    float4 v;
    if      (i < 196608) v = ((const float4*)in_w)[i];
    else if (i < 262144) v = ((const float4*)out_w)[i - 196608];
    else if (i < 524288) v = ((const float4*)w1)[i - 262144];
    else                 v = ((const float4*)w2)[i - 524288];
    __half2 p0 = __floats2half2_rn(v.x * 32.0f, v.y * 32.0f);
    __half2 p1 = __floats2half2_rn(v.z * 32.0f, v.w * 32.0f);
    ((uint2*)hi)[i] = make_uint2(*reinterpret_cast<uint32_t*>(&p0),
                                 *reinterpret_cast<uint32_t*>(&p1));
}
__global__ void wconv_all(const float* __restrict__ in_w, const float* __restrict__ out_w,
                          const float* __restrict__ w1, const float* __restrict__ w2,
                          __half* __restrict__ hi) {
    int i = blockIdx.x * 256 + threadIdx.x;          // 0..393215
    wconv_one(i,          in_w, out_w, w1, w2, hi);
    wconv_one(i + 393216, in_w, out_w, w1, w2, hi);
}

// ============================================================
// LayerNorm -> fp16(out/32)
// ============================================================
__global__ void ln_kernel(const float* __restrict__ x,
                          const float* __restrict__ g,
                          const float* __restrict__ b,
                          __half* __restrict__ h16) {
    int row = blockIdx.x;
    int t = threadIdx.x;                 // 0..127
    const float4* xr = (const float4*)(x + (size_t)row * Dc);
    float4 v = xr[t];
    float s  = v.x + v.y + v.z + v.w;
    float s2 = v.x*v.x + v.y*v.y + v.z*v.z + v.w*v.w;
    #pragma unroll
    for (int o = 16; o > 0; o >>= 1) {
        s  += __shfl_xor_sync(0xffffffffu, s,  o);
        s2 += __shfl_xor_sync(0xffffffffu, s2, o);
    }
    __shared__ float sh[8];
    int w = t >> 5;
    if ((t & 31) == 0) { sh[w*2] = s; sh[w*2+1] = s2; }
    __syncthreads();
    s  = sh[0] + sh[2] + sh[4] + sh[6];
    s2 = sh[1] + sh[3] + sh[5] + sh[7];
    float mu  = s * (1.0f / Dc);
    float var = s2 * (1.0f / Dc) - mu * mu;
    float rstd = rsqrtf(var + 1e-5f);
    float4 gv = ((const float4*)g)[t];
    float4 bv = ((const float4*)b)[t];
    float o0 = (v.x - mu) * rstd * gv.x + bv.x;
    float o1 = (v.y - mu) * rstd * gv.y + bv.y;
    float o2 = (v.z - mu) * rstd * gv.z + bv.z;
    float o3 = (v.w - mu) * rstd * gv.w + bv.w;
    __half2 p0 = __floats2half2_rn(o0 * 0.03125f, o1 * 0.03125f);
    __half2 p1 = __floats2half2_rn(o2 * 0.03125f, o3 * 0.03125f);
    size_t base = (size_t)row * Dc + t * 4;
    *(uint2*)(h16 + base) = make_uint2(*reinterpret_cast<uint32_t*>(&p0),
                                       *reinterpret_cast<uint32_t*>(&p1));
}

// ============================================================
// 128x128 GEMM (4 warps of 64x64), 3-stage, 2 CTAs/SM.
// EPI: 0=bias->fp16, 2=bias+GELU->fp16(/32)
// ============================================================
#define TB  16384
#define SSZ (2*TB)
#define SM_SZ (3*SSZ)        // 98304

template<int EPI>
__global__ __launch_bounds__(128, 2)
void gemm_mma(const __half* __restrict__ Ahi, const __half* __restrict__ Bhi,
              const float* __restrict__ bias,
              __half* __restrict__ C16,
              int M, int N, int K)
{
    extern __shared__ __align__(128) char smem[];
    uint32_t sb = smem_u32(smem);
    int tid = threadIdx.x;
    int lane = tid & 31, wid = tid >> 5;
    int bm = blockIdx.y * 128, bn = blockIdx.x * 128;
    int m0 = (wid & 1) * 64;
    int n0 = (wid >> 1) * 64;

    float acc[4][8][4];
    #pragma unroll
    for (int i = 0; i < 4; i++)
        #pragma unroll
        for (int j = 0; j < 8; j++)
            #pragma unroll
            for (int k = 0; k < 4; k++) acc[i][j][k] = 0.0f;

    auto load_stage = [&](int st, int k0) {
        uint32_t base = sb + st * SSZ;
        #pragma unroll
        for (int t = 0; t < 8; t++) {
            int line = tid + t * 128;
            int r  = line >> 3;
            int cc = line & 7;
            uint32_t d = sw128((uint32_t)(r * 128 + cc * 16));
            cp16(base + d,      Ahi + (size_t)(bm + r) * K + k0 + cc * 8);
            cp16(base + TB + d, Bhi + (size_t)(bn + r) * K + k0 + cc * 8);
        }
    };

    int nk = K >> 6;
    load_stage(0, 0);  CP_COMMIT();
    load_stage(1, 64); CP_COMMIT();

    int st = 0;
    for (int ch = 0; ch < nk; ch++) {
        CP_WAIT1();
        __syncthreads();
        if (ch + 2 < nk) {
            int st2 = st + 2; if (st2 >= 3) st2 -= 3;
            load_stage(st2, (ch + 2) * 64);
        }
        CP_COMMIT();

        uint32_t abase = sb + st * SSZ;
        uint32_t bbase = abase + TB;

        #pragma unroll
        for (int ks = 0; ks < 4; ks++) {
            int k0 = ks * 16;
            int frow = (lane & 7) + ((lane >> 3) & 1) * 8;
            int fcol = k0 + (lane >> 4) * 8;
            uint32_t ahi[4][4], bh[4][4];
            #pragma unroll
            for (int mi = 0; mi < 4; mi++) {
                uint32_t o = sw128((uint32_t)((m0 + mi*16 + frow) * 128 + fcol * 2));
                ldm_x4(ahi[mi], abase + o);
            }
            #pragma unroll
            for (int pr = 0; pr < 4; pr++) {
                uint32_t o = sw128((uint32_t)((n0 + pr*16 + frow) * 128 + fcol * 2));
                ldm_x4(bh[pr], bbase + o);
            }
            #pragma unroll
            for (int mi = 0; mi < 4; mi++)
                #pragma unroll
                for (int ni = 0; ni < 8; ni++) {
                    int pr = ni >> 1, sel = ni & 1;
                    mma_f16(acc[mi][ni], ahi[mi], bh[pr][sel], bh[pr][sel+2]);
                }
        }
        st++; if (st >= 3) st = 0;
    }

    int gr = lane >> 2, tq = lane & 3;
    #pragma unroll
    for (int mi = 0; mi < 4; mi++) {
        #pragma unroll
        for (int ni = 0; ni < 8; ni++) {
            int col = bn + n0 + ni*8 + tq*2;
            float b0 = bias[col], b1 = bias[col + 1];
            #pragma unroll
            for (int half = 0; half < 2; half++) {
                int row = bm + m0 + mi*16 + gr + half*8;
                float v0 = acc[mi][ni][half*2 + 0] + b0;
                float v1 = acc[mi][ni][half*2 + 1] + b1;
                size_t off = (size_t)row * N + col;
                if (EPI == 2) {
                    v0 = 0.5f * v0 * (1.0f + erff(v0 * 0.7071067811865475f));
                    v1 = 0.5f * v1 * (1.0f + erff(v1 * 0.7071067811865475f));
                    __half2 p = __floats2half2_rn(v0 * 0.03125f, v1 * 0.03125f);
                    *(uint32_t*)(C16 + off) = *reinterpret_cast<uint32_t*>(&p);
                } else {
                    __half2 p = __floats2half2_rn(v0, v1);
                    *(uint32_t*)(C16 + off) = *reinterpret_cast<uint32_t*>(&p);
                }
            }
        }
    }
}

// ============================================================
// 256x128 GEMM (8 warps of 64x64), 4-stage, 1 CTA/SM — N=512 GEMMs
// (out-proj, FF2): grid=128 CTAs = one balanced wave.
// Epilogue: bias + residual -> fp32.
// ============================================================
#define ATB 32768            // A tile 256x64 fp16
#define BTB 16384            // B tile 128x64 fp16
#define SSZL (ATB + BTB)     // 49152
#define SM_SZL (4*SSZL)      // 196608

__global__ __launch_bounds__(256, 1)
void gemm_mma_l(const __half* __restrict__ Ahi, const __half* __restrict__ Bhi,
                const float* __restrict__ bias, const float* __restrict__ res,
                float* __restrict__ C,
                int M, int N, int K)
{
    extern __shared__ __align__(128) char smem[];
    uint32_t sb = smem_u32(smem);
    int tid = threadIdx.x;
    int lane = tid & 31, wid = tid >> 5;
    int bm = blockIdx.y * 256, bn = blockIdx.x * 128;
    int m0 = (wid & 3) * 64;
    int n0 = (wid >> 2) * 64;

    float acc[4][8][4];
    #pragma unroll
    for (int i = 0; i < 4; i++)
        #pragma unroll
        for (int j = 0; j < 8; j++)
            #pragma unroll
            for (int k = 0; k < 4; k++) acc[i][j][k] = 0.0f;

    auto load_stage = [&](int st, int k0) {
        uint32_t base = sb + st * SSZL;
        #pragma unroll
        for (int t = 0; t < 8; t++) {
            int line = tid + t * 256;
            int r  = line >> 3;
            int cc = line & 7;
            uint32_t d = sw128((uint32_t)(r * 128 + cc * 16));
            cp16(base + d, Ahi + (size_t)(bm + r) * K + k0 + cc * 8);
        }
        #pragma unroll
        for (int t = 0; t < 4; t++) {
            int line = tid + t * 256;
            int r  = line >> 3;
            int cc = line & 7;
            uint32_t d = sw128((uint32_t)(r * 128 + cc * 16));
            cp16(base + ATB + d, Bhi + (size_t)(bn + r) * K + k0 + cc * 8);
        }
    };

    int nk = K >> 6;
    load_stage(0, 0);   CP_COMMIT();
    load_stage(1, 64);  CP_COMMIT();
    load_stage(2, 128); CP_COMMIT();

    int st = 0;
    for (int ch = 0; ch < nk; ch++) {
        CP_WAIT2();
        __syncthreads();
        if (ch + 3 < nk) {
            int st3 = st + 3; if (st3 >= 4) st3 -= 4;
            load_stage(st3, (ch + 3) * 64);
        }
        CP_COMMIT();

        uint32_t abase = sb + st * SSZL;
        uint32_t bbase = abase + ATB;

        #pragma unroll
        for (int ks = 0; ks < 4; ks++) {
            int k0 = ks * 16;
            int frow = (lane & 7) + ((lane >> 3) & 1) * 8;
            int fcol = k0 + (lane >> 4) * 8;
            uint32_t ahi[4][4], bh[4][4];
            #pragma unroll
            for (int mi = 0; mi < 4; mi++) {
                uint32_t o = sw128((uint32_t)((m0 + mi*16 + frow) * 128 + fcol * 2));
                ldm_x4(ahi[mi], abase + o);
            }
            #pragma unroll
            for (int pr = 0; pr < 4; pr++) {
                uint32_t o = sw128((uint32_t)((n0 + pr*16 + frow) * 128 + fcol * 2));
                ldm_x4(bh[pr], bbase + o);
            }
            #pragma unroll
            for (int mi = 0; mi < 4; mi++)
                #pragma unroll
                for (int ni = 0; ni < 8; ni++) {
                    int pr = ni >> 1, sel = ni & 1;
                    mma_f16(acc[mi][ni], ahi[mi], bh[pr][sel], bh[pr][sel+2]);
                }
        }
        st++; if (st >= 4) st = 0;
    }

    int gr = lane >> 2, tq = lane & 3;
    #pragma unroll
    for (int mi = 0; mi < 4; mi++) {
        #pragma unroll
        for (int ni = 0; ni < 8; ni++) {
            int col = bn + n0 + ni*8 + tq*2;
            float b0 = bias[col], b1 = bias[col + 1];
            #pragma unroll
            for (int half = 0; half < 2; half++) {
                int row = bm + m0 + mi*16 + gr + half*8;
                size_t off = (size_t)row * N + col;
                float2 r2 = *(const float2*)(res + off);
                *(float2*)(C + off) = make_float2(acc[mi][ni][half*2+0] + b0 + r2.x,
                                                  acc[mi][ni][half*2+1] + b1 + r2.y);
            }
        }
    }
}

// ============================================================
// Local attention: thread-per-query, smem K/V with conflict-free
// padded layout (row stride 33 half2). Block = 128 queries of one
// (b,h,span). No shuffles.
// ============================================================
__global__ __launch_bounds__(128)
void attn_tq(const __half* __restrict__ qkv16, __half* __restrict__ ctx16) {
    __shared__ uint32_t Ks[136 * 33];
    __shared__ uint32_t Vs[136 * 33];
    int blk = blockIdx.x;
    int span = blk & 15;               // Sc/128 = 16 spans
    int bh = blk >> 4;
    int h = bh & (Hc - 1), b = bh >> 3;
    int s0 = span * 128;
    int rowbase = b * Sc;
    int tid = threadIdx.x;

    // stage K/V rows s0-4 .. s0+131 (136 rows x 32 half2), padded stride 33
    #pragma unroll
    for (int t = 0; t < 9; t++) {
        int i = tid + t * 128;                 // 0..1151; need 1088
        if (i < 136 * 8) {
            int r = i >> 3, c = i & 7;
            int j = s0 - 4 + r;
            uint4 kv = make_uint4(0,0,0,0), vv = make_uint4(0,0,0,0);
            if (j >= 0 && j < Sc) {
                const uint4* kp = (const uint4*)(qkv16 + (size_t)(rowbase + j) * D3 + Dc + h * Dhc);
                const uint4* vp = (const uint4*)(qkv16 + (size_t)(rowbase + j) * D3 + 2*Dc + h * Dhc);
                kv = kp[c]; vv = vp[c];
            }
            int base = r * 33 + c * 4;
            Ks[base+0] = kv.x; Ks[base+1] = kv.y; Ks[base+2] = kv.z; Ks[base+3] = kv.w;
            Vs[base+0] = vv.x; Vs[base+1] = vv.y; Vs[base+2] = vv.z; Vs[base+3] = vv.w;
        }
    }
    __syncthreads();

    int s = s0 + tid;
    // q -> fp32 regs
    float qf[64];
    {
        const uint4* qp = (const uint4*)(qkv16 + (size_t)(rowbase + s) * D3 + h * Dhc);
        #pragma unroll
        for (int c = 0; c < 8; c++) {
            uint4 u = qp[c];
            uint32_t w4[4] = {u.x, u.y, u.z, u.w};
            #pragma unroll
            for (int k = 0; k < 4; k++) {
                float2 f = __half22float2(*reinterpret_cast<__half2*>(&w4[k]));
                qf[c*8 + k*2]     = f.x;
                qf[c*8 + k*2 + 1] = f.y;
            }
        }
    }

    // scores: straight fp32 FMA chains, no shuffles
    float e[9];
    float mx = -INFINITY;
    #pragma unroll
    for (int jj = 0; jj < 9; jj++) {
        int j = s - 4 + jj;
        int lr = tid + jj;
        float p = 0.0f;
        #pragma unroll
        for (int d = 0; d < 32; d++) {
            uint32_t kw = Ks[lr * 33 + d];
            float2 k2 = __half22float2(*reinterpret_cast<__half2*>(&kw));
            p = fmaf(qf[2*d],     k2.x, p);
            p = fmaf(qf[2*d + 1], k2.y, p);
        }
        e[jj] = (j >= 0 && j < Sc) ? p * 0.125f : -INFINITY;
        mx = fmaxf(mx, e[jj]);
    }
    float sum = 0.0f;
    #pragma unroll
    for (int jj = 0; jj < 9; jj++) { e[jj] = __expf(e[jj] - mx); sum += e[jj]; }
    float inv = 1.0f / sum;
    #pragma unroll
    for (int jj = 0; jj < 9; jj++) e[jj] *= inv;

    // PV in two 32-dim passes (caps registers); out-of-range rows are zero
    uint32_t outw[32];
    #pragma unroll
    for (int hf = 0; hf < 2; hf++) {
        float cx[32];
        #pragma unroll
        for (int d = 0; d < 32; d++) cx[d] = 0.0f;
        #pragma unroll
        for (int jj = 0; jj < 9; jj++) {
            int lr = tid + jj;
            float w = e[jj];
            #pragma unroll
            for (int d = 0; d < 16; d++) {
                uint32_t vw = Vs[lr * 33 + hf*16 + d];
                float2 v2 = __half22float2(*reinterpret_cast<__half2*>(&vw));
                cx[2*d]     = fmaf(w, v2.x, cx[2*d]);
                cx[2*d + 1] = fmaf(w, v2.y, cx[2*d + 1]);
            }
        }
        #pragma unroll
        for (int d = 0; d < 16; d++) {
            __half2 p2 = __floats2half2_rn(cx[2*d] * 0.03125f, cx[2*d + 1] * 0.03125f);
            outw[hf*16 + d] = *reinterpret_cast<uint32_t*>(&p2);
        }
    }
    uint4* op = (uint4*)(ctx16 + (size_t)(rowbase + s) * Dc + h * Dhc);
    #pragma unroll
    for (int c = 0; c < 8; c++)
        op[c] = make_uint4(outw[c*4], outw[c*4+1], outw[c*4+2], outw[c*4+3]);
}

// ============================================================
extern "C" void kernel_launch(void* const* d_in, const int* in_sizes, int n_in,
                              void* d_out, int out_size) {
    const float* x     = (const float*)d_in[0];
    const float* in_w  = (const float*)d_in[1];
    const float* in_b  = (const float*)d_in[2];
    const float* out_w = (const float*)d_in[3];
    const float* out_b = (const float*)d_in[4];
    const float* ff_w1 = (const float*)d_in[5];
    const float* ff_b1 = (const float*)d_in[6];
    const float* ff_w2 = (const float*)d_in[7];
    const float* ff_b2 = (const float*)d_in[8];
    const float* ln1_g = (const float*)d_in[9];
    const float* ln1_b = (const float*)d_in[10];
    const float* ln2_g = (const float*)d_in[11];
    const float* ln2_b = (const float*)d_in[12];
    float* out = (float*)d_out;

    __half *fw, *a16, *ff16, *qkv16;
    float *x1;
    cudaGetSymbolAddress((void**)&fw,    g_fw);
    cudaGetSymbolAddress((void**)&a16,   g_a16);
    cudaGetSymbolAddress((void**)&ff16,  g_ff16);
    cudaGetSymbolAddress((void**)&qkv16, g_qkv16);
    cudaGetSymbolAddress((void**)&x1,    g_x1);

    cudaFuncSetAttribute(gemm_mma<0>, cudaFuncAttributeMaxDynamicSharedMemorySize, SM_SZ);
    cudaFuncSetAttribute(gemm_mma<2>, cudaFuncAttributeMaxDynamicSharedMemorySize, SM_SZ);
    cudaFuncSetAttribute(gemm_mma_l,  cudaFuncAttributeMaxDynamicSharedMemorySize, SM_SZL);

    // weight conversion (single launch, 2x ILP)
    wconv_all<<<1536, 256>>>(in_w, out_w, ff_w1, ff_w2, fw);

    // 1) a16 = fp16(LN1(x)/32)
    ln_kernel<<<Mrows, 128>>>(x, ln1_g, ln1_b, a16);
    // 2) qkv16 = fp16(a16 @ (32*in_w)^T + in_b)
    gemm_mma<0><<<dim3(D3/128, Mrows/128), 128, SM_SZ>>>(
        a16, fw + FW_IN, in_b, qkv16, Mrows, D3, Dc);
    // 3) a16 = fp16(attention(qkv16)/32)   (thread-per-query)
    attn_tq<<<16 * Bc * Hc, 128>>>(qkv16, a16);
    // 4) x1 = x + a16 @ (32*out_w)^T + out_b   (256-row tiles, 4-stage)
    gemm_mma_l<<<dim3(Dc/128, Mrows/256), 256, SM_SZL>>>(
        a16, fw + FW_OUT, out_b, x, x1, Mrows, Dc, Dc);
    // 5) a16 = fp16(LN2(x1)/32)
    ln_kernel<<<Mrows, 128>>>(x1, ln2_g, ln2_b, a16);
    // 6) ff16 = fp16(gelu(a16 @ (32*ff_w1)^T + ff_b1)/32)
    gemm_mma<2><<<dim3(DffC/128, Mrows/128), 128, SM_SZ>>>(
        a16, fw + FW_FF1, ff_b1, ff16, Mrows, DffC, Dc);
    // 7) out = x1 + ff16 @ (32*ff_w2)^T + ff_b2   (256-row tiles, 4-stage)
    gemm_mma_l<<<dim3(Dc/128, Mrows/256), 256, SM_SZL>>>(
        ff16, fw + FW_FF2, ff_b2, x1, out, Mrows, Dc, DffC);
}

// round 11
// speedup vs baseline: 1.7234x; 1.0014x over previous
#include <cuda_runtime.h>
#include <cuda_fp16.h>
#include <math.h>
#include <stdint.h>

// Problem constants
#define Bc   4
#define Sc   2048
#define Dc   512
#define Hc   8
#define Dhc  64
#define Mrows (Bc*Sc)      // 8192
#define D3   (3*Dc)        // 1536
#define DffC (4*Dc)        // 2048

// ---- scratch (device globals; no cudaMalloc allowed) ----
__device__ __half g_fw[3145728];
#define FW_IN   0
#define FW_OUT  786432
#define FW_FF1  1048576
#define FW_FF2  2097152
__device__ __half g_a16  [(size_t)Mrows * Dc];
__device__ __half g_ff16 [(size_t)Mrows * DffC];
__device__ __half g_qkv16[(size_t)Mrows * D3];
__device__ float  g_x1   [(size_t)Mrows * Dc];

// ============================================================
// helpers
// ============================================================
__device__ __forceinline__ uint32_t smem_u32(const void* p) {
    uint32_t a;
    asm("{ .reg .u64 t; cvta.to.shared.u64 t, %1; cvt.u32.u64 %0, t; }" : "=r"(a) : "l"(p));
    return a;
}
__device__ __forceinline__ uint32_t sw128(uint32_t o) { return o ^ ((o >> 3) & 0x70); }

__device__ __forceinline__ void cp16(uint32_t dst, const void* src) {
    asm volatile("cp.async.cg.shared.global [%0], [%1], 16;" :: "r"(dst), "l"(src) : "memory");
}
#define CP_COMMIT() asm volatile("cp.async.commit_group;" ::: "memory")
#define CP_WAIT1()  asm volatile("cp.async.wait_group 1;" ::: "memory")
#define CP_WAIT2()  asm volatile("cp.async.wait_group 2;" ::: "memory")

__device__ __forceinline__ void ldm_x4(uint32_t* r, uint32_t addr) {
    asm volatile("ldmatrix.sync.aligned.m8n8.x4.shared.b16 {%0,%1,%2,%3}, [%4];"
                 : "=r"(r[0]), "=r"(r[1]), "=r"(r[2]), "=r"(r[3]) : "r"(addr));
}
__device__ __forceinline__ void mma_f16(float* c, const uint32_t* a, uint32_t b0, uint32_t b1) {
    asm volatile("mma.sync.aligned.m16n8k16.row.col.f32.f16.f16.f32 "
                 "{%0,%1,%2,%3}, {%4,%5,%6,%7}, {%8,%9}, {%0,%1,%2,%3};"
                 : "+f"(c[0]), "+f"(c[1]), "+f"(c[2]), "+f"(c[3])
                 : "r"(a[0]), "r"(a[1]), "r"(a[2]), "r"(a[3]), "r"(b0), "r"(b1));
}

// ============================================================
// weight conversion: all four weights -> fp16(32*w), one launch, 2x ILP
// ============================================================
__device__ __forceinline__ void wconv_one(int i,
    const float* __restrict__ in_w, const float* __restrict__ out_w,
    const float* __restrict__ w1, const float* __restrict__ w2,
    __half* __restrict__ hi) {
    float4 v;
    if      (i < 196608) v = ((const float4*)in_w)[i];
    else if (i < 262144) v = ((const float4*)out_w)[i - 196608];
    else if (i < 524288) v = ((const float4*)w1)[i - 262144];
    else                 v = ((const float4*)w2)[i - 524288];
    __half2 p0 = __floats2half2_rn(v.x * 32.0f, v.y * 32.0f);
    __half2 p1 = __floats2half2_rn(v.z * 32.0f, v.w * 32.0f);
    ((uint2*)hi)[i] = make_uint2(*reinterpret_cast<uint32_t*>(&p0),
                                 *reinterpret_cast<uint32_t*>(&p1));
}
__global__ void wconv_all(const float* __restrict__ in_w, const float* __restrict__ out_w,
                          const float* __restrict__ w1, const float* __restrict__ w2,
                          __half* __restrict__ hi) {
    int i = blockIdx.x * 256 + threadIdx.x;          // 0..393215
    wconv_one(i,          in_w, out_w, w1, w2, hi);
    wconv_one(i + 393216, in_w, out_w, w1, w2, hi);
}

// ============================================================
// LayerNorm -> fp16(out/32)
// ============================================================
__global__ void ln_kernel(const float* __restrict__ x,
                          const float* __restrict__ g,
                          const float* __restrict__ b,
                          __half* __restrict__ h16) {
    int row = blockIdx.x;
    int t = threadIdx.x;                 // 0..127
    const float4* xr = (const float4*)(x + (size_t)row * Dc);
    float4 v = xr[t];
    float s  = v.x + v.y + v.z + v.w;
    float s2 = v.x*v.x + v.y*v.y + v.z*v.z + v.w*v.w;
    #pragma unroll
    for (int o = 16; o > 0; o >>= 1) {
        s  += __shfl_xor_sync(0xffffffffu, s,  o);
        s2 += __shfl_xor_sync(0xffffffffu, s2, o);
    }
    __shared__ float sh[8];
    int w = t >> 5;
    if ((t & 31) == 0) { sh[w*2] = s; sh[w*2+1] = s2; }
    __syncthreads();
    s  = sh[0] + sh[2] + sh[4] + sh[6];
    s2 = sh[1] + sh[3] + sh[5] + sh[7];
    float mu  = s * (1.0f / Dc);
    float var = s2 * (1.0f / Dc) - mu * mu;
    float rstd = rsqrtf(var + 1e-5f);
    float4 gv = ((const float4*)g)[t];
    float4 bv = ((const float4*)b)[t];
    float o0 = (v.x - mu) * rstd * gv.x + bv.x;
    float o1 = (v.y - mu) * rstd * gv.y + bv.y;
    float o2 = (v.z - mu) * rstd * gv.z + bv.z;
    float o3 = (v.w - mu) * rstd * gv.w + bv.w;
    __half2 p0 = __floats2half2_rn(o0 * 0.03125f, o1 * 0.03125f);
    __half2 p1 = __floats2half2_rn(o2 * 0.03125f, o3 * 0.03125f);
    size_t base = (size_t)row * Dc + t * 4;
    *(uint2*)(h16 + base) = make_uint2(*reinterpret_cast<uint32_t*>(&p0),
                                       *reinterpret_cast<uint32_t*>(&p1));
}

// ============================================================
// 128x128 GEMM (4 warps of 64x64), 3-stage, 2 CTAs/SM.
// EPI: 0=bias->fp16, 2=bias+GELU->fp16(/32)
// ============================================================
#define TB  16384
#define SSZ (2*TB)
#define SM_SZ (3*SSZ)        // 98304

template<int EPI>
__global__ __launch_bounds__(128, 2)
void gemm_mma(const __half* __restrict__ Ahi, const __half* __restrict__ Bhi,
              const float* __restrict__ bias,
              __half* __restrict__ C16,
              int M, int N, int K)
{
    extern __shared__ __align__(128) char smem[];
    uint32_t sb = smem_u32(smem);
    int tid = threadIdx.x;
    int lane = tid & 31, wid = tid >> 5;
    int bm = blockIdx.y * 128, bn = blockIdx.x * 128;
    int m0 = (wid & 1) * 64;
    int n0 = (wid >> 1) * 64;

    float acc[4][8][4];
    #pragma unroll
    for (int i = 0; i < 4; i++)
        #pragma unroll
        for (int j = 0; j < 8; j++)
            #pragma unroll
            for (int k = 0; k < 4; k++) acc[i][j][k] = 0.0f;

    auto load_stage = [&](int st, int k0) {
        uint32_t base = sb + st * SSZ;
        #pragma unroll
        for (int t = 0; t < 8; t++) {
            int line = tid + t * 128;
            int r  = line >> 3;
            int cc = line & 7;
            uint32_t d = sw128((uint32_t)(r * 128 + cc * 16));
            cp16(base + d,      Ahi + (size_t)(bm + r) * K + k0 + cc * 8);
            cp16(base + TB + d, Bhi + (size_t)(bn + r) * K + k0 + cc * 8);
        }
    };

    int nk = K >> 6;
    load_stage(0, 0);  CP_COMMIT();
    load_stage(1, 64); CP_COMMIT();

    int st = 0;
    for (int ch = 0; ch < nk; ch++) {
        CP_WAIT1();
        __syncthreads();
        if (ch + 2 < nk) {
            int st2 = st + 2; if (st2 >= 3) st2 -= 3;
            load_stage(st2, (ch + 2) * 64);
        }
        CP_COMMIT();

        uint32_t abase = sb + st * SSZ;
        uint32_t bbase = abase + TB;

        #pragma unroll
        for (int ks = 0; ks < 4; ks++) {
            int k0 = ks * 16;
            int frow = (lane & 7) + ((lane >> 3) & 1) * 8;
            int fcol = k0 + (lane >> 4) * 8;
            uint32_t ahi[4][4], bh[4][4];
            #pragma unroll
            for (int mi = 0; mi < 4; mi++) {
                uint32_t o = sw128((uint32_t)((m0 + mi*16 + frow) * 128 + fcol * 2));
                ldm_x4(ahi[mi], abase + o);
            }
            #pragma unroll
            for (int pr = 0; pr < 4; pr++) {
                uint32_t o = sw128((uint32_t)((n0 + pr*16 + frow) * 128 + fcol * 2));
                ldm_x4(bh[pr], bbase + o);
            }
            #pragma unroll
            for (int mi = 0; mi < 4; mi++)
                #pragma unroll
                for (int ni = 0; ni < 8; ni++) {
                    int pr = ni >> 1, sel = ni & 1;
                    mma_f16(acc[mi][ni], ahi[mi], bh[pr][sel], bh[pr][sel+2]);
                }
        }
        st++; if (st >= 3) st = 0;
    }

    int gr = lane >> 2, tq = lane & 3;
    #pragma unroll
    for (int mi = 0; mi < 4; mi++) {
        #pragma unroll
        for (int ni = 0; ni < 8; ni++) {
            int col = bn + n0 + ni*8 + tq*2;
            float b0 = bias[col], b1 = bias[col + 1];
            #pragma unroll
            for (int half = 0; half < 2; half++) {
                int row = bm + m0 + mi*16 + gr + half*8;
                float v0 = acc[mi][ni][half*2 + 0] + b0;
                float v1 = acc[mi][ni][half*2 + 1] + b1;
                size_t off = (size_t)row * N + col;
                if (EPI == 2) {
                    v0 = 0.5f * v0 * (1.0f + erff(v0 * 0.7071067811865475f));
                    v1 = 0.5f * v1 * (1.0f + erff(v1 * 0.7071067811865475f));
                    __half2 p = __floats2half2_rn(v0 * 0.03125f, v1 * 0.03125f);
                    *(uint32_t*)(C16 + off) = *reinterpret_cast<uint32_t*>(&p);
                } else {
                    __half2 p = __floats2half2_rn(v0, v1);
                    *(uint32_t*)(C16 + off) = *reinterpret_cast<uint32_t*>(&p);
                }
            }
        }
    }
}

// ============================================================
// 256x128 GEMM (8 warps of 64x64), 4-stage, 1 CTA/SM — N=512 GEMMs
// (out-proj, FF2): grid=128 CTAs = one balanced wave.
// Epilogue: bias + residual -> fp32.
// ============================================================
#define ATB 32768            // A tile 256x64 fp16
#define BTB 16384            // B tile 128x64 fp16
#define SSZL (ATB + BTB)     // 49152
#define SM_SZL (4*SSZL)      // 196608

__global__ __launch_bounds__(256, 1)
void gemm_mma_l(const __half* __restrict__ Ahi, const __half* __restrict__ Bhi,
                const float* __restrict__ bias, const float* __restrict__ res,
                float* __restrict__ C,
                int M, int N, int K)
{
    extern __shared__ __align__(128) char smem[];
    uint32_t sb = smem_u32(smem);
    int tid = threadIdx.x;
    int lane = tid & 31, wid = tid >> 5;
    int bm = blockIdx.y * 256, bn = blockIdx.x * 128;
    int m0 = (wid & 3) * 64;
    int n0 = (wid >> 2) * 64;

    float acc[4][8][4];
    #pragma unroll
    for (int i = 0; i < 4; i++)
        #pragma unroll
        for (int j = 0; j < 8; j++)
            #pragma unroll
            for (int k = 0; k < 4; k++) acc[i][j][k] = 0.0f;

    auto load_stage = [&](int st, int k0) {
        uint32_t base = sb + st * SSZL;
        #pragma unroll
        for (int t = 0; t < 8; t++) {
            int line = tid + t * 256;
            int r  = line >> 3;
            int cc = line & 7;
            uint32_t d = sw128((uint32_t)(r * 128 + cc * 16));
            cp16(base + d, Ahi + (size_t)(bm + r) * K + k0 + cc * 8);
        }
        #pragma unroll
        for (int t = 0; t < 4; t++) {
            int line = tid + t * 256;
            int r  = line >> 3;
            int cc = line & 7;
            uint32_t d = sw128((uint32_t)(r * 128 + cc * 16));
            cp16(base + ATB + d, Bhi + (size_t)(bn + r) * K + k0 + cc * 8);
        }
    };

    int nk = K >> 6;
    load_stage(0, 0);   CP_COMMIT();
    load_stage(1, 64);  CP_COMMIT();
    load_stage(2, 128); CP_COMMIT();

    int st = 0;
    for (int ch = 0; ch < nk; ch++) {
        CP_WAIT2();
        __syncthreads();
        if (ch + 3 < nk) {
            int st3 = st + 3; if (st3 >= 4) st3 -= 4;
            load_stage(st3, (ch + 3) * 64);
        }
        CP_COMMIT();

        uint32_t abase = sb + st * SSZL;
        uint32_t bbase = abase + ATB;

        #pragma unroll
        for (int ks = 0; ks < 4; ks++) {
            int k0 = ks * 16;
            int frow = (lane & 7) + ((lane >> 3) & 1) * 8;
            int fcol = k0 + (lane >> 4) * 8;
            uint32_t ahi[4][4], bh[4][4];
            #pragma unroll
            for (int mi = 0; mi < 4; mi++) {
                uint32_t o = sw128((uint32_t)((m0 + mi*16 + frow) * 128 + fcol * 2));
                ldm_x4(ahi[mi], abase + o);
            }
            #pragma unroll
            for (int pr = 0; pr < 4; pr++) {
                uint32_t o = sw128((uint32_t)((n0 + pr*16 + frow) * 128 + fcol * 2));
                ldm_x4(bh[pr], bbase + o);
            }
            #pragma unroll
            for (int mi = 0; mi < 4; mi++)
                #pragma unroll
                for (int ni = 0; ni < 8; ni++) {
                    int pr = ni >> 1, sel = ni & 1;
                    mma_f16(acc[mi][ni], ahi[mi], bh[pr][sel], bh[pr][sel+2]);
                }
        }
        st++; if (st >= 4) st = 0;
    }

    int gr = lane >> 2, tq = lane & 3;
    #pragma unroll
    for (int mi = 0; mi < 4; mi++) {
        #pragma unroll
        for (int ni = 0; ni < 8; ni++) {
            int col = bn + n0 + ni*8 + tq*2;
            float b0 = bias[col], b1 = bias[col + 1];
            #pragma unroll
            for (int half = 0; half < 2; half++) {
                int row = bm + m0 + mi*16 + gr + half*8;
                size_t off = (size_t)row * N + col;
                float2 r2 = *(const float2*)(res + off);
                *(float2*)(C + off) = make_float2(acc[mi][ni][half*2+0] + b0 + r2.x,
                                                  acc[mi][ni][half*2+1] + b1 + r2.y);
            }
        }
    }
}

// ============================================================
// Local attention: thread-per-query, ILP-restructured.
// Scores d-outer/jj-inner (9 parallel FMA chains); q processed in
// two 32-dim halves to cap registers. K/V smem stride 33 (no conflicts).
// ============================================================
__global__ __launch_bounds__(128)
void attn_tq(const __half* __restrict__ qkv16, __half* __restrict__ ctx16) {
    __shared__ uint32_t Ks[136 * 33];
    __shared__ uint32_t Vs[136 * 33];
    int blk = blockIdx.x;
    int span = blk & 15;               // Sc/128 = 16 spans
    int bh = blk >> 4;
    int h = bh & (Hc - 1), b = bh >> 3;
    int s0 = span * 128;
    int rowbase = b * Sc;
    int tid = threadIdx.x;

    // stage K/V rows s0-4 .. s0+131 (136 rows x 32 half2), padded stride 33
    #pragma unroll
    for (int t = 0; t < 9; t++) {
        int i = tid + t * 128;                 // need 1088
        if (i < 136 * 8) {
            int r = i >> 3, c = i & 7;
            int j = s0 - 4 + r;
            uint4 kv = make_uint4(0,0,0,0), vv = make_uint4(0,0,0,0);
            if (j >= 0 && j < Sc) {
                const uint4* kp = (const uint4*)(qkv16 + (size_t)(rowbase + j) * D3 + Dc + h * Dhc);
                const uint4* vp = (const uint4*)(qkv16 + (size_t)(rowbase + j) * D3 + 2*Dc + h * Dhc);
                kv = kp[c]; vv = vp[c];
            }
            int base = r * 33 + c * 4;
            Ks[base+0] = kv.x; Ks[base+1] = kv.y; Ks[base+2] = kv.z; Ks[base+3] = kv.w;
            Vs[base+0] = vv.x; Vs[base+1] = vv.y; Vs[base+2] = vv.z; Vs[base+3] = vv.w;
        }
    }
    __syncthreads();

    int s = s0 + tid;
    const uint4* qp = (const uint4*)(qkv16 + (size_t)(rowbase + s) * D3 + h * Dhc);

    // scores: two 32-dim halves; inner loops keep 9 independent chains
    float e[9];
    #pragma unroll
    for (int jj = 0; jj < 9; jj++) e[jj] = 0.0f;
    #pragma unroll
    for (int hf = 0; hf < 2; hf++) {
        float2 qf[16];
        #pragma unroll
        for (int c = 0; c < 4; c++) {
            uint4 u = qp[hf*4 + c];
            uint32_t w4[4] = {u.x, u.y, u.z, u.w};
            #pragma unroll
            for (int k = 0; k < 4; k++)
                qf[c*4 + k] = __half22float2(*reinterpret_cast<__half2*>(&w4[k]));
        }
        #pragma unroll
        for (int d = 0; d < 16; d++) {
            float2 q2 = qf[d];
            #pragma unroll
            for (int jj = 0; jj < 9; jj++) {
                uint32_t kw = Ks[(tid + jj) * 33 + hf*16 + d];
                float2 k2 = __half22float2(*reinterpret_cast<__half2*>(&kw));
                e[jj] = fmaf(q2.x, k2.x, fmaf(q2.y, k2.y, e[jj]));
            }
        }
    }

    // mask + softmax
    float mx = -INFINITY;
    #pragma unroll
    for (int jj = 0; jj < 9; jj++) {
        int j = s - 4 + jj;
        e[jj] = (j >= 0 && j < Sc) ? e[jj] * 0.125f : -INFINITY;
        mx = fmaxf(mx, e[jj]);
    }
    float sum = 0.0f;
    #pragma unroll
    for (int jj = 0; jj < 9; jj++) { e[jj] = __expf(e[jj] - mx); sum += e[jj]; }
    float inv = 1.0f / sum;
    #pragma unroll
    for (int jj = 0; jj < 9; jj++) e[jj] *= inv;

    // PV: two 32-dim passes, 32 independent accumulators each; write per pass
    uint4* op = (uint4*)(ctx16 + (size_t)(rowbase + s) * Dc + h * Dhc);
    #pragma unroll
    for (int hf = 0; hf < 2; hf++) {
        float cx[32];
        #pragma unroll
        for (int d = 0; d < 32; d++) cx[d] = 0.0f;
        #pragma unroll
        for (int jj = 0; jj < 9; jj++) {
            float w = e[jj];
            int base = (tid + jj) * 33 + hf*16;
            #pragma unroll
            for (int d = 0; d < 16; d++) {
                uint32_t vw = Vs[base + d];
                float2 v2 = __half22float2(*reinterpret_cast<__half2*>(&vw));
                cx[2*d]     = fmaf(w, v2.x, cx[2*d]);
                cx[2*d + 1] = fmaf(w, v2.y, cx[2*d + 1]);
            }
        }
        uint32_t ow[16];
        #pragma unroll
        for (int d = 0; d < 16; d++) {
            __half2 p2 = __floats2half2_rn(cx[2*d] * 0.03125f, cx[2*d + 1] * 0.03125f);
            ow[d] = *reinterpret_cast<uint32_t*>(&p2);
        }
        #pragma unroll
        for (int c = 0; c < 4; c++)
            op[hf*4 + c] = make_uint4(ow[c*4], ow[c*4+1], ow[c*4+2], ow[c*4+3]);
    }
}

// ============================================================
extern "C" void kernel_launch(void* const* d_in, const int* in_sizes, int n_in,
                              void* d_out, int out_size) {
    const float* x     = (const float*)d_in[0];
    const float* in_w  = (const float*)d_in[1];
    const float* in_b  = (const float*)d_in[2];
    const float* out_w = (const float*)d_in[3];
    const float* out_b = (const float*)d_in[4];
    const float* ff_w1 = (const float*)d_in[5];
    const float* ff_b1 = (const float*)d_in[6];
    const float* ff_w2 = (const float*)d_in[7];
    const float* ff_b2 = (const float*)d_in[8];
    const float* ln1_g = (const float*)d_in[9];
    const float* ln1_b = (const float*)d_in[10];
    const float* ln2_g = (const float*)d_in[11];
    const float* ln2_b = (const float*)d_in[12];
    float* out = (float*)d_out;

    __half *fw, *a16, *ff16, *qkv16;
    float *x1;
    cudaGetSymbolAddress((void**)&fw,    g_fw);
    cudaGetSymbolAddress((void**)&a16,   g_a16);
    cudaGetSymbolAddress((void**)&ff16,  g_ff16);
    cudaGetSymbolAddress((void**)&qkv16, g_qkv16);
    cudaGetSymbolAddress((void**)&x1,    g_x1);

    cudaFuncSetAttribute(gemm_mma<0>, cudaFuncAttributeMaxDynamicSharedMemorySize, SM_SZ);
    cudaFuncSetAttribute(gemm_mma<2>, cudaFuncAttributeMaxDynamicSharedMemorySize, SM_SZ);
    cudaFuncSetAttribute(gemm_mma_l,  cudaFuncAttributeMaxDynamicSharedMemorySize, SM_SZL);

    // weight conversion (single launch, 2x ILP)
    wconv_all<<<1536, 256>>>(in_w, out_w, ff_w1, ff_w2, fw);

    // 1) a16 = fp16(LN1(x)/32)
    ln_kernel<<<Mrows, 128>>>(x, ln1_g, ln1_b, a16);
    // 2) qkv16 = fp16(a16 @ (32*in_w)^T + in_b)
    gemm_mma<0><<<dim3(D3/128, Mrows/128), 128, SM_SZ>>>(
        a16, fw + FW_IN, in_b, qkv16, Mrows, D3, Dc);
    // 3) a16 = fp16(attention(qkv16)/32)   (thread-per-query, ILP)
    attn_tq<<<16 * Bc * Hc, 128>>>(qkv16, a16);
    // 4) x1 = x + a16 @ (32*out_w)^T + out_b   (256-row tiles, 4-stage)
    gemm_mma_l<<<dim3(Dc/128, Mrows/256), 256, SM_SZL>>>(
        a16, fw + FW_OUT, out_b, x, x1, Mrows, Dc, Dc);
    // 5) a16 = fp16(LN2(x1)/32)
    ln_kernel<<<Mrows, 128>>>(x1, ln2_g, ln2_b, a16);
    // 6) ff16 = fp16(gelu(a16 @ (32*ff_w1)^T + ff_b1)/32)
    gemm_mma<2><<<dim3(DffC/128, Mrows/128), 128, SM_SZ>>>(
        a16, fw + FW_FF1, ff_b1, ff16, Mrows, DffC, Dc);
    // 7) out = x1 + ff16 @ (32*ff_w2)^T + ff_b2   (256-row tiles, 4-stage)
    gemm_mma_l<<<dim3(Dc/128, Mrows/256), 256, SM_SZL>>>(
        ff16, fw + FW_FF2, ff_b2, x1, out, Mrows, Dc, DffC);
}

// round 12
// speedup vs baseline: 1.7401x; 1.0097x over previous
#include <cuda_runtime.h>
#include <cuda_fp16.h>
#include <math.h>
#include <stdint.h>

// Problem constants
#define Bc   4
#define Sc   2048
#define Dc   512
#define Hc   8
#define Dhc  64
#define Mrows (Bc*Sc)      // 8192
#define D3   (3*Dc)        // 1536
#define DffC (4*Dc)        // 2048

// ---- scratch (device globals; no cudaMalloc allowed) ----
__device__ __half g_fw[3145728];
#define FW_IN   0
#define FW_OUT  786432
#define FW_FF1  1048576
#define FW_FF2  2097152
__device__ __half g_a16  [(size_t)Mrows * Dc];
__device__ __half g_ff16 [(size_t)Mrows * DffC];
__device__ __half g_qkv16[(size_t)Mrows * D3];
__device__ float  g_x1   [(size_t)Mrows * Dc];

// ============================================================
// helpers
// ============================================================
__device__ __forceinline__ uint32_t smem_u32(const void* p) {
    uint32_t a;
    asm("{ .reg .u64 t; cvta.to.shared.u64 t, %1; cvt.u32.u64 %0, t; }" : "=r"(a) : "l"(p));
    return a;
}
__device__ __forceinline__ uint32_t sw128(uint32_t o) { return o ^ ((o >> 3) & 0x70); }

__device__ __forceinline__ void cp16(uint32_t dst, const void* src) {
    asm volatile("cp.async.cg.shared.global [%0], [%1], 16;" :: "r"(dst), "l"(src) : "memory");
}
#define CP_COMMIT() asm volatile("cp.async.commit_group;" ::: "memory")
#define CP_WAIT1()  asm volatile("cp.async.wait_group 1;" ::: "memory")
#define CP_WAIT2()  asm volatile("cp.async.wait_group 2;" ::: "memory")

__device__ __forceinline__ void ldm_x4(uint32_t* r, uint32_t addr) {
    asm volatile("ldmatrix.sync.aligned.m8n8.x4.shared.b16 {%0,%1,%2,%3}, [%4];"
                 : "=r"(r[0]), "=r"(r[1]), "=r"(r[2]), "=r"(r[3]) : "r"(addr));
}
__device__ __forceinline__ void mma_f16(float* c, const uint32_t* a, uint32_t b0, uint32_t b1) {
    asm volatile("mma.sync.aligned.m16n8k16.row.col.f32.f16.f16.f32 "
                 "{%0,%1,%2,%3}, {%4,%5,%6,%7}, {%8,%9}, {%0,%1,%2,%3};"
                 : "+f"(c[0]), "+f"(c[1]), "+f"(c[2]), "+f"(c[3])
                 : "r"(a[0]), "r"(a[1]), "r"(a[2]), "r"(a[3]), "r"(b0), "r"(b1));
}

// ============================================================
// weight conversion: all four weights -> fp16(32*w), one launch, 4x ILP
// ============================================================
__device__ __forceinline__ void wconv_one(int i,
    const float* __restrict__ in_w, const float* __restrict__ out_w,
    const float* __restrict__ w1, const float* __restrict__ w2,
    __half* __restrict__ hi) {
    float4 v;
    if      (i < 196608) v = ((const float4*)in_w)[i];
    else if (i < 262144) v = ((const float4*)out_w)[i - 196608];
    else if (i < 524288) v = ((const float4*)w1)[i - 262144];
    else                 v = ((const float4*)w2)[i - 524288];
    __half2 p0 = __floats2half2_rn(v.x * 32.0f, v.y * 32.0f);
    __half2 p1 = __floats2half2_rn(v.z * 32.0f, v.w * 32.0f);
    ((uint2*)hi)[i] = make_uint2(*reinterpret_cast<uint32_t*>(&p0),
                                 *reinterpret_cast<uint32_t*>(&p1));
}
__global__ void wconv_all(const float* __restrict__ in_w, const float* __restrict__ out_w,
                          const float* __restrict__ w1, const float* __restrict__ w2,
                          __half* __restrict__ hi) {
    int i = blockIdx.x * 256 + threadIdx.x;          // 0..196607
    wconv_one(i,          in_w, out_w, w1, w2, hi);
    wconv_one(i + 196608, in_w, out_w, w1, w2, hi);
    wconv_one(i + 393216, in_w, out_w, w1, w2, hi);
    wconv_one(i + 589824, in_w, out_w, w1, w2, hi);
}

// ============================================================
// LayerNorm -> fp16(out/32)
// ============================================================
__global__ void ln_kernel(const float* __restrict__ x,
                          const float* __restrict__ g,
                          const float* __restrict__ b,
                          __half* __restrict__ h16) {
    int row = blockIdx.x;
    int t = threadIdx.x;                 // 0..127
    const float4* xr = (const float4*)(x + (size_t)row * Dc);
    float4 v = xr[t];
    float s  = v.x + v.y + v.z + v.w;
    float s2 = v.x*v.x + v.y*v.y + v.z*v.z + v.w*v.w;
    #pragma unroll
    for (int o = 16; o > 0; o >>= 1) {
        s  += __shfl_xor_sync(0xffffffffu, s,  o);
        s2 += __shfl_xor_sync(0xffffffffu, s2, o);
    }
    __shared__ float sh[8];
    int w = t >> 5;
    if ((t & 31) == 0) { sh[w*2] = s; sh[w*2+1] = s2; }
    __syncthreads();
    s  = sh[0] + sh[2] + sh[4] + sh[6];
    s2 = sh[1] + sh[3] + sh[5] + sh[7];
    float mu  = s * (1.0f / Dc);
    float var = s2 * (1.0f / Dc) - mu * mu;
    float rstd = rsqrtf(var + 1e-5f);
    float4 gv = ((const float4*)g)[t];
    float4 bv = ((const float4*)b)[t];
    float o0 = (v.x - mu) * rstd * gv.x + bv.x;
    float o1 = (v.y - mu) * rstd * gv.y + bv.y;
    float o2 = (v.z - mu) * rstd * gv.z + bv.z;
    float o3 = (v.w - mu) * rstd * gv.w + bv.w;
    __half2 p0 = __floats2half2_rn(o0 * 0.03125f, o1 * 0.03125f);
    __half2 p1 = __floats2half2_rn(o2 * 0.03125f, o3 * 0.03125f);
    size_t base = (size_t)row * Dc + t * 4;
    *(uint2*)(h16 + base) = make_uint2(*reinterpret_cast<uint32_t*>(&p0),
                                       *reinterpret_cast<uint32_t*>(&p1));
}

// ============================================================
// 128x128 GEMM (4 warps of 64x64), 3-stage, 2 CTAs/SM.
// EPI: 0=bias->fp16, 2=bias+GELU->fp16(/32)
// ============================================================
#define TB  16384
#define SSZ (2*TB)
#define SM_SZ (3*SSZ)        // 98304

template<int EPI>
__global__ __launch_bounds__(128, 2)
void gemm_mma(const __half* __restrict__ Ahi, const __half* __restrict__ Bhi,
              const float* __restrict__ bias,
              __half* __restrict__ C16,
              int M, int N, int K)
{
    extern __shared__ __align__(128) char smem[];
    uint32_t sb = smem_u32(smem);
    int tid = threadIdx.x;
    int lane = tid & 31, wid = tid >> 5;
    int bm = blockIdx.y * 128, bn = blockIdx.x * 128;
    int m0 = (wid & 1) * 64;
    int n0 = (wid >> 1) * 64;

    float acc[4][8][4];
    #pragma unroll
    for (int i = 0; i < 4; i++)
        #pragma unroll
        for (int j = 0; j < 8; j++)
            #pragma unroll
            for (int k = 0; k < 4; k++) acc[i][j][k] = 0.0f;

    auto load_stage = [&](int st, int k0) {
        uint32_t base = sb + st * SSZ;
        #pragma unroll
        for (int t = 0; t < 8; t++) {
            int line = tid + t * 128;
            int r  = line >> 3;
            int cc = line & 7;
            uint32_t d = sw128((uint32_t)(r * 128 + cc * 16));
            cp16(base + d,      Ahi + (size_t)(bm + r) * K + k0 + cc * 8);
            cp16(base + TB + d, Bhi + (size_t)(bn + r) * K + k0 + cc * 8);
        }
    };

    int nk = K >> 6;
    load_stage(0, 0);  CP_COMMIT();
    load_stage(1, 64); CP_COMMIT();

    int st = 0;
    for (int ch = 0; ch < nk; ch++) {
        CP_WAIT1();
        __syncthreads();
        if (ch + 2 < nk) {
            int st2 = st + 2; if (st2 >= 3) st2 -= 3;
            load_stage(st2, (ch + 2) * 64);
        }
        CP_COMMIT();

        uint32_t abase = sb + st * SSZ;
        uint32_t bbase = abase + TB;

        #pragma unroll
        for (int ks = 0; ks < 4; ks++) {
            int k0 = ks * 16;
            int frow = (lane & 7) + ((lane >> 3) & 1) * 8;
            int fcol = k0 + (lane >> 4) * 8;
            uint32_t ahi[4][4], bh[4][4];
            #pragma unroll
            for (int mi = 0; mi < 4; mi++) {
                uint32_t o = sw128((uint32_t)((m0 + mi*16 + frow) * 128 + fcol * 2));
                ldm_x4(ahi[mi], abase + o);
            }
            #pragma unroll
            for (int pr = 0; pr < 4; pr++) {
                uint32_t o = sw128((uint32_t)((n0 + pr*16 + frow) * 128 + fcol * 2));
                ldm_x4(bh[pr], bbase + o);
            }
            #pragma unroll
            for (int mi = 0; mi < 4; mi++)
                #pragma unroll
                for (int ni = 0; ni < 8; ni++) {
                    int pr = ni >> 1, sel = ni & 1;
                    mma_f16(acc[mi][ni], ahi[mi], bh[pr][sel], bh[pr][sel+2]);
                }
        }
        st++; if (st >= 3) st = 0;
    }

    int gr = lane >> 2, tq = lane & 3;
    #pragma unroll
    for (int mi = 0; mi < 4; mi++) {
        #pragma unroll
        for (int ni = 0; ni < 8; ni++) {
            int col = bn + n0 + ni*8 + tq*2;
            float b0 = bias[col], b1 = bias[col + 1];
            #pragma unroll
            for (int half = 0; half < 2; half++) {
                int row = bm + m0 + mi*16 + gr + half*8;
                float v0 = acc[mi][ni][half*2 + 0] + b0;
                float v1 = acc[mi][ni][half*2 + 1] + b1;
                size_t off = (size_t)row * N + col;
                if (EPI == 2) {
                    v0 = 0.5f * v0 * (1.0f + erff(v0 * 0.7071067811865475f));
                    v1 = 0.5f * v1 * (1.0f + erff(v1 * 0.7071067811865475f));
                    __half2 p = __floats2half2_rn(v0 * 0.03125f, v1 * 0.03125f);
                    *(uint32_t*)(C16 + off) = *reinterpret_cast<uint32_t*>(&p);
                } else {
                    __half2 p = __floats2half2_rn(v0, v1);
                    *(uint32_t*)(C16 + off) = *reinterpret_cast<uint32_t*>(&p);
                }
            }
        }
    }
}

// ============================================================
// 256x128 GEMM (8 warps of 64x64), 4-stage, 1 CTA/SM — N=512 GEMMs
// (out-proj, FF2): grid=128 CTAs = one balanced wave.
// Epilogue: bias + residual -> fp32.
// ============================================================
#define ATB 32768            // A tile 256x64 fp16
#define BTB 16384            // B tile 128x64 fp16
#define SSZL (ATB + BTB)     // 49152
#define SM_SZL (4*SSZL)      // 196608

__global__ __launch_bounds__(256, 1)
void gemm_mma_l(const __half* __restrict__ Ahi, const __half* __restrict__ Bhi,
                const float* __restrict__ bias, const float* __restrict__ res,
                float* __restrict__ C,
                int M, int N, int K)
{
    extern __shared__ __align__(128) char smem[];
    uint32_t sb = smem_u32(smem);
    int tid = threadIdx.x;
    int lane = tid & 31, wid = tid >> 5;
    int bm = blockIdx.y * 256, bn = blockIdx.x * 128;
    int m0 = (wid & 3) * 64;
    int n0 = (wid >> 2) * 64;

    float acc[4][8][4];
    #pragma unroll
    for (int i = 0; i < 4; i++)
        #pragma unroll
        for (int j = 0; j < 8; j++)
            #pragma unroll
            for (int k = 0; k < 4; k++) acc[i][j][k] = 0.0f;

    auto load_stage = [&](int st, int k0) {
        uint32_t base = sb + st * SSZL;
        #pragma unroll
        for (int t = 0; t < 8; t++) {
            int line = tid + t * 256;
            int r  = line >> 3;
            int cc = line & 7;
            uint32_t d = sw128((uint32_t)(r * 128 + cc * 16));
            cp16(base + d, Ahi + (size_t)(bm + r) * K + k0 + cc * 8);
        }
        #pragma unroll
        for (int t = 0; t < 4; t++) {
            int line = tid + t * 256;
            int r  = line >> 3;
            int cc = line & 7;
            uint32_t d = sw128((uint32_t)(r * 128 + cc * 16));
            cp16(base + ATB + d, Bhi + (size_t)(bn + r) * K + k0 + cc * 8);
        }
    };

    int nk = K >> 6;
    load_stage(0, 0);   CP_COMMIT();
    load_stage(1, 64);  CP_COMMIT();
    load_stage(2, 128); CP_COMMIT();

    int st = 0;
    for (int ch = 0; ch < nk; ch++) {
        CP_WAIT2();
        __syncthreads();
        if (ch + 3 < nk) {
            int st3 = st + 3; if (st3 >= 4) st3 -= 4;
            load_stage(st3, (ch + 3) * 64);
        }
        CP_COMMIT();

        uint32_t abase = sb + st * SSZL;
        uint32_t bbase = abase + ATB;

        #pragma unroll
        for (int ks = 0; ks < 4; ks++) {
            int k0 = ks * 16;
            int frow = (lane & 7) + ((lane >> 3) & 1) * 8;
            int fcol = k0 + (lane >> 4) * 8;
            uint32_t ahi[4][4], bh[4][4];
            #pragma unroll
            for (int mi = 0; mi < 4; mi++) {
                uint32_t o = sw128((uint32_t)((m0 + mi*16 + frow) * 128 + fcol * 2));
                ldm_x4(ahi[mi], abase + o);
            }
            #pragma unroll
            for (int pr = 0; pr < 4; pr++) {
                uint32_t o = sw128((uint32_t)((n0 + pr*16 + frow) * 128 + fcol * 2));
                ldm_x4(bh[pr], bbase + o);
            }
            #pragma unroll
            for (int mi = 0; mi < 4; mi++)
                #pragma unroll
                for (int ni = 0; ni < 8; ni++) {
                    int pr = ni >> 1, sel = ni & 1;
                    mma_f16(acc[mi][ni], ahi[mi], bh[pr][sel], bh[pr][sel+2]);
                }
        }
        st++; if (st >= 4) st = 0;
    }

    int gr = lane >> 2, tq = lane & 3;
    #pragma unroll
    for (int mi = 0; mi < 4; mi++) {
        #pragma unroll
        for (int ni = 0; ni < 8; ni++) {
            int col = bn + n0 + ni*8 + tq*2;
            float b0 = bias[col], b1 = bias[col + 1];
            #pragma unroll
            for (int half = 0; half < 2; half++) {
                int row = bm + m0 + mi*16 + gr + half*8;
                size_t off = (size_t)row * N + col;
                float2 r2 = *(const float2*)(res + off);
                *(float2*)(C + off) = make_float2(acc[mi][ni][half*2+0] + b0 + r2.x,
                                                  acc[mi][ni][half*2+1] + b1 + r2.y);
            }
        }
    }
}

// ============================================================
// Local attention: 2 threads per query (each owns a 32-dim half).
// 256-thread block covers a 128-query span; K/V staged once,
// row stride 33 half2 (conflict-free). Partial scores combined
// with one shfl_xor(1); softmax duplicated per pair (cheap).
// ============================================================
__global__ __launch_bounds__(256)
void attn_tq2(const __half* __restrict__ qkv16, __half* __restrict__ ctx16) {
    __shared__ uint32_t Ks[136 * 33];
    __shared__ uint32_t Vs[136 * 33];
    int blk = blockIdx.x;
    int span = blk & 15;               // Sc/128 = 16 spans
    int bh = blk >> 4;
    int h = bh & (Hc - 1), b = bh >> 3;
    int s0 = span * 128;
    int rowbase = b * Sc;
    int tid = threadIdx.x;

    // stage K/V rows s0-4 .. s0+131 (136 rows x 8 uint4), stride 33 words
    #pragma unroll
    for (int t = 0; t < 5; t++) {
        int i = tid + t * 256;                 // need 1088
        if (i < 136 * 8) {
            int r = i >> 3, c = i & 7;
            int j = s0 - 4 + r;
            uint4 kv = make_uint4(0,0,0,0), vv = make_uint4(0,0,0,0);
            if (j >= 0 && j < Sc) {
                const uint4* kp = (const uint4*)(qkv16 + (size_t)(rowbase + j) * D3 + Dc + h * Dhc);
                const uint4* vp = (const uint4*)(qkv16 + (size_t)(rowbase + j) * D3 + 2*Dc + h * Dhc);
                kv = kp[c]; vv = vp[c];
            }
            int base = r * 33 + c * 4;
            Ks[base+0] = kv.x; Ks[base+1] = kv.y; Ks[base+2] = kv.z; Ks[base+3] = kv.w;
            Vs[base+0] = vv.x; Vs[base+1] = vv.y; Vs[base+2] = vv.z; Vs[base+3] = vv.w;
        }
    }
    __syncthreads();

    int q  = tid >> 1;                 // 0..127 local query
    int hf = tid & 1;                  // dim half: 0 -> dims 0..31, 1 -> 32..63
    int s  = s0 + q;

    // load this thread's 32-dim q half
    const uint4* qp = (const uint4*)(qkv16 + (size_t)(rowbase + s) * D3 + h * Dhc);
    float2 qf[16];
    #pragma unroll
    for (int c = 0; c < 4; c++) {
        uint4 u = qp[hf*4 + c];
        uint32_t w4[4] = {u.x, u.y, u.z, u.w};
        #pragma unroll
        for (int k = 0; k < 4; k++)
            qf[c*4 + k] = __half22float2(*reinterpret_cast<__half2*>(&w4[k]));
    }

    // partial scores over this half's 32 dims (9 independent chains)
    float e[9];
    #pragma unroll
    for (int jj = 0; jj < 9; jj++) e[jj] = 0.0f;
    #pragma unroll
    for (int d = 0; d < 16; d++) {
        float2 q2 = qf[d];
        #pragma unroll
        for (int jj = 0; jj < 9; jj++) {
            uint32_t kw = Ks[(q + jj) * 33 + hf*16 + d];
            float2 k2 = __half22float2(*reinterpret_cast<__half2*>(&kw));
            e[jj] = fmaf(q2.x, k2.x, fmaf(q2.y, k2.y, e[jj]));
        }
    }
    // combine halves: partner lane differs only in bit 0
    #pragma unroll
    for (int jj = 0; jj < 9; jj++)
        e[jj] += __shfl_xor_sync(0xffffffffu, e[jj], 1);

    // mask + softmax (duplicated in both threads of the pair; deterministic)
    float mx = -INFINITY;
    #pragma unroll
    for (int jj = 0; jj < 9; jj++) {
        int j = s - 4 + jj;
        e[jj] = (j >= 0 && j < Sc) ? e[jj] * 0.125f : -INFINITY;
        mx = fmaxf(mx, e[jj]);
    }
    float sum = 0.0f;
    #pragma unroll
    for (int jj = 0; jj < 9; jj++) { e[jj] = __expf(e[jj] - mx); sum += e[jj]; }
    float inv = 1.0f / sum;
    #pragma unroll
    for (int jj = 0; jj < 9; jj++) e[jj] *= inv;

    // PV over this half's 32 dims
    float cx[32];
    #pragma unroll
    for (int d = 0; d < 32; d++) cx[d] = 0.0f;
    #pragma unroll
    for (int jj = 0; jj < 9; jj++) {
        float w = e[jj];
        int base = (q + jj) * 33 + hf*16;
        #pragma unroll
        for (int d = 0; d < 16; d++) {
            uint32_t vw = Vs[base + d];
            float2 v2 = __half22float2(*reinterpret_cast<__half2*>(&vw));
            cx[2*d]     = fmaf(w, v2.x, cx[2*d]);
            cx[2*d + 1] = fmaf(w, v2.y, cx[2*d + 1]);
        }
    }
    uint32_t ow[16];
    #pragma unroll
    for (int d = 0; d < 16; d++) {
        __half2 p2 = __floats2half2_rn(cx[2*d] * 0.03125f, cx[2*d + 1] * 0.03125f);
        ow[d] = *reinterpret_cast<uint32_t*>(&p2);
    }
    uint4* op = (uint4*)(ctx16 + (size_t)(rowbase + s) * Dc + h * Dhc);
    #pragma unroll
    for (int c = 0; c < 4; c++)
        op[hf*4 + c] = make_uint4(ow[c*4], ow[c*4+1], ow[c*4+2], ow[c*4+3]);
}

// ============================================================
extern "C" void kernel_launch(void* const* d_in, const int* in_sizes, int n_in,
                              void* d_out, int out_size) {
    const float* x     = (const float*)d_in[0];
    const float* in_w  = (const float*)d_in[1];
    const float* in_b  = (const float*)d_in[2];
    const float* out_w = (const float*)d_in[3];
    const float* out_b = (const float*)d_in[4];
    const float* ff_w1 = (const float*)d_in[5];
    const float* ff_b1 = (const float*)d_in[6];
    const float* ff_w2 = (const float*)d_in[7];
    const float* ff_b2 = (const float*)d_in[8];
    const float* ln1_g = (const float*)d_in[9];
    const float* ln1_b = (const float*)d_in[10];
    const float* ln2_g = (const float*)d_in[11];
    const float* ln2_b = (const float*)d_in[12];
    float* out = (float*)d_out;

    __half *fw, *a16, *ff16, *qkv16;
    float *x1;
    cudaGetSymbolAddress((void**)&fw,    g_fw);
    cudaGetSymbolAddress((void**)&a16,   g_a16);
    cudaGetSymbolAddress((void**)&ff16,  g_ff16);
    cudaGetSymbolAddress((void**)&qkv16, g_qkv16);
    cudaGetSymbolAddress((void**)&x1,    g_x1);

    cudaFuncSetAttribute(gemm_mma<0>, cudaFuncAttributeMaxDynamicSharedMemorySize, SM_SZ);
    cudaFuncSetAttribute(gemm_mma<2>, cudaFuncAttributeMaxDynamicSharedMemorySize, SM_SZ);
    cudaFuncSetAttribute(gemm_mma_l,  cudaFuncAttributeMaxDynamicSharedMemorySize, SM_SZL);

    // weight conversion (single launch, 4x ILP)
    wconv_all<<<768, 256>>>(in_w, out_w, ff_w1, ff_w2, fw);

    // 1) a16 = fp16(LN1(x)/32)
    ln_kernel<<<Mrows, 128>>>(x, ln1_g, ln1_b, a16);
    // 2) qkv16 = fp16(a16 @ (32*in_w)^T + in_b)
    gemm_mma<0><<<dim3(D3/128, Mrows/128), 128, SM_SZ>>>(
        a16, fw + FW_IN, in_b, qkv16, Mrows, D3, Dc);
    // 3) a16 = fp16(attention(qkv16)/32)   (2 threads/query)
    attn_tq2<<<16 * Bc * Hc, 256>>>(qkv16, a16);
    // 4) x1 = x + a16 @ (32*out_w)^T + out_b   (256-row tiles, 4-stage)
    gemm_mma_l<<<dim3(Dc/128, Mrows/256), 256, SM_SZL>>>(
        a16, fw + FW_OUT, out_b, x, x1, Mrows, Dc, Dc);
    // 5) a16 = fp16(LN2(x1)/32)
    ln_kernel<<<Mrows, 128>>>(x1, ln2_g, ln2_b, a16);
    // 6) ff16 = fp16(gelu(a16 @ (32*ff_w1)^T + ff_b1)/32)
    gemm_mma<2><<<dim3(DffC/128, Mrows/128), 128, SM_SZ>>>(
        a16, fw + FW_FF1, ff_b1, ff16, Mrows, DffC, Dc);
    // 7) out = x1 + ff16 @ (32*ff_w2)^T + ff_b2   (256-row tiles, 4-stage)
    gemm_mma_l<<<dim3(Dc/128, Mrows/256), 256, SM_SZL>>>(
        ff16, fw + FW_FF2, ff_b2, x1, out, Mrows, Dc, DffC);
}

// round 13
// speedup vs baseline: 1.7466x; 1.0038x over previous
#include <cuda_runtime.h>
#include <cuda_fp16.h>
#include <math.h>
#include <stdint.h>

// Problem constants
#define Bc   4
#define Sc   2048
#define Dc   512
#define Hc   8
#define Dhc  64
#define Mrows (Bc*Sc)      // 8192
#define D3   (3*Dc)        // 1536
#define DffC (4*Dc)        // 2048

// ---- scratch (device globals; no cudaMalloc allowed) ----
__device__ __half g_fw[3145728];
#define FW_IN   0
#define FW_OUT  786432
#define FW_FF1  1048576
#define FW_FF2  2097152
__device__ __half g_a16  [(size_t)Mrows * Dc];
__device__ __half g_ff16 [(size_t)Mrows * DffC];
__device__ __half g_qkv16[(size_t)Mrows * D3];
__device__ float  g_x1   [(size_t)Mrows * Dc];

// ============================================================
// helpers
// ============================================================
__device__ __forceinline__ uint32_t smem_u32(const void* p) {
    uint32_t a;
    asm("{ .reg .u64 t; cvta.to.shared.u64 t, %1; cvt.u32.u64 %0, t; }" : "=r"(a) : "l"(p));
    return a;
}
__device__ __forceinline__ uint32_t sw128(uint32_t o) { return o ^ ((o >> 3) & 0x70); }

__device__ __forceinline__ void cp16(uint32_t dst, const void* src) {
    asm volatile("cp.async.cg.shared.global [%0], [%1], 16;" :: "r"(dst), "l"(src) : "memory");
}
#define CP_COMMIT() asm volatile("cp.async.commit_group;" ::: "memory")
#define CP_WAIT1()  asm volatile("cp.async.wait_group 1;" ::: "memory")
#define CP_WAIT2()  asm volatile("cp.async.wait_group 2;" ::: "memory")

__device__ __forceinline__ void ldm_x4(uint32_t* r, uint32_t addr) {
    asm volatile("ldmatrix.sync.aligned.m8n8.x4.shared.b16 {%0,%1,%2,%3}, [%4];"
                 : "=r"(r[0]), "=r"(r[1]), "=r"(r[2]), "=r"(r[3]) : "r"(addr));
}
__device__ __forceinline__ void mma_f16(float* c, const uint32_t* a, uint32_t b0, uint32_t b1) {
    asm volatile("mma.sync.aligned.m16n8k16.row.col.f32.f16.f16.f32 "
                 "{%0,%1,%2,%3}, {%4,%5,%6,%7}, {%8,%9}, {%0,%1,%2,%3};"
                 : "+f"(c[0]), "+f"(c[1]), "+f"(c[2]), "+f"(c[3])
                 : "r"(a[0]), "r"(a[1]), "r"(a[2]), "r"(a[3]), "r"(b0), "r"(b1));
}

// ============================================================
// weight conversion: all four weights -> fp16(32*w), one launch, 4x ILP
// ============================================================
__device__ __forceinline__ void wconv_one(int i,
    const float* __restrict__ in_w, const float* __restrict__ out_w,
    const float* __restrict__ w1, const float* __restrict__ w2,
    __half* __restrict__ hi) {
    float4 v;
    if      (i < 196608) v = ((const float4*)in_w)[i];
    else if (i < 262144) v = ((const float4*)out_w)[i - 196608];
    else if (i < 524288) v = ((const float4*)w1)[i - 262144];
    else                 v = ((const float4*)w2)[i - 524288];
    __half2 p0 = __floats2half2_rn(v.x * 32.0f, v.y * 32.0f);
    __half2 p1 = __floats2half2_rn(v.z * 32.0f, v.w * 32.0f);
    ((uint2*)hi)[i] = make_uint2(*reinterpret_cast<uint32_t*>(&p0),
                                 *reinterpret_cast<uint32_t*>(&p1));
}
__global__ void wconv_all(const float* __restrict__ in_w, const float* __restrict__ out_w,
                          const float* __restrict__ w1, const float* __restrict__ w2,
                          __half* __restrict__ hi) {
    int i = blockIdx.x * 256 + threadIdx.x;          // 0..196607
    wconv_one(i,          in_w, out_w, w1, w2, hi);
    wconv_one(i + 196608, in_w, out_w, w1, w2, hi);
    wconv_one(i + 393216, in_w, out_w, w1, w2, hi);
    wconv_one(i + 589824, in_w, out_w, w1, w2, hi);
}

// ============================================================
// LayerNorm -> fp16(out/32)
// ============================================================
__global__ void ln_kernel(const float* __restrict__ x,
                          const float* __restrict__ g,
                          const float* __restrict__ b,
                          __half* __restrict__ h16) {
    int row = blockIdx.x;
    int t = threadIdx.x;                 // 0..127
    const float4* xr = (const float4*)(x + (size_t)row * Dc);
    float4 v = xr[t];
    float s  = v.x + v.y + v.z + v.w;
    float s2 = v.x*v.x + v.y*v.y + v.z*v.z + v.w*v.w;
    #pragma unroll
    for (int o = 16; o > 0; o >>= 1) {
        s  += __shfl_xor_sync(0xffffffffu, s,  o);
        s2 += __shfl_xor_sync(0xffffffffu, s2, o);
    }
    __shared__ float sh[8];
    int w = t >> 5;
    if ((t & 31) == 0) { sh[w*2] = s; sh[w*2+1] = s2; }
    __syncthreads();
    s  = sh[0] + sh[2] + sh[4] + sh[6];
    s2 = sh[1] + sh[3] + sh[5] + sh[7];
    float mu  = s * (1.0f / Dc);
    float var = s2 * (1.0f / Dc) - mu * mu;
    float rstd = rsqrtf(var + 1e-5f);
    float4 gv = ((const float4*)g)[t];
    float4 bv = ((const float4*)b)[t];
    float o0 = (v.x - mu) * rstd * gv.x + bv.x;
    float o1 = (v.y - mu) * rstd * gv.y + bv.y;
    float o2 = (v.z - mu) * rstd * gv.z + bv.z;
    float o3 = (v.w - mu) * rstd * gv.w + bv.w;
    __half2 p0 = __floats2half2_rn(o0 * 0.03125f, o1 * 0.03125f);
    __half2 p1 = __floats2half2_rn(o2 * 0.03125f, o3 * 0.03125f);
    size_t base = (size_t)row * Dc + t * 4;
    *(uint2*)(h16 + base) = make_uint2(*reinterpret_cast<uint32_t*>(&p0),
                                       *reinterpret_cast<uint32_t*>(&p1));
}

// ============================================================
// 128x128 GEMM (4 warps of 64x64), 3-stage, 2 CTAs/SM.
// EPI: 0=bias->fp16, 2=bias+GELU->fp16(/32)
// ============================================================
#define TB  16384
#define SSZ (2*TB)
#define SM_SZ (3*SSZ)        // 98304

template<int EPI>
__global__ __launch_bounds__(128, 2)
void gemm_mma(const __half* __restrict__ Ahi, const __half* __restrict__ Bhi,
              const float* __restrict__ bias,
              __half* __restrict__ C16,
              int M, int N, int K)
{
    extern __shared__ __align__(128) char smem[];
    uint32_t sb = smem_u32(smem);
    int tid = threadIdx.x;
    int lane = tid & 31, wid = tid >> 5;
    int bm = blockIdx.y * 128, bn = blockIdx.x * 128;
    int m0 = (wid & 1) * 64;
    int n0 = (wid >> 1) * 64;

    float acc[4][8][4];
    #pragma unroll
    for (int i = 0; i < 4; i++)
        #pragma unroll
        for (int j = 0; j < 8; j++)
            #pragma unroll
            for (int k = 0; k < 4; k++) acc[i][j][k] = 0.0f;

    auto load_stage = [&](int st, int k0) {
        uint32_t base = sb + st * SSZ;
        #pragma unroll
        for (int t = 0; t < 8; t++) {
            int line = tid + t * 128;
            int r  = line >> 3;
            int cc = line & 7;
            uint32_t d = sw128((uint32_t)(r * 128 + cc * 16));
            cp16(base + d,      Ahi + (size_t)(bm + r) * K + k0 + cc * 8);
            cp16(base + TB + d, Bhi + (size_t)(bn + r) * K + k0 + cc * 8);
        }
    };

    int nk = K >> 6;
    load_stage(0, 0);  CP_COMMIT();
    load_stage(1, 64); CP_COMMIT();

    int st = 0;
    for (int ch = 0; ch < nk; ch++) {
        CP_WAIT1();
        __syncthreads();
        if (ch + 2 < nk) {
            int st2 = st + 2; if (st2 >= 3) st2 -= 3;
            load_stage(st2, (ch + 2) * 64);
        }
        CP_COMMIT();

        uint32_t abase = sb + st * SSZ;
        uint32_t bbase = abase + TB;

        #pragma unroll
        for (int ks = 0; ks < 4; ks++) {
            int k0 = ks * 16;
            int frow = (lane & 7) + ((lane >> 3) & 1) * 8;
            int fcol = k0 + (lane >> 4) * 8;
            uint32_t ahi[4][4], bh[4][4];
            #pragma unroll
            for (int mi = 0; mi < 4; mi++) {
                uint32_t o = sw128((uint32_t)((m0 + mi*16 + frow) * 128 + fcol * 2));
                ldm_x4(ahi[mi], abase + o);
            }
            #pragma unroll
            for (int pr = 0; pr < 4; pr++) {
                uint32_t o = sw128((uint32_t)((n0 + pr*16 + frow) * 128 + fcol * 2));
                ldm_x4(bh[pr], bbase + o);
            }
            #pragma unroll
            for (int mi = 0; mi < 4; mi++)
                #pragma unroll
                for (int ni = 0; ni < 8; ni++) {
                    int pr = ni >> 1, sel = ni & 1;
                    mma_f16(acc[mi][ni], ahi[mi], bh[pr][sel], bh[pr][sel+2]);
                }
        }
        st++; if (st >= 3) st = 0;
    }

    int gr = lane >> 2, tq = lane & 3;
    #pragma unroll
    for (int mi = 0; mi < 4; mi++) {
        #pragma unroll
        for (int ni = 0; ni < 8; ni++) {
            int col = bn + n0 + ni*8 + tq*2;
            float b0 = bias[col], b1 = bias[col + 1];
            #pragma unroll
            for (int half = 0; half < 2; half++) {
                int row = bm + m0 + mi*16 + gr + half*8;
                float v0 = acc[mi][ni][half*2 + 0] + b0;
                float v1 = acc[mi][ni][half*2 + 1] + b1;
                size_t off = (size_t)row * N + col;
                if (EPI == 2) {
                    v0 = 0.5f * v0 * (1.0f + erff(v0 * 0.7071067811865475f));
                    v1 = 0.5f * v1 * (1.0f + erff(v1 * 0.7071067811865475f));
                    __half2 p = __floats2half2_rn(v0 * 0.03125f, v1 * 0.03125f);
                    *(uint32_t*)(C16 + off) = *reinterpret_cast<uint32_t*>(&p);
                } else {
                    __half2 p = __floats2half2_rn(v0, v1);
                    *(uint32_t*)(C16 + off) = *reinterpret_cast<uint32_t*>(&p);
                }
            }
        }
    }
}

// ============================================================
// 256x128 GEMM (8 warps of 64x64), 4-stage, 1 CTA/SM — N=512 GEMMs
// (out-proj, FF2): grid=128 CTAs = one balanced wave.
// Epilogue: bias + residual -> fp32.
// ============================================================
#define ATB 32768            // A tile 256x64 fp16
#define BTB 16384            // B tile 128x64 fp16
#define SSZL (ATB + BTB)     // 49152
#define SM_SZL (4*SSZL)      // 196608

__global__ __launch_bounds__(256, 1)
void gemm_mma_l(const __half* __restrict__ Ahi, const __half* __restrict__ Bhi,
                const float* __restrict__ bias, const float* __restrict__ res,
                float* __restrict__ C,
                int M, int N, int K)
{
    extern __shared__ __align__(128) char smem[];
    uint32_t sb = smem_u32(smem);
    int tid = threadIdx.x;
    int lane = tid & 31, wid = tid >> 5;
    int bm = blockIdx.y * 256, bn = blockIdx.x * 128;
    int m0 = (wid & 3) * 64;
    int n0 = (wid >> 2) * 64;

    float acc[4][8][4];
    #pragma unroll
    for (int i = 0; i < 4; i++)
        #pragma unroll
        for (int j = 0; j < 8; j++)
            #pragma unroll
            for (int k = 0; k < 4; k++) acc[i][j][k] = 0.0f;

    auto load_stage = [&](int st, int k0) {
        uint32_t base = sb + st * SSZL;
        #pragma unroll
        for (int t = 0; t < 8; t++) {
            int line = tid + t * 256;
            int r  = line >> 3;
            int cc = line & 7;
            uint32_t d = sw128((uint32_t)(r * 128 + cc * 16));
            cp16(base + d, Ahi + (size_t)(bm + r) * K + k0 + cc * 8);
        }
        #pragma unroll
        for (int t = 0; t < 4; t++) {
            int line = tid + t * 256;
            int r  = line >> 3;
            int cc = line & 7;
            uint32_t d = sw128((uint32_t)(r * 128 + cc * 16));
            cp16(base + ATB + d, Bhi + (size_t)(bn + r) * K + k0 + cc * 8);
        }
    };

    int nk = K >> 6;
    load_stage(0, 0);   CP_COMMIT();
    load_stage(1, 64);  CP_COMMIT();
    load_stage(2, 128); CP_COMMIT();

    int st = 0;
    for (int ch = 0; ch < nk; ch++) {
        CP_WAIT2();
        __syncthreads();
        if (ch + 3 < nk) {
            int st3 = st + 3; if (st3 >= 4) st3 -= 4;
            load_stage(st3, (ch + 3) * 64);
        }
        CP_COMMIT();

        uint32_t abase = sb + st * SSZL;
        uint32_t bbase = abase + ATB;

        #pragma unroll
        for (int ks = 0; ks < 4; ks++) {
            int k0 = ks * 16;
            int frow = (lane & 7) + ((lane >> 3) & 1) * 8;
            int fcol = k0 + (lane >> 4) * 8;
            uint32_t ahi[4][4], bh[4][4];
            #pragma unroll
            for (int mi = 0; mi < 4; mi++) {
                uint32_t o = sw128((uint32_t)((m0 + mi*16 + frow) * 128 + fcol * 2));
                ldm_x4(ahi[mi], abase + o);
            }
            #pragma unroll
            for (int pr = 0; pr < 4; pr++) {
                uint32_t o = sw128((uint32_t)((n0 + pr*16 + frow) * 128 + fcol * 2));
                ldm_x4(bh[pr], bbase + o);
            }
            #pragma unroll
            for (int mi = 0; mi < 4; mi++)
                #pragma unroll
                for (int ni = 0; ni < 8; ni++) {
                    int pr = ni >> 1, sel = ni & 1;
                    mma_f16(acc[mi][ni], ahi[mi], bh[pr][sel], bh[pr][sel+2]);
                }
        }
        st++; if (st >= 4) st = 0;
    }

    int gr = lane >> 2, tq = lane & 3;
    #pragma unroll
    for (int mi = 0; mi < 4; mi++) {
        #pragma unroll
        for (int ni = 0; ni < 8; ni++) {
            int col = bn + n0 + ni*8 + tq*2;
            float b0 = bias[col], b1 = bias[col + 1];
            #pragma unroll
            for (int half = 0; half < 2; half++) {
                int row = bm + m0 + mi*16 + gr + half*8;
                size_t off = (size_t)row * N + col;
                float2 r2 = *(const float2*)(res + off);
                *(float2*)(C + off) = make_float2(acc[mi][ni][half*2+0] + b0 + r2.x,
                                                  acc[mi][ni][half*2+1] + b1 + r2.y);
            }
        }
    }
}

// ============================================================
// Local attention: 4 threads per query (each owns a 16-dim quarter).
// 512-thread block covers a 128-query span; K/V staged once,
// row stride 33 half2 (conflict-free: (q + 8*qt + d + jj) mod 32
// enumerates all lanes). Partials combined with shfl_xor(1),(2);
// softmax duplicated per quartet (9-elt, cheap).
// ============================================================
__global__ __launch_bounds__(512)
void attn_tq4(const __half* __restrict__ qkv16, __half* __restrict__ ctx16) {
    __shared__ uint32_t Ks[136 * 33];
    __shared__ uint32_t Vs[136 * 33];
    int blk = blockIdx.x;
    int span = blk & 15;               // Sc/128 = 16 spans
    int bh = blk >> 4;
    int h = bh & (Hc - 1), b = bh >> 3;
    int s0 = span * 128;
    int rowbase = b * Sc;
    int tid = threadIdx.x;

    // stage K/V rows s0-4 .. s0+131 (136 rows x 8 uint4), stride 33 words
    #pragma unroll
    for (int t = 0; t < 3; t++) {
        int i = tid + t * 512;                 // need 1088
        if (i < 136 * 8) {
            int r = i >> 3, c = i & 7;
            int j = s0 - 4 + r;
            uint4 kv = make_uint4(0,0,0,0), vv = make_uint4(0,0,0,0);
            if (j >= 0 && j < Sc) {
                const uint4* kp = (const uint4*)(qkv16 + (size_t)(rowbase + j) * D3 + Dc + h * Dhc);
                const uint4* vp = (const uint4*)(qkv16 + (size_t)(rowbase + j) * D3 + 2*Dc + h * Dhc);
                kv = kp[c]; vv = vp[c];
            }
            int base = r * 33 + c * 4;
            Ks[base+0] = kv.x; Ks[base+1] = kv.y; Ks[base+2] = kv.z; Ks[base+3] = kv.w;
            Vs[base+0] = vv.x; Vs[base+1] = vv.y; Vs[base+2] = vv.z; Vs[base+3] = vv.w;
        }
    }
    __syncthreads();

    int q  = tid >> 2;                 // 0..127 local query
    int qt = tid & 3;                  // dim quarter: 16 dims = 8 half2 words
    int s  = s0 + q;

    // load this thread's 16-dim q quarter (2 uint4 = 8 half2)
    const uint4* qp = (const uint4*)(qkv16 + (size_t)(rowbase + s) * D3 + h * Dhc);
    float2 qf[8];
    #pragma unroll
    for (int c = 0; c < 2; c++) {
        uint4 u = qp[qt*2 + c];
        uint32_t w4[4] = {u.x, u.y, u.z, u.w};
        #pragma unroll
        for (int k = 0; k < 4; k++)
            qf[c*4 + k] = __half22float2(*reinterpret_cast<__half2*>(&w4[k]));
    }

    // partial scores over this quarter's 16 dims (9 independent chains)
    float e[9];
    #pragma unroll
    for (int jj = 0; jj < 9; jj++) e[jj] = 0.0f;
    #pragma unroll
    for (int d = 0; d < 8; d++) {
        float2 q2 = qf[d];
        #pragma unroll
        for (int jj = 0; jj < 9; jj++) {
            uint32_t kw = Ks[(q + jj) * 33 + qt*8 + d];
            float2 k2 = __half22float2(*reinterpret_cast<__half2*>(&kw));
            e[jj] = fmaf(q2.x, k2.x, fmaf(q2.y, k2.y, e[jj]));
        }
    }
    // combine quarters: partner lanes differ in bits 0,1
    #pragma unroll
    for (int jj = 0; jj < 9; jj++) {
        e[jj] += __shfl_xor_sync(0xffffffffu, e[jj], 1);
        e[jj] += __shfl_xor_sync(0xffffffffu, e[jj], 2);
    }

    // mask + softmax (duplicated in all 4 threads of the quartet)
    float mx = -INFINITY;
    #pragma unroll
    for (int jj = 0; jj < 9; jj++) {
        int j = s - 4 + jj;
        e[jj] = (j >= 0 && j < Sc) ? e[jj] * 0.125f : -INFINITY;
        mx = fmaxf(mx, e[jj]);
    }
    float sum = 0.0f;
    #pragma unroll
    for (int jj = 0; jj < 9; jj++) { e[jj] = __expf(e[jj] - mx); sum += e[jj]; }
    float inv = 1.0f / sum;
    #pragma unroll
    for (int jj = 0; jj < 9; jj++) e[jj] *= inv;

    // PV over this quarter's 16 dims
    float cx[16];
    #pragma unroll
    for (int d = 0; d < 16; d++) cx[d] = 0.0f;
    #pragma unroll
    for (int jj = 0; jj < 9; jj++) {
        float w = e[jj];
        int base = (q + jj) * 33 + qt*8;
        #pragma unroll
        for (int d = 0; d < 8; d++) {
            uint32_t vw = Vs[base + d];
            float2 v2 = __half22float2(*reinterpret_cast<__half2*>(&vw));
            cx[2*d]     = fmaf(w, v2.x, cx[2*d]);
            cx[2*d + 1] = fmaf(w, v2.y, cx[2*d + 1]);
        }
    }
    uint32_t ow[8];
    #pragma unroll
    for (int d = 0; d < 8; d++) {
        __half2 p2 = __floats2half2_rn(cx[2*d] * 0.03125f, cx[2*d + 1] * 0.03125f);
        ow[d] = *reinterpret_cast<uint32_t*>(&p2);
    }
    uint4* op = (uint4*)(ctx16 + (size_t)(rowbase + s) * Dc + h * Dhc);
    op[qt*2 + 0] = make_uint4(ow[0], ow[1], ow[2], ow[3]);
    op[qt*2 + 1] = make_uint4(ow[4], ow[5], ow[6], ow[7]);
}

// ============================================================
extern "C" void kernel_launch(void* const* d_in, const int* in_sizes, int n_in,
                              void* d_out, int out_size) {
    const float* x     = (const float*)d_in[0];
    const float* in_w  = (const float*)d_in[1];
    const float* in_b  = (const float*)d_in[2];
    const float* out_w = (const float*)d_in[3];
    const float* out_b = (const float*)d_in[4];
    const float* ff_w1 = (const float*)d_in[5];
    const float* ff_b1 = (const float*)d_in[6];
    const float* ff_w2 = (const float*)d_in[7];
    const float* ff_b2 = (const float*)d_in[8];
    const float* ln1_g = (const float*)d_in[9];
    const float* ln1_b = (const float*)d_in[10];
    const float* ln2_g = (const float*)d_in[11];
    const float* ln2_b = (const float*)d_in[12];
    float* out = (float*)d_out;

    __half *fw, *a16, *ff16, *qkv16;
    float *x1;
    cudaGetSymbolAddress((void**)&fw,    g_fw);
    cudaGetSymbolAddress((void**)&a16,   g_a16);
    cudaGetSymbolAddress((void**)&ff16,  g_ff16);
    cudaGetSymbolAddress((void**)&qkv16, g_qkv16);
    cudaGetSymbolAddress((void**)&x1,    g_x1);

    cudaFuncSetAttribute(gemm_mma<0>, cudaFuncAttributeMaxDynamicSharedMemorySize, SM_SZ);
    cudaFuncSetAttribute(gemm_mma<2>, cudaFuncAttributeMaxDynamicSharedMemorySize, SM_SZ);
    cudaFuncSetAttribute(gemm_mma_l,  cudaFuncAttributeMaxDynamicSharedMemorySize, SM_SZL);

    // weight conversion (single launch, 4x ILP)
    wconv_all<<<768, 256>>>(in_w, out_w, ff_w1, ff_w2, fw);

    // 1) a16 = fp16(LN1(x)/32)
    ln_kernel<<<Mrows, 128>>>(x, ln1_g, ln1_b, a16);
    // 2) qkv16 = fp16(a16 @ (32*in_w)^T + in_b)
    gemm_mma<0><<<dim3(D3/128, Mrows/128), 128, SM_SZ>>>(
        a16, fw + FW_IN, in_b, qkv16, Mrows, D3, Dc);
    // 3) a16 = fp16(attention(qkv16)/32)   (4 threads/query)
    attn_tq4<<<16 * Bc * Hc, 512>>>(qkv16, a16);
    // 4) x1 = x + a16 @ (32*out_w)^T + out_b   (256-row tiles, 4-stage)
    gemm_mma_l<<<dim3(Dc/128, Mrows/256), 256, SM_SZL>>>(
        a16, fw + FW_OUT, out_b, x, x1, Mrows, Dc, Dc);
    // 5) a16 = fp16(LN2(x1)/32)
    ln_kernel<<<Mrows, 128>>>(x1, ln2_g, ln2_b, a16);
    // 6) ff16 = fp16(gelu(a16 @ (32*ff_w1)^T + ff_b1)/32)
    gemm_mma<2><<<dim3(DffC/128, Mrows/128), 128, SM_SZ>>>(
        a16, fw + FW_FF1, ff_b1, ff16, Mrows, DffC, Dc);
    // 7) out = x1 + ff16 @ (32*ff_w2)^T + ff_b2   (256-row tiles, 4-stage)
    gemm_mma_l<<<dim3(Dc/128, Mrows/256), 256, SM_SZL>>>(
        ff16, fw + FW_FF2, ff_b2, x1, out, Mrows, Dc, DffC);
}

// round 14
// speedup vs baseline: 1.7623x; 1.0090x over previous
#include <cuda_runtime.h>
#include <cuda_fp16.h>
#include <math.h>
#include <stdint.h>

// Problem constants
#define Bc   4
#define Sc   2048
#define Dc   512
#define Hc   8
#define Dhc  64
#define Mrows (Bc*Sc)      // 8192
#define D3   (3*Dc)        // 1536
#define DffC (4*Dc)        // 2048

// ---- scratch (device globals; no cudaMalloc allowed) ----
__device__ __half g_fw[3145728];
#define FW_IN   0
#define FW_OUT  786432
#define FW_FF1  1048576
#define FW_FF2  2097152
__device__ __half g_a16  [(size_t)Mrows * Dc];
__device__ __half g_ff16 [(size_t)Mrows * DffC];
__device__ __half g_qkv16[(size_t)Mrows * D3];
__device__ float  g_x1   [(size_t)Mrows * Dc];

// ============================================================
// helpers
// ============================================================
__device__ __forceinline__ uint32_t smem_u32(const void* p) {
    uint32_t a;
    asm("{ .reg .u64 t; cvta.to.shared.u64 t, %1; cvt.u32.u64 %0, t; }" : "=r"(a) : "l"(p));
    return a;
}
__device__ __forceinline__ uint32_t sw128(uint32_t o) { return o ^ ((o >> 3) & 0x70); }

__device__ __forceinline__ void cp16(uint32_t dst, const void* src) {
    asm volatile("cp.async.cg.shared.global [%0], [%1], 16;" :: "r"(dst), "l"(src) : "memory");
}
#define CP_COMMIT() asm volatile("cp.async.commit_group;" ::: "memory")
#define CP_WAIT1()  asm volatile("cp.async.wait_group 1;" ::: "memory")
#define CP_WAIT2()  asm volatile("cp.async.wait_group 2;" ::: "memory")

__device__ __forceinline__ void ldm_x4(uint32_t* r, uint32_t addr) {
    asm volatile("ldmatrix.sync.aligned.m8n8.x4.shared.b16 {%0,%1,%2,%3}, [%4];"
                 : "=r"(r[0]), "=r"(r[1]), "=r"(r[2]), "=r"(r[3]) : "r"(addr));
}
__device__ __forceinline__ void mma_f16(float* c, const uint32_t* a, uint32_t b0, uint32_t b1) {
    asm volatile("mma.sync.aligned.m16n8k16.row.col.f32.f16.f16.f32 "
                 "{%0,%1,%2,%3}, {%4,%5,%6,%7}, {%8,%9}, {%0,%1,%2,%3};"
                 : "+f"(c[0]), "+f"(c[1]), "+f"(c[2]), "+f"(c[3])
                 : "r"(a[0]), "r"(a[1]), "r"(a[2]), "r"(a[3]), "r"(b0), "r"(b1));
}

// ============================================================
// Fused prologue: weight conversion (blocks 0..767, 4x ILP) and
// LN1 -> fp16(/32) (blocks 768..8959, one row each).
// The two halves are independent and fill the chip together.
// ============================================================
__device__ __forceinline__ void wconv_one(int i,
    const float* __restrict__ in_w, const float* __restrict__ out_w,
    const float* __restrict__ w1, const float* __restrict__ w2,
    __half* __restrict__ hi) {
    float4 v;
    if      (i < 196608) v = ((const float4*)in_w)[i];
    else if (i < 262144) v = ((const float4*)out_w)[i - 196608];
    else if (i < 524288) v = ((const float4*)w1)[i - 262144];
    else                 v = ((const float4*)w2)[i - 524288];
    __half2 p0 = __floats2half2_rn(v.x * 32.0f, v.y * 32.0f);
    __half2 p1 = __floats2half2_rn(v.z * 32.0f, v.w * 32.0f);
    ((uint2*)hi)[i] = make_uint2(*reinterpret_cast<uint32_t*>(&p0),
                                 *reinterpret_cast<uint32_t*>(&p1));
}

__device__ __forceinline__ void ln_row(int row, const float* __restrict__ x,
                                       const float* __restrict__ g,
                                       const float* __restrict__ b,
                                       __half* __restrict__ h16, int t) {
    const float4* xr = (const float4*)(x + (size_t)row * Dc);
    float4 v = xr[t];
    float s  = v.x + v.y + v.z + v.w;
    float s2 = v.x*v.x + v.y*v.y + v.z*v.z + v.w*v.w;
    #pragma unroll
    for (int o = 16; o > 0; o >>= 1) {
        s  += __shfl_xor_sync(0xffffffffu, s,  o);
        s2 += __shfl_xor_sync(0xffffffffu, s2, o);
    }
    __shared__ float sh[8];
    int w = t >> 5;
    if ((t & 31) == 0) { sh[w*2] = s; sh[w*2+1] = s2; }
    __syncthreads();
    s  = sh[0] + sh[2] + sh[4] + sh[6];
    s2 = sh[1] + sh[3] + sh[5] + sh[7];
    float mu  = s * (1.0f / Dc);
    float var = s2 * (1.0f / Dc) - mu * mu;
    float rstd = rsqrtf(var + 1e-5f);
    float4 gv = ((const float4*)g)[t];
    float4 bv = ((const float4*)b)[t];
    float o0 = (v.x - mu) * rstd * gv.x + bv.x;
    float o1 = (v.y - mu) * rstd * gv.y + bv.y;
    float o2 = (v.z - mu) * rstd * gv.z + bv.z;
    float o3 = (v.w - mu) * rstd * gv.w + bv.w;
    __half2 p0 = __floats2half2_rn(o0 * 0.03125f, o1 * 0.03125f);
    __half2 p1 = __floats2half2_rn(o2 * 0.03125f, o3 * 0.03125f);
    size_t base = (size_t)row * Dc + t * 4;
    *(uint2*)(h16 + base) = make_uint2(*reinterpret_cast<uint32_t*>(&p0),
                                       *reinterpret_cast<uint32_t*>(&p1));
}

__global__ void prologue_kernel(const float* __restrict__ in_w, const float* __restrict__ out_w,
                                const float* __restrict__ w1, const float* __restrict__ w2,
                                __half* __restrict__ fw,
                                const float* __restrict__ x,
                                const float* __restrict__ ln1_g, const float* __restrict__ ln1_b,
                                __half* __restrict__ a16) {
    int blk = blockIdx.x;
    if (blk < 768) {
        // weight conversion: 768 blocks x 128 threads x 8 ILP = 786432 float4
        int i = blk * 128 + threadIdx.x;           // 0..98303
        #pragma unroll
        for (int t = 0; t < 8; t++)
            wconv_one(i + t * 98304, in_w, out_w, w1, w2, fw);
    } else {
        // LN1: one row per block
        ln_row(blk - 768, x, ln1_g, ln1_b, a16, threadIdx.x);
    }
}

// standalone LN (for LN2)
__global__ void ln_kernel(const float* __restrict__ x,
                          const float* __restrict__ g,
                          const float* __restrict__ b,
                          __half* __restrict__ h16) {
    ln_row(blockIdx.x, x, g, b, h16, threadIdx.x);
}

// ============================================================
// 128x128 GEMM (4 warps of 64x64), 3-stage, 2 CTAs/SM.
// EPI: 0=bias->fp16, 2=bias+GELU->fp16(/32)
// ============================================================
#define TB  16384
#define SSZ (2*TB)
#define SM_SZ (3*SSZ)        // 98304

template<int EPI>
__global__ __launch_bounds__(128, 2)
void gemm_mma(const __half* __restrict__ Ahi, const __half* __restrict__ Bhi,
              const float* __restrict__ bias,
              __half* __restrict__ C16,
              int M, int N, int K)
{
    extern __shared__ __align__(128) char smem[];
    uint32_t sb = smem_u32(smem);
    int tid = threadIdx.x;
    int lane = tid & 31, wid = tid >> 5;
    int bm = blockIdx.y * 128, bn = blockIdx.x * 128;
    int m0 = (wid & 1) * 64;
    int n0 = (wid >> 1) * 64;

    float acc[4][8][4];
    #pragma unroll
    for (int i = 0; i < 4; i++)
        #pragma unroll
        for (int j = 0; j < 8; j++)
            #pragma unroll
            for (int k = 0; k < 4; k++) acc[i][j][k] = 0.0f;

    auto load_stage = [&](int st, int k0) {
        uint32_t base = sb + st * SSZ;
        #pragma unroll
        for (int t = 0; t < 8; t++) {
            int line = tid + t * 128;
            int r  = line >> 3;
            int cc = line & 7;
            uint32_t d = sw128((uint32_t)(r * 128 + cc * 16));
            cp16(base + d,      Ahi + (size_t)(bm + r) * K + k0 + cc * 8);
            cp16(base + TB + d, Bhi + (size_t)(bn + r) * K + k0 + cc * 8);
        }
    };

    int nk = K >> 6;
    load_stage(0, 0);  CP_COMMIT();
    load_stage(1, 64); CP_COMMIT();

    int st = 0;
    for (int ch = 0; ch < nk; ch++) {
        CP_WAIT1();
        __syncthreads();
        if (ch + 2 < nk) {
            int st2 = st + 2; if (st2 >= 3) st2 -= 3;
            load_stage(st2, (ch + 2) * 64);
        }
        CP_COMMIT();

        uint32_t abase = sb + st * SSZ;
        uint32_t bbase = abase + TB;

        #pragma unroll
        for (int ks = 0; ks < 4; ks++) {
            int k0 = ks * 16;
            int frow = (lane & 7) + ((lane >> 3) & 1) * 8;
            int fcol = k0 + (lane >> 4) * 8;
            uint32_t ahi[4][4], bh[4][4];
            #pragma unroll
            for (int mi = 0; mi < 4; mi++) {
                uint32_t o = sw128((uint32_t)((m0 + mi*16 + frow) * 128 + fcol * 2));
                ldm_x4(ahi[mi], abase + o);
            }
            #pragma unroll
            for (int pr = 0; pr < 4; pr++) {
                uint32_t o = sw128((uint32_t)((n0 + pr*16 + frow) * 128 + fcol * 2));
                ldm_x4(bh[pr], bbase + o);
            }
            #pragma unroll
            for (int mi = 0; mi < 4; mi++)
                #pragma unroll
                for (int ni = 0; ni < 8; ni++) {
                    int pr = ni >> 1, sel = ni & 1;
                    mma_f16(acc[mi][ni], ahi[mi], bh[pr][sel], bh[pr][sel+2]);
                }
        }
        st++; if (st >= 3) st = 0;
    }

    int gr = lane >> 2, tq = lane & 3;
    #pragma unroll
    for (int mi = 0; mi < 4; mi++) {
        #pragma unroll
        for (int ni = 0; ni < 8; ni++) {
            int col = bn + n0 + ni*8 + tq*2;
            float b0 = bias[col], b1 = bias[col + 1];
            #pragma unroll
            for (int half = 0; half < 2; half++) {
                int row = bm + m0 + mi*16 + gr + half*8;
                float v0 = acc[mi][ni][half*2 + 0] + b0;
                float v1 = acc[mi][ni][half*2 + 1] + b1;
                size_t off = (size_t)row * N + col;
                if (EPI == 2) {
                    v0 = 0.5f * v0 * (1.0f + erff(v0 * 0.7071067811865475f));
                    v1 = 0.5f * v1 * (1.0f + erff(v1 * 0.7071067811865475f));
                    __half2 p = __floats2half2_rn(v0 * 0.03125f, v1 * 0.03125f);
                    *(uint32_t*)(C16 + off) = *reinterpret_cast<uint32_t*>(&p);
                } else {
                    __half2 p = __floats2half2_rn(v0, v1);
                    *(uint32_t*)(C16 + off) = *reinterpret_cast<uint32_t*>(&p);
                }
            }
        }
    }
}

// ============================================================
// 256x128 GEMM (8 warps of 64x64), 4-stage, 1 CTA/SM — N=512 GEMMs
// (out-proj, FF2): grid=128 CTAs = one balanced wave.
// Epilogue: bias + residual -> fp32.
// ============================================================
#define ATB 32768
#define BTB 16384
#define SSZL (ATB + BTB)     // 49152
#define SM_SZL (4*SSZL)      // 196608

__global__ __launch_bounds__(256, 1)
void gemm_mma_l(const __half* __restrict__ Ahi, const __half* __restrict__ Bhi,
                const float* __restrict__ bias, const float* __restrict__ res,
                float* __restrict__ C,
                int M, int N, int K)
{
    extern __shared__ __align__(128) char smem[];
    uint32_t sb = smem_u32(smem);
    int tid = threadIdx.x;
    int lane = tid & 31, wid = tid >> 5;
    int bm = blockIdx.y * 256, bn = blockIdx.x * 128;
    int m0 = (wid & 3) * 64;
    int n0 = (wid >> 2) * 64;

    float acc[4][8][4];
    #pragma unroll
    for (int i = 0; i < 4; i++)
        #pragma unroll
        for (int j = 0; j < 8; j++)
            #pragma unroll
            for (int k = 0; k < 4; k++) acc[i][j][k] = 0.0f;

    auto load_stage = [&](int st, int k0) {
        uint32_t base = sb + st * SSZL;
        #pragma unroll
        for (int t = 0; t < 8; t++) {
            int line = tid + t * 256;
            int r  = line >> 3;
            int cc = line & 7;
            uint32_t d = sw128((uint32_t)(r * 128 + cc * 16));
            cp16(base + d, Ahi + (size_t)(bm + r) * K + k0 + cc * 8);
        }
        #pragma unroll
        for (int t = 0; t < 4; t++) {
            int line = tid + t * 256;
            int r  = line >> 3;
            int cc = line & 7;
            uint32_t d = sw128((uint32_t)(r * 128 + cc * 16));
            cp16(base + ATB + d, Bhi + (size_t)(bn + r) * K + k0 + cc * 8);
        }
    };

    int nk = K >> 6;
    load_stage(0, 0);   CP_COMMIT();
    load_stage(1, 64);  CP_COMMIT();
    load_stage(2, 128); CP_COMMIT();

    int st = 0;
    for (int ch = 0; ch < nk; ch++) {
        CP_WAIT2();
        __syncthreads();
        if (ch + 3 < nk) {
            int st3 = st + 3; if (st3 >= 4) st3 -= 4;
            load_stage(st3, (ch + 3) * 64);
        }
        CP_COMMIT();

        uint32_t abase = sb + st * SSZL;
        uint32_t bbase = abase + ATB;

        #pragma unroll
        for (int ks = 0; ks < 4; ks++) {
            int k0 = ks * 16;
            int frow = (lane & 7) + ((lane >> 3) & 1) * 8;
            int fcol = k0 + (lane >> 4) * 8;
            uint32_t ahi[4][4], bh[4][4];
            #pragma unroll
            for (int mi = 0; mi < 4; mi++) {
                uint32_t o = sw128((uint32_t)((m0 + mi*16 + frow) * 128 + fcol * 2));
                ldm_x4(ahi[mi], abase + o);
            }
            #pragma unroll
            for (int pr = 0; pr < 4; pr++) {
                uint32_t o = sw128((uint32_t)((n0 + pr*16 + frow) * 128 + fcol * 2));
                ldm_x4(bh[pr], bbase + o);
            }
            #pragma unroll
            for (int mi = 0; mi < 4; mi++)
                #pragma unroll
                for (int ni = 0; ni < 8; ni++) {
                    int pr = ni >> 1, sel = ni & 1;
                    mma_f16(acc[mi][ni], ahi[mi], bh[pr][sel], bh[pr][sel+2]);
                }
        }
        st++; if (st >= 4) st = 0;
    }

    int gr = lane >> 2, tq = lane & 3;
    #pragma unroll
    for (int mi = 0; mi < 4; mi++) {
        #pragma unroll
        for (int ni = 0; ni < 8; ni++) {
            int col = bn + n0 + ni*8 + tq*2;
            float b0 = bias[col], b1 = bias[col + 1];
            #pragma unroll
            for (int half = 0; half < 2; half++) {
                int row = bm + m0 + mi*16 + gr + half*8;
                size_t off = (size_t)row * N + col;
                float2 r2 = *(const float2*)(res + off);
                *(float2*)(C + off) = make_float2(acc[mi][ni][half*2+0] + b0 + r2.x,
                                                  acc[mi][ni][half*2+1] + b1 + r2.y);
            }
        }
    }
}

// ============================================================
// Local attention: 2 threads per query (measured-best config).
// 256-thread block covers a 128-query span; K/V staged once,
// row stride 33 half2 (conflict-free). Partials combined with one
// shfl_xor(1); softmax duplicated per pair.
// ============================================================
__global__ __launch_bounds__(256)
void attn_tq2(const __half* __restrict__ qkv16, __half* __restrict__ ctx16) {
    __shared__ uint32_t Ks[136 * 33];
    __shared__ uint32_t Vs[136 * 33];
    int blk = blockIdx.x;
    int span = blk & 15;
    int bh = blk >> 4;
    int h = bh & (Hc - 1), b = bh >> 3;
    int s0 = span * 128;
    int rowbase = b * Sc;
    int tid = threadIdx.x;

    #pragma unroll
    for (int t = 0; t < 5; t++) {
        int i = tid + t * 256;
        if (i < 136 * 8) {
            int r = i >> 3, c = i & 7;
            int j = s0 - 4 + r;
            uint4 kv = make_uint4(0,0,0,0), vv = make_uint4(0,0,0,0);
            if (j >= 0 && j < Sc) {
                const uint4* kp = (const uint4*)(qkv16 + (size_t)(rowbase + j) * D3 + Dc + h * Dhc);
                const uint4* vp = (const uint4*)(qkv16 + (size_t)(rowbase + j) * D3 + 2*Dc + h * Dhc);
                kv = kp[c]; vv = vp[c];
            }
            int base = r * 33 + c * 4;
            Ks[base+0] = kv.x; Ks[base+1] = kv.y; Ks[base+2] = kv.z; Ks[base+3] = kv.w;
            Vs[base+0] = vv.x; Vs[base+1] = vv.y; Vs[base+2] = vv.z; Vs[base+3] = vv.w;
        }
    }
    __syncthreads();

    int q  = tid >> 1;
    int hf = tid & 1;
    int s  = s0 + q;

    const uint4* qp = (const uint4*)(qkv16 + (size_t)(rowbase + s) * D3 + h * Dhc);
    float2 qf[16];
    #pragma unroll
    for (int c = 0; c < 4; c++) {
        uint4 u = qp[hf*4 + c];
        uint32_t w4[4] = {u.x, u.y, u.z, u.w};
        #pragma unroll
        for (int k = 0; k < 4; k++)
            qf[c*4 + k] = __half22float2(*reinterpret_cast<__half2*>(&w4[k]));
    }

    float e[9];
    #pragma unroll
    for (int jj = 0; jj < 9; jj++) e[jj] = 0.0f;
    #pragma unroll
    for (int d = 0; d < 16; d++) {
        float2 q2 = qf[d];
        #pragma unroll
        for (int jj = 0; jj < 9; jj++) {
            uint32_t kw = Ks[(q + jj) * 33 + hf*16 + d];
            float2 k2 = __half22float2(*reinterpret_cast<__half2*>(&kw));
            e[jj] = fmaf(q2.x, k2.x, fmaf(q2.y, k2.y, e[jj]));
        }
    }
    #pragma unroll
    for (int jj = 0; jj < 9; jj++)
        e[jj] += __shfl_xor_sync(0xffffffffu, e[jj], 1);

    float mx = -INFINITY;
    #pragma unroll
    for (int jj = 0; jj < 9; jj++) {
        int j = s - 4 + jj;
        e[jj] = (j >= 0 && j < Sc) ? e[jj] * 0.125f : -INFINITY;
        mx = fmaxf(mx, e[jj]);
    }
    float sum = 0.0f;
    #pragma unroll
    for (int jj = 0; jj < 9; jj++) { e[jj] = __expf(e[jj] - mx); sum += e[jj]; }
    float inv = 1.0f / sum;
    #pragma unroll
    for (int jj = 0; jj < 9; jj++) e[jj] *= inv;

    float cx[32];
    #pragma unroll
    for (int d = 0; d < 32; d++) cx[d] = 0.0f;
    #pragma unroll
    for (int jj = 0; jj < 9; jj++) {
        float w = e[jj];
        int base = (q + jj) * 33 + hf*16;
        #pragma unroll
        for (int d = 0; d < 16; d++) {
            uint32_t vw = Vs[base + d];
            float2 v2 = __half22float2(*reinterpret_cast<__half2*>(&vw));
            cx[2*d]     = fmaf(w, v2.x, cx[2*d]);
            cx[2*d + 1] = fmaf(w, v2.y, cx[2*d + 1]);
        }
    }
    uint32_t ow[16];
    #pragma unroll
    for (int d = 0; d < 16; d++) {
        __half2 p2 = __floats2half2_rn(cx[2*d] * 0.03125f, cx[2*d + 1] * 0.03125f);
        ow[d] = *reinterpret_cast<uint32_t*>(&p2);
    }
    uint4* op = (uint4*)(ctx16 + (size_t)(rowbase + s) * Dc + h * Dhc);
    #pragma unroll
    for (int c = 0; c < 4; c++)
        op[hf*4 + c] = make_uint4(ow[c*4], ow[c*4+1], ow[c*4+2], ow[c*4+3]);
}

// ============================================================
extern "C" void kernel_launch(void* const* d_in, const int* in_sizes, int n_in,
                              void* d_out, int out_size) {
    const float* x     = (const float*)d_in[0];
    const float* in_w  = (const float*)d_in[1];
    const float* in_b  = (const float*)d_in[2];
    const float* out_w = (const float*)d_in[3];
    const float* out_b = (const float*)d_in[4];
    const float* ff_w1 = (const float*)d_in[5];
    const float* ff_b1 = (const float*)d_in[6];
    const float* ff_w2 = (const float*)d_in[7];
    const float* ff_b2 = (const float*)d_in[8];
    const float* ln1_g = (const float*)d_in[9];
    const float* ln1_b = (const float*)d_in[10];
    const float* ln2_g = (const float*)d_in[11];
    const float* ln2_b = (const float*)d_in[12];
    float* out = (float*)d_out;

    __half *fw, *a16, *ff16, *qkv16;
    float *x1;
    cudaGetSymbolAddress((void**)&fw,    g_fw);
    cudaGetSymbolAddress((void**)&a16,   g_a16);
    cudaGetSymbolAddress((void**)&ff16,  g_ff16);
    cudaGetSymbolAddress((void**)&qkv16, g_qkv16);
    cudaGetSymbolAddress((void**)&x1,    g_x1);

    cudaFuncSetAttribute(gemm_mma<0>, cudaFuncAttributeMaxDynamicSharedMemorySize, SM_SZ);
    cudaFuncSetAttribute(gemm_mma<2>, cudaFuncAttributeMaxDynamicSharedMemorySize, SM_SZ);
    cudaFuncSetAttribute(gemm_mma_l,  cudaFuncAttributeMaxDynamicSharedMemorySize, SM_SZL);

    // 0) fused prologue: weight conversion (768 blocks) + LN1 (8192 blocks)
    prologue_kernel<<<768 + Mrows, 128>>>(in_w, out_w, ff_w1, ff_w2, fw,
                                          x, ln1_g, ln1_b, a16);
    // 2) qkv16 = fp16(a16 @ (32*in_w)^T + in_b)
    gemm_mma<0><<<dim3(D3/128, Mrows/128), 128, SM_SZ>>>(
        a16, fw + FW_IN, in_b, qkv16, Mrows, D3, Dc);
    // 3) a16 = fp16(attention(qkv16)/32)   (2 threads/query — measured best)
    attn_tq2<<<16 * Bc * Hc, 256>>>(qkv16, a16);
    // 4) x1 = x + a16 @ (32*out_w)^T + out_b   (256-row tiles, 4-stage)
    gemm_mma_l<<<dim3(Dc/128, Mrows/256), 256, SM_SZL>>>(
        a16, fw + FW_OUT, out_b, x, x1, Mrows, Dc, Dc);
    // 5) a16 = fp16(LN2(x1)/32)
    ln_kernel<<<Mrows, 128>>>(x1, ln2_g, ln2_b, a16);
    // 6) ff16 = fp16(gelu(a16 @ (32*ff_w1)^T + ff_b1)/32)
    gemm_mma<2><<<dim3(DffC/128, Mrows/128), 128, SM_SZ>>>(
        a16, fw + FW_FF1, ff_b1, ff16, Mrows, DffC, Dc);
    // 7) out = x1 + ff16 @ (32*ff_w2)^T + ff_b2   (256-row tiles, 4-stage)
    gemm_mma_l<<<dim3(Dc/128, Mrows/256), 256, SM_SZL>>>(
        ff16, fw + FW_FF2, ff_b2, x1, out, Mrows, Dc, DffC);
}

// round 15
// speedup vs baseline: 1.7710x; 1.0049x over previous
#include <cuda_runtime.h>
#include <cuda_fp16.h>
#include <math.h>
#include <stdint.h>

// Problem constants
#define Bc   4
#define Sc   2048
#define Dc   512
#define Hc   8
#define Dhc  64
#define Mrows (Bc*Sc)      // 8192
#define D3   (3*Dc)        // 1536
#define DffC (4*Dc)        // 2048

// ---- scratch (device globals; no cudaMalloc allowed) ----
__device__ __half g_fw[3145728];
#define FW_IN   0
#define FW_OUT  786432
#define FW_FF1  1048576
#define FW_FF2  2097152
__device__ __half g_a16  [(size_t)Mrows * Dc];
__device__ __half g_ff16 [(size_t)Mrows * DffC];
__device__ __half g_qkv16[(size_t)Mrows * D3];
__device__ float  g_x1   [(size_t)Mrows * Dc];

// ============================================================
// helpers
// ============================================================
__device__ __forceinline__ uint32_t smem_u32(const void* p) {
    uint32_t a;
    asm("{ .reg .u64 t; cvta.to.shared.u64 t, %1; cvt.u32.u64 %0, t; }" : "=r"(a) : "l"(p));
    return a;
}
__device__ __forceinline__ uint32_t sw128(uint32_t o) { return o ^ ((o >> 3) & 0x70); }

__device__ __forceinline__ void cp16(uint32_t dst, const void* src) {
    asm volatile("cp.async.cg.shared.global [%0], [%1], 16;" :: "r"(dst), "l"(src) : "memory");
}
#define CP_COMMIT() asm volatile("cp.async.commit_group;" ::: "memory")
#define CP_WAIT1()  asm volatile("cp.async.wait_group 1;" ::: "memory")
#define CP_WAIT2()  asm volatile("cp.async.wait_group 2;" ::: "memory")

__device__ __forceinline__ void ldm_x4(uint32_t* r, uint32_t addr) {
    asm volatile("ldmatrix.sync.aligned.m8n8.x4.shared.b16 {%0,%1,%2,%3}, [%4];"
                 : "=r"(r[0]), "=r"(r[1]), "=r"(r[2]), "=r"(r[3]) : "r"(addr));
}
__device__ __forceinline__ void mma_f16(float* c, const uint32_t* a, uint32_t b0, uint32_t b1) {
    asm volatile("mma.sync.aligned.m16n8k16.row.col.f32.f16.f16.f32 "
                 "{%0,%1,%2,%3}, {%4,%5,%6,%7}, {%8,%9}, {%0,%1,%2,%3};"
                 : "+f"(c[0]), "+f"(c[1]), "+f"(c[2]), "+f"(c[3])
                 : "r"(a[0]), "r"(a[1]), "r"(a[2]), "r"(a[3]), "r"(b0), "r"(b1));
}

// ============================================================
// Fused prologue: weight conversion (blocks 0..767, 8x ILP) and
// LN1 -> fp16(/32) (blocks 768..8959, one row each).
// ============================================================
__device__ __forceinline__ void wconv_one(int i,
    const float* __restrict__ in_w, const float* __restrict__ out_w,
    const float* __restrict__ w1, const float* __restrict__ w2,
    __half* __restrict__ hi) {
    float4 v;
    if      (i < 196608) v = ((const float4*)in_w)[i];
    else if (i < 262144) v = ((const float4*)out_w)[i - 196608];
    else if (i < 524288) v = ((const float4*)w1)[i - 262144];
    else                 v = ((const float4*)w2)[i - 524288];
    __half2 p0 = __floats2half2_rn(v.x * 32.0f, v.y * 32.0f);
    __half2 p1 = __floats2half2_rn(v.z * 32.0f, v.w * 32.0f);
    ((uint2*)hi)[i] = make_uint2(*reinterpret_cast<uint32_t*>(&p0),
                                 *reinterpret_cast<uint32_t*>(&p1));
}

__device__ __forceinline__ void ln_row(int row, const float* __restrict__ x,
                                       const float* __restrict__ g,
                                       const float* __restrict__ b,
                                       __half* __restrict__ h16, int t) {
    const float4* xr = (const float4*)(x + (size_t)row * Dc);
    float4 v = xr[t];
    float s  = v.x + v.y + v.z + v.w;
    float s2 = v.x*v.x + v.y*v.y + v.z*v.z + v.w*v.w;
    #pragma unroll
    for (int o = 16; o > 0; o >>= 1) {
        s  += __shfl_xor_sync(0xffffffffu, s,  o);
        s2 += __shfl_xor_sync(0xffffffffu, s2, o);
    }
    __shared__ float sh[8];
    int w = t >> 5;
    if ((t & 31) == 0) { sh[w*2] = s; sh[w*2+1] = s2; }
    __syncthreads();
    s  = sh[0] + sh[2] + sh[4] + sh[6];
    s2 = sh[1] + sh[3] + sh[5] + sh[7];
    float mu  = s * (1.0f / Dc);
    float var = s2 * (1.0f / Dc) - mu * mu;
    float rstd = rsqrtf(var + 1e-5f);
    float4 gv = ((const float4*)g)[t];
    float4 bv = ((const float4*)b)[t];
    float o0 = (v.x - mu) * rstd * gv.x + bv.x;
    float o1 = (v.y - mu) * rstd * gv.y + bv.y;
    float o2 = (v.z - mu) * rstd * gv.z + bv.z;
    float o3 = (v.w - mu) * rstd * gv.w + bv.w;
    __half2 p0 = __floats2half2_rn(o0 * 0.03125f, o1 * 0.03125f);
    __half2 p1 = __floats2half2_rn(o2 * 0.03125f, o3 * 0.03125f);
    size_t base = (size_t)row * Dc + t * 4;
    *(uint2*)(h16 + base) = make_uint2(*reinterpret_cast<uint32_t*>(&p0),
                                       *reinterpret_cast<uint32_t*>(&p1));
}

__global__ void prologue_kernel(const float* __restrict__ in_w, const float* __restrict__ out_w,
                                const float* __restrict__ w1, const float* __restrict__ w2,
                                __half* __restrict__ fw,
                                const float* __restrict__ x,
                                const float* __restrict__ ln1_g, const float* __restrict__ ln1_b,
                                __half* __restrict__ a16) {
    int blk = blockIdx.x;
    if (blk < 768) {
        int i = blk * 128 + threadIdx.x;
        #pragma unroll
        for (int t = 0; t < 8; t++)
            wconv_one(i + t * 98304, in_w, out_w, w1, w2, fw);
    } else {
        ln_row(blk - 768, x, ln1_g, ln1_b, a16, threadIdx.x);
    }
}

__global__ void ln_kernel(const float* __restrict__ x,
                          const float* __restrict__ g,
                          const float* __restrict__ b,
                          __half* __restrict__ h16) {
    ln_row(blockIdx.x, x, g, b, h16, threadIdx.x);
}

// ============================================================
// 128x128 GEMM (4 warps of 64x64), 3-stage, 2 CTAs/SM.
// EPI: 0=bias->fp16, 2=bias+GELU->fp16(/32)
// ============================================================
#define TB  16384
#define SSZ (2*TB)
#define SM_SZ (3*SSZ)        // 98304

template<int EPI>
__global__ __launch_bounds__(128, 2)
void gemm_mma(const __half* __restrict__ Ahi, const __half* __restrict__ Bhi,
              const float* __restrict__ bias,
              __half* __restrict__ C16,
              int M, int N, int K)
{
    extern __shared__ __align__(128) char smem[];
    uint32_t sb = smem_u32(smem);
    int tid = threadIdx.x;
    int lane = tid & 31, wid = tid >> 5;
    int bm = blockIdx.y * 128, bn = blockIdx.x * 128;
    int m0 = (wid & 1) * 64;
    int n0 = (wid >> 1) * 64;

    float acc[4][8][4];
    #pragma unroll
    for (int i = 0; i < 4; i++)
        #pragma unroll
        for (int j = 0; j < 8; j++)
            #pragma unroll
            for (int k = 0; k < 4; k++) acc[i][j][k] = 0.0f;

    auto load_stage = [&](int st, int k0) {
        uint32_t base = sb + st * SSZ;
        #pragma unroll
        for (int t = 0; t < 8; t++) {
            int line = tid + t * 128;
            int r  = line >> 3;
            int cc = line & 7;
            uint32_t d = sw128((uint32_t)(r * 128 + cc * 16));
            cp16(base + d,      Ahi + (size_t)(bm + r) * K + k0 + cc * 8);
            cp16(base + TB + d, Bhi + (size_t)(bn + r) * K + k0 + cc * 8);
        }
    };

    int nk = K >> 6;
    load_stage(0, 0);  CP_COMMIT();
    load_stage(1, 64); CP_COMMIT();

    int st = 0;
    for (int ch = 0; ch < nk; ch++) {
        CP_WAIT1();
        __syncthreads();
        if (ch + 2 < nk) {
            int st2 = st + 2; if (st2 >= 3) st2 -= 3;
            load_stage(st2, (ch + 2) * 64);
        }
        CP_COMMIT();

        uint32_t abase = sb + st * SSZ;
        uint32_t bbase = abase + TB;

        #pragma unroll
        for (int ks = 0; ks < 4; ks++) {
            int k0 = ks * 16;
            int frow = (lane & 7) + ((lane >> 3) & 1) * 8;
            int fcol = k0 + (lane >> 4) * 8;
            uint32_t ahi[4][4], bh[4][4];
            #pragma unroll
            for (int mi = 0; mi < 4; mi++) {
                uint32_t o = sw128((uint32_t)((m0 + mi*16 + frow) * 128 + fcol * 2));
                ldm_x4(ahi[mi], abase + o);
            }
            #pragma unroll
            for (int pr = 0; pr < 4; pr++) {
                uint32_t o = sw128((uint32_t)((n0 + pr*16 + frow) * 128 + fcol * 2));
                ldm_x4(bh[pr], bbase + o);
            }
            #pragma unroll
            for (int mi = 0; mi < 4; mi++)
                #pragma unroll
                for (int ni = 0; ni < 8; ni++) {
                    int pr = ni >> 1, sel = ni & 1;
                    mma_f16(acc[mi][ni], ahi[mi], bh[pr][sel], bh[pr][sel+2]);
                }
        }
        st++; if (st >= 3) st = 0;
    }

    int gr = lane >> 2, tq = lane & 3;
    #pragma unroll
    for (int mi = 0; mi < 4; mi++) {
        #pragma unroll
        for (int ni = 0; ni < 8; ni++) {
            int col = bn + n0 + ni*8 + tq*2;
            float b0 = bias[col], b1 = bias[col + 1];
            #pragma unroll
            for (int half = 0; half < 2; half++) {
                int row = bm + m0 + mi*16 + gr + half*8;
                float v0 = acc[mi][ni][half*2 + 0] + b0;
                float v1 = acc[mi][ni][half*2 + 1] + b1;
                size_t off = (size_t)row * N + col;
                if (EPI == 2) {
                    v0 = 0.5f * v0 * (1.0f + erff(v0 * 0.7071067811865475f));
                    v1 = 0.5f * v1 * (1.0f + erff(v1 * 0.7071067811865475f));
                    __half2 p = __floats2half2_rn(v0 * 0.03125f, v1 * 0.03125f);
                    *(uint32_t*)(C16 + off) = *reinterpret_cast<uint32_t*>(&p);
                } else {
                    __half2 p = __floats2half2_rn(v0, v1);
                    *(uint32_t*)(C16 + off) = *reinterpret_cast<uint32_t*>(&p);
                }
            }
        }
    }
}

// ============================================================
// 256x128 GEMM, 16 warps of 64x32 (512 threads, 1 CTA/SM = 16 warps/SM),
// 4-stage, grid=128 CTAs = one balanced wave. N=512 GEMMs (out, FF2).
// Epilogue: bias + residual -> fp32.
// ============================================================
#define ATB 32768
#define BTB 16384
#define SSZL (ATB + BTB)     // 49152
#define SM_SZL (4*SSZL)      // 196608

__global__ __launch_bounds__(512, 1)
void gemm_mma_l(const __half* __restrict__ Ahi, const __half* __restrict__ Bhi,
                const float* __restrict__ bias, const float* __restrict__ res,
                float* __restrict__ C,
                int M, int N, int K)
{
    extern __shared__ __align__(128) char smem[];
    uint32_t sb = smem_u32(smem);
    int tid = threadIdx.x;
    int lane = tid & 31, wid = tid >> 5;
    int bm = blockIdx.y * 256, bn = blockIdx.x * 128;
    int m0 = (wid & 3) * 64;          // 4 warps in m
    int n0 = (wid >> 2) * 32;         // 4 warps in n (32 cols each)

    float acc[4][4][4];
    #pragma unroll
    for (int i = 0; i < 4; i++)
        #pragma unroll
        for (int j = 0; j < 4; j++)
            #pragma unroll
            for (int k = 0; k < 4; k++) acc[i][j][k] = 0.0f;

    auto load_stage = [&](int st, int k0) {
        uint32_t base = sb + st * SSZL;
        #pragma unroll
        for (int t = 0; t < 4; t++) {            // A: 2048 lines / 512 thr
            int line = tid + t * 512;
            int r  = line >> 3;
            int cc = line & 7;
            uint32_t d = sw128((uint32_t)(r * 128 + cc * 16));
            cp16(base + d, Ahi + (size_t)(bm + r) * K + k0 + cc * 8);
        }
        #pragma unroll
        for (int t = 0; t < 2; t++) {            // B: 1024 lines
            int line = tid + t * 512;
            int r  = line >> 3;
            int cc = line & 7;
            uint32_t d = sw128((uint32_t)(r * 128 + cc * 16));
            cp16(base + ATB + d, Bhi + (size_t)(bn + r) * K + k0 + cc * 8);
        }
    };

    int nk = K >> 6;
    load_stage(0, 0);   CP_COMMIT();
    load_stage(1, 64);  CP_COMMIT();
    load_stage(2, 128); CP_COMMIT();

    int st = 0;
    for (int ch = 0; ch < nk; ch++) {
        CP_WAIT2();
        __syncthreads();
        if (ch + 3 < nk) {
            int st3 = st + 3; if (st3 >= 4) st3 -= 4;
            load_stage(st3, (ch + 3) * 64);
        }
        CP_COMMIT();

        uint32_t abase = sb + st * SSZL;
        uint32_t bbase = abase + ATB;

        #pragma unroll
        for (int ks = 0; ks < 4; ks++) {
            int k0 = ks * 16;
            int frow = (lane & 7) + ((lane >> 3) & 1) * 8;
            int fcol = k0 + (lane >> 4) * 8;
            uint32_t ahi[4][4], bh[2][4];
            #pragma unroll
            for (int mi = 0; mi < 4; mi++) {
                uint32_t o = sw128((uint32_t)((m0 + mi*16 + frow) * 128 + fcol * 2));
                ldm_x4(ahi[mi], abase + o);
            }
            #pragma unroll
            for (int pr = 0; pr < 2; pr++) {
                uint32_t o = sw128((uint32_t)((n0 + pr*16 + frow) * 128 + fcol * 2));
                ldm_x4(bh[pr], bbase + o);
            }
            #pragma unroll
            for (int mi = 0; mi < 4; mi++)
                #pragma unroll
                for (int ni = 0; ni < 4; ni++) {
                    int pr = ni >> 1, sel = ni & 1;
                    mma_f16(acc[mi][ni], ahi[mi], bh[pr][sel], bh[pr][sel+2]);
                }
        }
        st++; if (st >= 4) st = 0;
    }

    int gr = lane >> 2, tq = lane & 3;
    #pragma unroll
    for (int mi = 0; mi < 4; mi++) {
        #pragma unroll
        for (int ni = 0; ni < 4; ni++) {
            int col = bn + n0 + ni*8 + tq*2;
            float b0 = bias[col], b1 = bias[col + 1];
            #pragma unroll
            for (int half = 0; half < 2; half++) {
                int row = bm + m0 + mi*16 + gr + half*8;
                size_t off = (size_t)row * N + col;
                float2 r2 = *(const float2*)(res + off);
                *(float2*)(C + off) = make_float2(acc[mi][ni][half*2+0] + b0 + r2.x,
                                                  acc[mi][ni][half*2+1] + b1 + r2.y);
            }
        }
    }
}

// ============================================================
// Local attention: 2 threads per query (measured-best config).
// ============================================================
__global__ __launch_bounds__(256)
void attn_tq2(const __half* __restrict__ qkv16, __half* __restrict__ ctx16) {
    __shared__ uint32_t Ks[136 * 33];
    __shared__ uint32_t Vs[136 * 33];
    int blk = blockIdx.x;
    int span = blk & 15;
    int bh = blk >> 4;
    int h = bh & (Hc - 1), b = bh >> 3;
    int s0 = span * 128;
    int rowbase = b * Sc;
    int tid = threadIdx.x;

    #pragma unroll
    for (int t = 0; t < 5; t++) {
        int i = tid + t * 256;
        if (i < 136 * 8) {
            int r = i >> 3, c = i & 7;
            int j = s0 - 4 + r;
            uint4 kv = make_uint4(0,0,0,0), vv = make_uint4(0,0,0,0);
            if (j >= 0 && j < Sc) {
                const uint4* kp = (const uint4*)(qkv16 + (size_t)(rowbase + j) * D3 + Dc + h * Dhc);
                const uint4* vp = (const uint4*)(qkv16 + (size_t)(rowbase + j) * D3 + 2*Dc + h * Dhc);
                kv = kp[c]; vv = vp[c];
            }
            int base = r * 33 + c * 4;
            Ks[base+0] = kv.x; Ks[base+1] = kv.y; Ks[base+2] = kv.z; Ks[base+3] = kv.w;
            Vs[base+0] = vv.x; Vs[base+1] = vv.y; Vs[base+2] = vv.z; Vs[base+3] = vv.w;
        }
    }
    __syncthreads();

    int q  = tid >> 1;
    int hf = tid & 1;
    int s  = s0 + q;

    const uint4* qp = (const uint4*)(qkv16 + (size_t)(rowbase + s) * D3 + h * Dhc);
    float2 qf[16];
    #pragma unroll
    for (int c = 0; c < 4; c++) {
        uint4 u = qp[hf*4 + c];
        uint32_t w4[4] = {u.x, u.y, u.z, u.w};
        #pragma unroll
        for (int k = 0; k < 4; k++)
            qf[c*4 + k] = __half22float2(*reinterpret_cast<__half2*>(&w4[k]));
    }

    float e[9];
    #pragma unroll
    for (int jj = 0; jj < 9; jj++) e[jj] = 0.0f;
    #pragma unroll
    for (int d = 0; d < 16; d++) {
        float2 q2 = qf[d];
        #pragma unroll
        for (int jj = 0; jj < 9; jj++) {
            uint32_t kw = Ks[(q + jj) * 33 + hf*16 + d];
            float2 k2 = __half22float2(*reinterpret_cast<__half2*>(&kw));
            e[jj] = fmaf(q2.x, k2.x, fmaf(q2.y, k2.y, e[jj]));
        }
    }
    #pragma unroll
    for (int jj = 0; jj < 9; jj++)
        e[jj] += __shfl_xor_sync(0xffffffffu, e[jj], 1);

    float mx = -INFINITY;
    #pragma unroll
    for (int jj = 0; jj < 9; jj++) {
        int j = s - 4 + jj;
        e[jj] = (j >= 0 && j < Sc) ? e[jj] * 0.125f : -INFINITY;
        mx = fmaxf(mx, e[jj]);
    }
    float sum = 0.0f;
    #pragma unroll
    for (int jj = 0; jj < 9; jj++) { e[jj] = __expf(e[jj] - mx); sum += e[jj]; }
    float inv = 1.0f / sum;
    #pragma unroll
    for (int jj = 0; jj < 9; jj++) e[jj] *= inv;

    float cx[32];
    #pragma unroll
    for (int d = 0; d < 32; d++) cx[d] = 0.0f;
    #pragma unroll
    for (int jj = 0; jj < 9; jj++) {
        float w = e[jj];
        int base = (q + jj) * 33 + hf*16;
        #pragma unroll
        for (int d = 0; d < 16; d++) {
            uint32_t vw = Vs[base + d];
            float2 v2 = __half22float2(*reinterpret_cast<__half2*>(&vw));
            cx[2*d]     = fmaf(w, v2.x, cx[2*d]);
            cx[2*d + 1] = fmaf(w, v2.y, cx[2*d + 1]);
        }
    }
    uint32_t ow[16];
    #pragma unroll
    for (int d = 0; d < 16; d++) {
        __half2 p2 = __floats2half2_rn(cx[2*d] * 0.03125f, cx[2*d + 1] * 0.03125f);
        ow[d] = *reinterpret_cast<uint32_t*>(&p2);
    }
    uint4* op = (uint4*)(ctx16 + (size_t)(rowbase + s) * Dc + h * Dhc);
    #pragma unroll
    for (int c = 0; c < 4; c++)
        op[hf*4 + c] = make_uint4(ow[c*4], ow[c*4+1], ow[c*4+2], ow[c*4+3]);
}

// ============================================================
extern "C" void kernel_launch(void* const* d_in, const int* in_sizes, int n_in,
                              void* d_out, int out_size) {
    const float* x     = (const float*)d_in[0];
    const float* in_w  = (const float*)d_in[1];
    const float* in_b  = (const float*)d_in[2];
    const float* out_w = (const float*)d_in[3];
    const float* out_b = (const float*)d_in[4];
    const float* ff_w1 = (const float*)d_in[5];
    const float* ff_b1 = (const float*)d_in[6];
    const float* ff_w2 = (const float*)d_in[7];
    const float* ff_b2 = (const float*)d_in[8];
    const float* ln1_g = (const float*)d_in[9];
    const float* ln1_b = (const float*)d_in[10];
    const float* ln2_g = (const float*)d_in[11];
    const float* ln2_b = (const float*)d_in[12];
    float* out = (float*)d_out;

    __half *fw, *a16, *ff16, *qkv16;
    float *x1;
    cudaGetSymbolAddress((void**)&fw,    g_fw);
    cudaGetSymbolAddress((void**)&a16,   g_a16);
    cudaGetSymbolAddress((void**)&ff16,  g_ff16);
    cudaGetSymbolAddress((void**)&qkv16, g_qkv16);
    cudaGetSymbolAddress((void**)&x1,    g_x1);

    cudaFuncSetAttribute(gemm_mma<0>, cudaFuncAttributeMaxDynamicSharedMemorySize, SM_SZ);
    cudaFuncSetAttribute(gemm_mma<2>, cudaFuncAttributeMaxDynamicSharedMemorySize, SM_SZ);
    cudaFuncSetAttribute(gemm_mma_l,  cudaFuncAttributeMaxDynamicSharedMemorySize, SM_SZL);

    // 0) fused prologue: weight conversion + LN1
    prologue_kernel<<<768 + Mrows, 128>>>(in_w, out_w, ff_w1, ff_w2, fw,
                                          x, ln1_g, ln1_b, a16);
    // 2) qkv16 = fp16(a16 @ (32*in_w)^T + in_b)
    gemm_mma<0><<<dim3(D3/128, Mrows/128), 128, SM_SZ>>>(
        a16, fw + FW_IN, in_b, qkv16, Mrows, D3, Dc);
    // 3) a16 = fp16(attention(qkv16)/32)
    attn_tq2<<<16 * Bc * Hc, 256>>>(qkv16, a16);
    // 4) x1 = x + a16 @ (32*out_w)^T + out_b   (256x128, 16 warps, one wave)
    gemm_mma_l<<<dim3(Dc/128, Mrows/256), 512, SM_SZL>>>(
        a16, fw + FW_OUT, out_b, x, x1, Mrows, Dc, Dc);
    // 5) a16 = fp16(LN2(x1)/32)
    ln_kernel<<<Mrows, 128>>>(x1, ln2_g, ln2_b, a16);
    // 6) ff16 = fp16(gelu(a16 @ (32*ff_w1)^T + ff_b1)/32)
    gemm_mma<2><<<dim3(DffC/128, Mrows/128), 128, SM_SZ>>>(
        a16, fw + FW_FF1, ff_b1, ff16, Mrows, DffC, Dc);
    // 7) out = x1 + ff16 @ (32*ff_w2)^T + ff_b2   (256x128, 16 warps, one wave)
    gemm_mma_l<<<dim3(Dc/128, Mrows/256), 512, SM_SZL>>>(
        ff16, fw + FW_FF2, ff_b2, x1, out, Mrows, Dc, DffC);
}